// round 1
// baseline (speedup 1.0000x reference)
#include <cuda_runtime.h>
#include <math.h>

// ---------------- problem constants ----------------
#define BSZ     4
#define NQ      1024
#define NK      2048
#define DIM     1024
#define HEADS   16
#define HD      64
#define HIDDEN  4096
#define MQ      (BSZ*NQ)   // 4096
#define MK      (BSZ*NK)   // 8192

// ---------------- scratch (device globals; no allocation allowed) ----------
__device__ float g_qn [(size_t)MQ * DIM];
__device__ float g_q  [(size_t)MQ * DIM];
__device__ float g_k  [(size_t)MK * DIM];
__device__ float g_v  [(size_t)MK * DIM];
__device__ float g_ctx[(size_t)MQ * DIM];
__device__ float g_h1 [(size_t)MQ * HIDDEN];

// ==================== LayerNorm: one block per row of 1024 ====================
__global__ __launch_bounds__(256)
void ln_kernel(const float* __restrict__ x, const float* __restrict__ g,
               const float* __restrict__ bt, float* __restrict__ out)
{
    int row = blockIdx.x;
    int t = threadIdx.x;
    const float4* xr = (const float4*)(x + (size_t)row * DIM);
    float4 v = xr[t];
    float s  = v.x + v.y + v.z + v.w;
    float sq = v.x*v.x + v.y*v.y + v.z*v.z + v.w*v.w;

    #pragma unroll
    for (int off = 16; off; off >>= 1) {
        s  += __shfl_xor_sync(0xffffffffu, s,  off);
        sq += __shfl_xor_sync(0xffffffffu, sq, off);
    }
    __shared__ float ss[8], sqs[8];
    int warp = t >> 5, lane = t & 31;
    if (lane == 0) { ss[warp] = s; sqs[warp] = sq; }
    __syncthreads();
    if (t < 32) {
        float a = (t < 8) ? ss[t]  : 0.f;
        float b = (t < 8) ? sqs[t] : 0.f;
        #pragma unroll
        for (int off = 4; off; off >>= 1) {
            a += __shfl_xor_sync(0xffffffffu, a, off);
            b += __shfl_xor_sync(0xffffffffu, b, off);
        }
        if (t == 0) { ss[0] = a; sqs[0] = b; }
    }
    __syncthreads();
    float mu  = ss[0]  * (1.0f / DIM);
    float var = sqs[0] * (1.0f / DIM) - mu * mu;
    float inv = rsqrtf(var + 1e-5f);

    float4 gv = ((const float4*)g)[t];
    float4 bv = ((const float4*)bt)[t];
    float4 o;
    o.x = (v.x - mu) * inv * gv.x + bv.x;
    o.y = (v.y - mu) * inv * gv.y + bv.y;
    o.z = (v.z - mu) * inv * gv.z + bv.z;
    o.w = (v.w - mu) * inv * gv.w + bv.w;
    ((float4*)(out + (size_t)row * DIM))[t] = o;
}

// ==================== SGEMM 128x128x8, 8x8 per thread =======================
// C[M,N] = A[M,K] @ B[K,N] + bias   (+gelu | +residual)
// mode: 0 = bias, 1 = bias+gelu(exact), 2 = bias+residual
__device__ __forceinline__ float gelu_exact(float x) {
    return 0.5f * x * (1.0f + erff(x * 0.70710678118654752f));
}

__global__ __launch_bounds__(256)
void sgemm_kernel(int M, int N, int K,
                  const float* __restrict__ A,
                  const float* __restrict__ B,
                  const float* __restrict__ bias,
                  const float* __restrict__ res,
                  float* __restrict__ C, int mode)
{
    __shared__ float As[8][128];
    __shared__ float Bs[8][128];

    int tid = threadIdx.x;
    int bx = blockIdx.x, by = blockIdx.y;

    A += (size_t)by * 128 * K;
    B += (size_t)bx * 128;
    C += (size_t)by * 128 * N + (size_t)bx * 128;
    const float* resp  = res ? (res + (size_t)by * 128 * N + (size_t)bx * 128) : nullptr;
    const float* biasp = bias + (size_t)bx * 128;

    int aRow = tid >> 1;
    int aCol = (tid & 1) * 4;
    int bRow = tid >> 5;
    int bCol = (tid & 31) * 4;

    int tr = (tid >> 4) * 8;
    int tc = (tid & 15) * 8;

    float acc[8][8] = {};

    for (int k0 = 0; k0 < K; k0 += 8) {
        float4 a4 = *(const float4*)(A + (size_t)aRow * K + k0 + aCol);
        As[aCol + 0][aRow] = a4.x;
        As[aCol + 1][aRow] = a4.y;
        As[aCol + 2][aRow] = a4.z;
        As[aCol + 3][aRow] = a4.w;
        float4 b4 = *(const float4*)(B + (size_t)(k0 + bRow) * N + bCol);
        *(float4*)&Bs[bRow][bCol] = b4;
        __syncthreads();

        #pragma unroll
        for (int k = 0; k < 8; k++) {
            float4 a0 = *(const float4*)&As[k][tr];
            float4 a1 = *(const float4*)&As[k][tr + 4];
            float4 b0 = *(const float4*)&Bs[k][tc];
            float4 b1 = *(const float4*)&Bs[k][tc + 4];
            float ra[8] = {a0.x, a0.y, a0.z, a0.w, a1.x, a1.y, a1.z, a1.w};
            float rb[8] = {b0.x, b0.y, b0.z, b0.w, b1.x, b1.y, b1.z, b1.w};
            #pragma unroll
            for (int i = 0; i < 8; i++)
                #pragma unroll
                for (int j = 0; j < 8; j++)
                    acc[i][j] += ra[i] * rb[j];
        }
        __syncthreads();
    }

    #pragma unroll
    for (int i = 0; i < 8; i++) {
        size_t r = (size_t)(tr + i);
        #pragma unroll
        for (int j0 = 0; j0 < 8; j0 += 4) {
            float4 o;
            float* po = &o.x;
            #pragma unroll
            for (int jj = 0; jj < 4; jj++) {
                int j = j0 + jj;
                float val = acc[i][j] + biasp[tc + j];
                if (mode == 1) val = gelu_exact(val);
                if (mode == 2) val += resp[r * N + tc + j];
                po[jj] = val;
            }
            *(float4*)(C + r * N + tc + j0) = o;
        }
    }
}

// ==================== Flash attention: 64 q-rows x 64 k-cols tiles ==========
// grid (NQ/64, HEADS, BSZ), 256 threads
// Q/K/V layouts: [B, N, HEADS, HD] flattened => row stride DIM, head offset h*HD
#define ATT_SMEM_FLOATS (64*64 + 64*64 + 64*68 + 3*64)

__global__ __launch_bounds__(256)
void attn_kernel(const float* __restrict__ Q, const float* __restrict__ Kg,
                 const float* __restrict__ Vg, float* __restrict__ ctx)
{
    extern __shared__ float sm[];
    float* Qts = sm;                 // [d][r]  (transposed), 64x64
    float* KVs = sm + 64 * 64;       // K: [d][n] transposed; then V: [n][d] raw
    float* Pts = sm + 2 * 64 * 64;   // [k][r]  padded stride 68
    float* m_s = Pts + 64 * 68;
    float* l_s = m_s + 64;
    float* f_s = l_s + 64;

    int b = blockIdx.z, h = blockIdx.y, qt = blockIdx.x;
    int tid = threadIdx.x;
    const float scale = 0.125f;  // 1/sqrt(64)

    const float* Qbase = Q  + ((size_t)(b * NQ + qt * 64)) * DIM + h * HD;
    const float* Kbase = Kg + ((size_t)b * NK) * DIM + h * HD;
    const float* Vbase = Vg + ((size_t)b * NK) * DIM + h * HD;

    // load Q tile transposed + pre-scaled
    #pragma unroll
    for (int i = 0; i < 4; i++) {
        int idx = tid + i * 256;         // 0..1023 float4 slots
        int r  = idx >> 4;
        int c4 = (idx & 15) * 4;
        float4 q4 = *(const float4*)(Qbase + (size_t)r * DIM + c4);
        Qts[(c4 + 0) * 64 + r] = q4.x * scale;
        Qts[(c4 + 1) * 64 + r] = q4.y * scale;
        Qts[(c4 + 2) * 64 + r] = q4.z * scale;
        Qts[(c4 + 3) * 64 + r] = q4.w * scale;
    }
    if (tid < 64) { m_s[tid] = -1e30f; l_s[tid] = 0.f; }

    int tr = (tid >> 4) * 4;   // 4 q-rows
    int tc = (tid & 15) * 4;   // 4 k-cols / d-cols
    float o[4][4] = {};

    for (int kt = 0; kt < NK / 64; kt++) {
        __syncthreads();  // protect KVs/Pts reuse (and Q load on first iter)

        // K tile transposed into KVs[d][n]
        #pragma unroll
        for (int i = 0; i < 4; i++) {
            int idx = tid + i * 256;
            int r  = idx >> 4;
            int c4 = (idx & 15) * 4;
            float4 k4 = *(const float4*)(Kbase + (size_t)(kt * 64 + r) * DIM + c4);
            KVs[(c4 + 0) * 64 + r] = k4.x;
            KVs[(c4 + 1) * 64 + r] = k4.y;
            KVs[(c4 + 2) * 64 + r] = k4.z;
            KVs[(c4 + 3) * 64 + r] = k4.w;
        }
        __syncthreads();

        // S = (Q*scale) @ K^T  for rows tr.., cols tc..
        float s[4][4] = {};
        #pragma unroll
        for (int d = 0; d < 64; d++) {
            float4 a  = *(const float4*)&Qts[d * 64 + tr];
            float4 bk = *(const float4*)&KVs[d * 64 + tc];
            s[0][0] += a.x * bk.x; s[0][1] += a.x * bk.y; s[0][2] += a.x * bk.z; s[0][3] += a.x * bk.w;
            s[1][0] += a.y * bk.x; s[1][1] += a.y * bk.y; s[1][2] += a.y * bk.z; s[1][3] += a.y * bk.w;
            s[2][0] += a.z * bk.x; s[2][1] += a.z * bk.y; s[2][2] += a.z * bk.z; s[2][3] += a.z * bk.w;
            s[3][0] += a.w * bk.x; s[3][1] += a.w * bk.y; s[3][2] += a.w * bk.z; s[3][3] += a.w * bk.w;
        }
        #pragma unroll
        for (int j = 0; j < 4; j++)
            #pragma unroll
            for (int i = 0; i < 4; i++)
                Pts[(tc + j) * 68 + (tr + i)] = s[i][j];
        __syncthreads();

        // online softmax update: warp w handles rows w*8..w*8+7
        {
            int warp = tid >> 5, lane = tid & 31;
            for (int rr = 0; rr < 8; rr++) {
                int r = warp * 8 + rr;
                float v0 = Pts[lane * 68 + r];
                float v1 = Pts[(lane + 32) * 68 + r];
                float mx = fmaxf(v0, v1);
                #pragma unroll
                for (int off = 16; off; off >>= 1)
                    mx = fmaxf(mx, __shfl_xor_sync(0xffffffffu, mx, off));
                float mold = m_s[r];
                float mnew = fmaxf(mold, mx);
                float p0 = __expf(v0 - mnew), p1 = __expf(v1 - mnew);
                Pts[lane * 68 + r] = p0;
                Pts[(lane + 32) * 68 + r] = p1;
                float sum = p0 + p1;
                #pragma unroll
                for (int off = 16; off; off >>= 1)
                    sum += __shfl_xor_sync(0xffffffffu, sum, off);
                if (lane == 0) {
                    float f = __expf(mold - mnew);
                    l_s[r] = l_s[r] * f + sum;
                    m_s[r] = mnew;
                    f_s[r] = f;
                }
            }
        }
        __syncthreads();

        // V tile raw into KVs[n][d]
        #pragma unroll
        for (int i = 0; i < 4; i++) {
            int idx = tid + i * 256;
            int r  = idx >> 4;
            int c4 = (idx & 15) * 4;
            float4 v4 = *(const float4*)(Vbase + (size_t)(kt * 64 + r) * DIM + c4);
            *(float4*)&KVs[r * 64 + c4] = v4;
        }
        __syncthreads();

        // rescale O and accumulate O += P @ V
        float f0 = f_s[tr], f1 = f_s[tr + 1], f2 = f_s[tr + 2], f3 = f_s[tr + 3];
        #pragma unroll
        for (int j = 0; j < 4; j++) {
            o[0][j] *= f0; o[1][j] *= f1; o[2][j] *= f2; o[3][j] *= f3;
        }
        #pragma unroll
        for (int kk = 0; kk < 64; kk++) {
            float4 a  = *(const float4*)&Pts[kk * 68 + tr];   // P[tr..tr+3][kk]
            float4 bv = *(const float4*)&KVs[kk * 64 + tc];   // V[kk][tc..tc+3]
            o[0][0] += a.x * bv.x; o[0][1] += a.x * bv.y; o[0][2] += a.x * bv.z; o[0][3] += a.x * bv.w;
            o[1][0] += a.y * bv.x; o[1][1] += a.y * bv.y; o[1][2] += a.y * bv.z; o[1][3] += a.y * bv.w;
            o[2][0] += a.z * bv.x; o[2][1] += a.z * bv.y; o[2][2] += a.z * bv.z; o[2][3] += a.z * bv.w;
            o[3][0] += a.w * bv.x; o[3][1] += a.w * bv.y; o[3][2] += a.w * bv.z; o[3][3] += a.w * bv.w;
        }
    }

    // epilogue: divide by l, write ctx[b, q, h, d]
    float* Cb = ctx + ((size_t)(b * NQ + qt * 64)) * DIM + h * HD;
    #pragma unroll
    for (int i = 0; i < 4; i++) {
        float inv = 1.0f / l_s[tr + i];
        float4 r4 = make_float4(o[i][0] * inv, o[i][1] * inv, o[i][2] * inv, o[i][3] * inv);
        *(float4*)(Cb + (size_t)(tr + i) * DIM + tc) = r4;
    }
}

// ==================== launch =================================================
extern "C" void kernel_launch(void* const* d_in, const int* in_sizes, int n_in,
                              void* d_out, int out_size)
{
    const float* tgt  = (const float*)d_in[0];
    const float* emb  = (const float*)d_in[1];
    const float* ln_g = (const float*)d_in[2];
    const float* ln_b = (const float*)d_in[3];
    const float* wq = (const float*)d_in[4];  const float* bq = (const float*)d_in[5];
    const float* wk = (const float*)d_in[6];  const float* bk = (const float*)d_in[7];
    const float* wv = (const float*)d_in[8];  const float* bv = (const float*)d_in[9];
    const float* wo = (const float*)d_in[10]; const float* bo = (const float*)d_in[11];
    const float* w1 = (const float*)d_in[12]; const float* b1 = (const float*)d_in[13];
    const float* w2 = (const float*)d_in[14]; const float* b2 = (const float*)d_in[15];
    float* out = (float*)d_out;

    float *qn, *q, *k, *v, *ctx, *h1;
    cudaGetSymbolAddress((void**)&qn,  g_qn);
    cudaGetSymbolAddress((void**)&q,   g_q);
    cudaGetSymbolAddress((void**)&k,   g_k);
    cudaGetSymbolAddress((void**)&v,   g_v);
    cudaGetSymbolAddress((void**)&ctx, g_ctx);
    cudaGetSymbolAddress((void**)&h1,  g_h1);

    const size_t att_smem = (size_t)ATT_SMEM_FLOATS * sizeof(float); // 50944 B
    cudaFuncSetAttribute(attn_kernel, cudaFuncAttributeMaxDynamicSharedMemorySize,
                         (int)att_smem);

    // 1) qn = LN(tgt)
    ln_kernel<<<MQ, 256>>>(tgt, ln_g, ln_b, qn);

    // 2) Q = qn @ wq + bq
    sgemm_kernel<<<dim3(DIM / 128, MQ / 128), 256>>>(MQ, DIM, DIM, qn, wq, bq, nullptr, q, 0);
    // 3) K = emb @ wk + bk
    sgemm_kernel<<<dim3(DIM / 128, MK / 128), 256>>>(MK, DIM, DIM, emb, wk, bk, nullptr, k, 0);
    // 4) V = emb @ wv + bv
    sgemm_kernel<<<dim3(DIM / 128, MK / 128), 256>>>(MK, DIM, DIM, emb, wv, bv, nullptr, v, 0);

    // 5) ctx = softmax(Q K^T / sqrt(d)) V
    attn_kernel<<<dim3(NQ / 64, HEADS, BSZ), 256, att_smem>>>(q, k, v, ctx);

    // 6) tgt1 = tgt + ctx @ wo + bo   -> d_out
    sgemm_kernel<<<dim3(DIM / 128, MQ / 128), 256>>>(MQ, DIM, DIM, ctx, wo, bo, tgt, out, 2);

    // 7) h_in = LN(tgt1)
    ln_kernel<<<MQ, 256>>>(out, ln_g, ln_b, qn);

    // 8) h1 = gelu(h_in @ w1 + b1)
    sgemm_kernel<<<dim3(HIDDEN / 128, MQ / 128), 256>>>(MQ, HIDDEN, DIM, qn, w1, b1, nullptr, h1, 1);

    // 9) out = tgt1 + h1 @ w2 + b2   (in-place residual on d_out)
    sgemm_kernel<<<dim3(DIM / 128, MQ / 128), 256>>>(MQ, DIM, HIDDEN, h1, w2, b2, out, out, 2);
}

// round 2
// speedup vs baseline: 1.9027x; 1.9027x over previous
#include <cuda_runtime.h>
#include <math.h>
#include <stdint.h>

// ---------------- problem constants ----------------
#define BSZ     4
#define NQ      1024
#define NK      2048
#define DIM     1024
#define HEADS   16
#define HD      64
#define HIDDEN  4096
#define MQ      (BSZ*NQ)   // 4096
#define MK      (BSZ*NK)   // 8192

// ---------------- scratch (device globals; no allocation allowed) ----------
__device__ float g_qn [(size_t)MQ * DIM];
__device__ float g_q  [(size_t)MQ * DIM];
__device__ float g_k  [(size_t)MK * DIM];
__device__ float g_v  [(size_t)MK * DIM];
__device__ float g_ctx[(size_t)MQ * DIM];
__device__ float g_h1 [(size_t)MQ * HIDDEN];

// ==================== LayerNorm: one block per row of 1024 ====================
__global__ __launch_bounds__(256)
void ln_kernel(const float* __restrict__ x, const float* __restrict__ g,
               const float* __restrict__ bt, float* __restrict__ out)
{
    int row = blockIdx.x;
    int t = threadIdx.x;
    const float4* xr = (const float4*)(x + (size_t)row * DIM);
    float4 v = xr[t];
    float s  = v.x + v.y + v.z + v.w;
    float sq = v.x*v.x + v.y*v.y + v.z*v.z + v.w*v.w;

    #pragma unroll
    for (int off = 16; off; off >>= 1) {
        s  += __shfl_xor_sync(0xffffffffu, s,  off);
        sq += __shfl_xor_sync(0xffffffffu, sq, off);
    }
    __shared__ float ss[8], sqs[8];
    int warp = t >> 5, lane = t & 31;
    if (lane == 0) { ss[warp] = s; sqs[warp] = sq; }
    __syncthreads();
    if (t < 32) {
        float a = (t < 8) ? ss[t]  : 0.f;
        float b = (t < 8) ? sqs[t] : 0.f;
        #pragma unroll
        for (int off = 4; off; off >>= 1) {
            a += __shfl_xor_sync(0xffffffffu, a, off);
            b += __shfl_xor_sync(0xffffffffu, b, off);
        }
        if (t == 0) { ss[0] = a; sqs[0] = b; }
    }
    __syncthreads();
    float mu  = ss[0]  * (1.0f / DIM);
    float var = sqs[0] * (1.0f / DIM) - mu * mu;
    float inv = rsqrtf(var + 1e-5f);

    float4 gv = ((const float4*)g)[t];
    float4 bv = ((const float4*)bt)[t];
    float4 o;
    o.x = (v.x - mu) * inv * gv.x + bv.x;
    o.y = (v.y - mu) * inv * gv.y + bv.y;
    o.z = (v.z - mu) * inv * gv.z + bv.z;
    o.w = (v.w - mu) * inv * gv.w + bv.w;
    ((float4*)(out + (size_t)row * DIM))[t] = o;
}

// ==================== helpers ====================
__device__ __forceinline__ float gelu_exact(float x) {
    return 0.5f * x * (1.0f + erff(x * 0.70710678118654752f));
}
__device__ __forceinline__ uint32_t f2tf32(float x) {
    uint32_t r;
    asm("cvt.rna.tf32.f32 %0, %1;" : "=r"(r) : "f"(x));
    return r;
}
__device__ __forceinline__ void mma_tf32(float d[4], const uint32_t a[4], const uint32_t b[2]) {
    asm volatile(
        "mma.sync.aligned.m16n8k8.row.col.f32.tf32.tf32.f32 "
        "{%0,%1,%2,%3}, {%4,%5,%6,%7}, {%8,%9}, {%0,%1,%2,%3};"
        : "+f"(d[0]), "+f"(d[1]), "+f"(d[2]), "+f"(d[3])
        : "r"(a[0]), "r"(a[1]), "r"(a[2]), "r"(a[3]), "r"(b[0]), "r"(b[1]));
}

// ==================== tf32 tensor-core GEMM ====================
// C[M,N] = A[M,K] @ B[K,N] + bias (+gelu | +residual)
// CTA 128x128, kc=32, 8 warps each 32(m)x64(n), double-buffered smem.
// mode: 0 = bias, 1 = bias+gelu, 2 = bias+residual
#define SKA 36                 // As [m][k] stride (banks 4r+c distinct)
#define SKB 136                // Bs [k][n] stride (banks 8c+r distinct)
#define ASZ (128*SKA)          // 4608 u32
#define BSZ_SM (32*SKB)        // 4352 u32
#define GEMM_SMEM ((2*(ASZ+BSZ_SM))*4)   // 71680 bytes

__global__ __launch_bounds__(256, 1)
void tf32_gemm(int M, int N, int K,
               const float* __restrict__ A,
               const float* __restrict__ B,
               const float* __restrict__ bias,
               const float* __restrict__ res,
               float* __restrict__ C, int mode)
{
    extern __shared__ uint32_t sm[];
    uint32_t* AsBase = sm;                 // 2 * ASZ
    uint32_t* BsBase = sm + 2 * ASZ;       // 2 * BSZ_SM

    int tid = threadIdx.x;
    int lane = tid & 31;
    int warp = tid >> 5;
    int wr = warp >> 1;          // 0..3  -> m offset
    int wc = warp & 1;           // 0..1  -> n offset
    int warp_m = wr * 32;
    int warp_n = wc * 64;
    int r = lane >> 2;           // 0..7
    int c = lane & 3;            // 0..3

    int ctaM = blockIdx.y * 128;
    int ctaN = blockIdx.x * 128;

    const float* Ab = A + (size_t)ctaM * K;
    const float* Bb = B + ctaN;

    // global load indices
    int aRow = tid >> 3;               // 0..31 (+ i*32)
    int aK4  = (tid & 7) * 4;

    float4 Ar[4], Br[4];
    float acc[2][8][4] = {};

    // ---- prologue: load stage k0=0 ----
    #pragma unroll
    for (int i = 0; i < 4; i++)
        Ar[i] = *(const float4*)(Ab + (size_t)(aRow + i * 32) * K + aK4);
    #pragma unroll
    for (int i = 0; i < 4; i++) {
        int idx = tid + i * 256;
        int bk = idx >> 5, bn = (idx & 31) * 4;
        Br[i] = *(const float4*)(Bb + (size_t)bk * N + bn);
    }
    // store stage 0
    #pragma unroll
    for (int i = 0; i < 4; i++) {
        uint32_t* p = AsBase + (size_t)(aRow + i * 32) * SKA + aK4;
        p[0] = f2tf32(Ar[i].x); p[1] = f2tf32(Ar[i].y);
        p[2] = f2tf32(Ar[i].z); p[3] = f2tf32(Ar[i].w);
    }
    #pragma unroll
    for (int i = 0; i < 4; i++) {
        int idx = tid + i * 256;
        int bk = idx >> 5, bn = (idx & 31) * 4;
        uint32_t* p = BsBase + (size_t)bk * SKB + bn;
        p[0] = f2tf32(Br[i].x); p[1] = f2tf32(Br[i].y);
        p[2] = f2tf32(Br[i].z); p[3] = f2tf32(Br[i].w);
    }
    __syncthreads();

    int buf = 0;
    for (int k0 = 0; k0 < K; k0 += 32) {
        bool more = (k0 + 32) < K;
        if (more) {
            const float* An = Ab + (k0 + 32);
            const float* Bn = Bb + (size_t)(k0 + 32) * N;
            #pragma unroll
            for (int i = 0; i < 4; i++)
                Ar[i] = *(const float4*)(An + (size_t)(aRow + i * 32) * K + aK4);
            #pragma unroll
            for (int i = 0; i < 4; i++) {
                int idx = tid + i * 256;
                int bk = idx >> 5, bn = (idx & 31) * 4;
                Br[i] = *(const float4*)(Bn + (size_t)bk * N + bn);
            }
        }

        const uint32_t* Asb = AsBase + buf * ASZ;
        const uint32_t* Bsb = BsBase + buf * BSZ_SM;
        #pragma unroll
        for (int ks = 0; ks < 4; ks++) {
            uint32_t af[2][4], bf[8][2];
            #pragma unroll
            for (int mt = 0; mt < 2; mt++) {
                int m0 = warp_m + mt * 16;
                const uint32_t* pa = Asb + (size_t)(m0 + r) * SKA + ks * 8 + c;
                af[mt][0] = pa[0];
                af[mt][2] = pa[4];
                af[mt][1] = pa[8 * SKA];
                af[mt][3] = pa[8 * SKA + 4];
            }
            #pragma unroll
            for (int nt = 0; nt < 8; nt++) {
                int n0 = warp_n + nt * 8;
                const uint32_t* pb = Bsb + (size_t)(ks * 8 + c) * SKB + n0 + r;
                bf[nt][0] = pb[0];
                bf[nt][1] = pb[4 * SKB];
            }
            #pragma unroll
            for (int mt = 0; mt < 2; mt++)
                #pragma unroll
                for (int nt = 0; nt < 8; nt++)
                    mma_tf32(acc[mt][nt], af[mt], bf[nt]);
        }

        if (more) {
            uint32_t* Asw = AsBase + (buf ^ 1) * ASZ;
            uint32_t* Bsw = BsBase + (buf ^ 1) * BSZ_SM;
            #pragma unroll
            for (int i = 0; i < 4; i++) {
                uint32_t* p = Asw + (size_t)(aRow + i * 32) * SKA + aK4;
                p[0] = f2tf32(Ar[i].x); p[1] = f2tf32(Ar[i].y);
                p[2] = f2tf32(Ar[i].z); p[3] = f2tf32(Ar[i].w);
            }
            #pragma unroll
            for (int i = 0; i < 4; i++) {
                int idx = tid + i * 256;
                int bk = idx >> 5, bn = (idx & 31) * 4;
                uint32_t* p = Bsw + (size_t)bk * SKB + bn;
                p[0] = f2tf32(Br[i].x); p[1] = f2tf32(Br[i].y);
                p[2] = f2tf32(Br[i].z); p[3] = f2tf32(Br[i].w);
            }
            __syncthreads();
            buf ^= 1;
        }
    }

    // ---- epilogue ----
    #pragma unroll
    for (int mt = 0; mt < 2; mt++) {
        #pragma unroll
        for (int nt = 0; nt < 8; nt++) {
            int row = ctaM + warp_m + mt * 16 + r;
            int col = ctaN + warp_n + nt * 8 + 2 * c;
            float b0 = bias[col], b1 = bias[col + 1];
            float v0 = acc[mt][nt][0] + b0;
            float v1 = acc[mt][nt][1] + b1;
            float v2 = acc[mt][nt][2] + b0;
            float v3 = acc[mt][nt][3] + b1;
            if (mode == 1) {
                v0 = gelu_exact(v0); v1 = gelu_exact(v1);
                v2 = gelu_exact(v2); v3 = gelu_exact(v3);
            } else if (mode == 2) {
                const float* r0 = res + (size_t)row * N + col;
                const float* r1 = res + (size_t)(row + 8) * N + col;
                v0 += r0[0]; v1 += r0[1];
                v2 += r1[0]; v3 += r1[1];
            }
            *(float2*)(C + (size_t)row * N + col)       = make_float2(v0, v1);
            *(float2*)(C + (size_t)(row + 8) * N + col) = make_float2(v2, v3);
        }
    }
}

// ==================== Flash attention: 64 q-rows x 64 k-cols tiles ==========
#define ATT_SMEM_FLOATS (64*64 + 64*64 + 64*68 + 3*64)

__global__ __launch_bounds__(256)
void attn_kernel(const float* __restrict__ Q, const float* __restrict__ Kg,
                 const float* __restrict__ Vg, float* __restrict__ ctx)
{
    extern __shared__ float smf[];
    float* Qts = smf;
    float* KVs = smf + 64 * 64;
    float* Pts = smf + 2 * 64 * 64;
    float* m_s = Pts + 64 * 68;
    float* l_s = m_s + 64;
    float* f_s = l_s + 64;

    int b = blockIdx.z, h = blockIdx.y, qt = blockIdx.x;
    int tid = threadIdx.x;
    const float scale = 0.125f;

    const float* Qbase = Q  + ((size_t)(b * NQ + qt * 64)) * DIM + h * HD;
    const float* Kbase = Kg + ((size_t)b * NK) * DIM + h * HD;
    const float* Vbase = Vg + ((size_t)b * NK) * DIM + h * HD;

    #pragma unroll
    for (int i = 0; i < 4; i++) {
        int idx = tid + i * 256;
        int r  = idx >> 4;
        int c4 = (idx & 15) * 4;
        float4 q4 = *(const float4*)(Qbase + (size_t)r * DIM + c4);
        Qts[(c4 + 0) * 64 + r] = q4.x * scale;
        Qts[(c4 + 1) * 64 + r] = q4.y * scale;
        Qts[(c4 + 2) * 64 + r] = q4.z * scale;
        Qts[(c4 + 3) * 64 + r] = q4.w * scale;
    }
    if (tid < 64) { m_s[tid] = -1e30f; l_s[tid] = 0.f; }

    int tr = (tid >> 4) * 4;
    int tc = (tid & 15) * 4;
    float o[4][4] = {};

    for (int kt = 0; kt < NK / 64; kt++) {
        __syncthreads();

        #pragma unroll
        for (int i = 0; i < 4; i++) {
            int idx = tid + i * 256;
            int r  = idx >> 4;
            int c4 = (idx & 15) * 4;
            float4 k4 = *(const float4*)(Kbase + (size_t)(kt * 64 + r) * DIM + c4);
            KVs[(c4 + 0) * 64 + r] = k4.x;
            KVs[(c4 + 1) * 64 + r] = k4.y;
            KVs[(c4 + 2) * 64 + r] = k4.z;
            KVs[(c4 + 3) * 64 + r] = k4.w;
        }
        __syncthreads();

        float s[4][4] = {};
        #pragma unroll
        for (int d = 0; d < 64; d++) {
            float4 a  = *(const float4*)&Qts[d * 64 + tr];
            float4 bk = *(const float4*)&KVs[d * 64 + tc];
            s[0][0] += a.x * bk.x; s[0][1] += a.x * bk.y; s[0][2] += a.x * bk.z; s[0][3] += a.x * bk.w;
            s[1][0] += a.y * bk.x; s[1][1] += a.y * bk.y; s[1][2] += a.y * bk.z; s[1][3] += a.y * bk.w;
            s[2][0] += a.z * bk.x; s[2][1] += a.z * bk.y; s[2][2] += a.z * bk.z; s[2][3] += a.z * bk.w;
            s[3][0] += a.w * bk.x; s[3][1] += a.w * bk.y; s[3][2] += a.w * bk.z; s[3][3] += a.w * bk.w;
        }
        #pragma unroll
        for (int j = 0; j < 4; j++)
            #pragma unroll
            for (int i = 0; i < 4; i++)
                Pts[(tc + j) * 68 + (tr + i)] = s[i][j];
        __syncthreads();

        {
            int warp = tid >> 5, lane = tid & 31;
            for (int rr = 0; rr < 8; rr++) {
                int rw = warp * 8 + rr;
                float v0 = Pts[lane * 68 + rw];
                float v1 = Pts[(lane + 32) * 68 + rw];
                float mx = fmaxf(v0, v1);
                #pragma unroll
                for (int off = 16; off; off >>= 1)
                    mx = fmaxf(mx, __shfl_xor_sync(0xffffffffu, mx, off));
                float mold = m_s[rw];
                float mnew = fmaxf(mold, mx);
                float p0 = __expf(v0 - mnew), p1 = __expf(v1 - mnew);
                Pts[lane * 68 + rw] = p0;
                Pts[(lane + 32) * 68 + rw] = p1;
                float sum = p0 + p1;
                #pragma unroll
                for (int off = 16; off; off >>= 1)
                    sum += __shfl_xor_sync(0xffffffffu, sum, off);
                if (lane == 0) {
                    float f = __expf(mold - mnew);
                    l_s[rw] = l_s[rw] * f + sum;
                    m_s[rw] = mnew;
                    f_s[rw] = f;
                }
            }
        }
        __syncthreads();

        #pragma unroll
        for (int i = 0; i < 4; i++) {
            int idx = tid + i * 256;
            int r  = idx >> 4;
            int c4 = (idx & 15) * 4;
            float4 v4 = *(const float4*)(Vbase + (size_t)(kt * 64 + r) * DIM + c4);
            *(float4*)&KVs[r * 64 + c4] = v4;
        }
        __syncthreads();

        float f0 = f_s[tr], f1 = f_s[tr + 1], f2 = f_s[tr + 2], f3 = f_s[tr + 3];
        #pragma unroll
        for (int j = 0; j < 4; j++) {
            o[0][j] *= f0; o[1][j] *= f1; o[2][j] *= f2; o[3][j] *= f3;
        }
        #pragma unroll
        for (int kk = 0; kk < 64; kk++) {
            float4 a  = *(const float4*)&Pts[kk * 68 + tr];
            float4 bv = *(const float4*)&KVs[kk * 64 + tc];
            o[0][0] += a.x * bv.x; o[0][1] += a.x * bv.y; o[0][2] += a.x * bv.z; o[0][3] += a.x * bv.w;
            o[1][0] += a.y * bv.x; o[1][1] += a.y * bv.y; o[1][2] += a.y * bv.z; o[1][3] += a.y * bv.w;
            o[2][0] += a.z * bv.x; o[2][1] += a.z * bv.y; o[2][2] += a.z * bv.z; o[2][3] += a.z * bv.w;
            o[3][0] += a.w * bv.x; o[3][1] += a.w * bv.y; o[3][2] += a.w * bv.z; o[3][3] += a.w * bv.w;
        }
    }

    float* Cb = ctx + ((size_t)(b * NQ + qt * 64)) * DIM + h * HD;
    #pragma unroll
    for (int i = 0; i < 4; i++) {
        float inv = 1.0f / l_s[tr + i];
        float4 r4 = make_float4(o[i][0] * inv, o[i][1] * inv, o[i][2] * inv, o[i][3] * inv);
        *(float4*)(Cb + (size_t)(tr + i) * DIM + tc) = r4;
    }
}

// ==================== launch =================================================
extern "C" void kernel_launch(void* const* d_in, const int* in_sizes, int n_in,
                              void* d_out, int out_size)
{
    const float* tgt  = (const float*)d_in[0];
    const float* emb  = (const float*)d_in[1];
    const float* ln_g = (const float*)d_in[2];
    const float* ln_b = (const float*)d_in[3];
    const float* wq = (const float*)d_in[4];  const float* bq = (const float*)d_in[5];
    const float* wk = (const float*)d_in[6];  const float* bk = (const float*)d_in[7];
    const float* wv = (const float*)d_in[8];  const float* bv = (const float*)d_in[9];
    const float* wo = (const float*)d_in[10]; const float* bo = (const float*)d_in[11];
    const float* w1 = (const float*)d_in[12]; const float* b1 = (const float*)d_in[13];
    const float* w2 = (const float*)d_in[14]; const float* b2 = (const float*)d_in[15];
    float* out = (float*)d_out;

    float *qn, *q, *k, *v, *ctx, *h1;
    cudaGetSymbolAddress((void**)&qn,  g_qn);
    cudaGetSymbolAddress((void**)&q,   g_q);
    cudaGetSymbolAddress((void**)&k,   g_k);
    cudaGetSymbolAddress((void**)&v,   g_v);
    cudaGetSymbolAddress((void**)&ctx, g_ctx);
    cudaGetSymbolAddress((void**)&h1,  g_h1);

    const size_t att_smem = (size_t)ATT_SMEM_FLOATS * sizeof(float);
    cudaFuncSetAttribute(attn_kernel, cudaFuncAttributeMaxDynamicSharedMemorySize,
                         (int)att_smem);
    cudaFuncSetAttribute(tf32_gemm, cudaFuncAttributeMaxDynamicSharedMemorySize,
                         GEMM_SMEM);

    // 1) qn = LN(tgt)
    ln_kernel<<<MQ, 256>>>(tgt, ln_g, ln_b, qn);

    // 2) Q = qn @ wq + bq
    tf32_gemm<<<dim3(DIM / 128, MQ / 128), 256, GEMM_SMEM>>>(MQ, DIM, DIM, qn, wq, bq, nullptr, q, 0);
    // 3) K = emb @ wk + bk
    tf32_gemm<<<dim3(DIM / 128, MK / 128), 256, GEMM_SMEM>>>(MK, DIM, DIM, emb, wk, bk, nullptr, k, 0);
    // 4) V = emb @ wv + bv
    tf32_gemm<<<dim3(DIM / 128, MK / 128), 256, GEMM_SMEM>>>(MK, DIM, DIM, emb, wv, bv, nullptr, v, 0);

    // 5) ctx = softmax(Q K^T / sqrt(d)) V
    attn_kernel<<<dim3(NQ / 64, HEADS, BSZ), 256, att_smem>>>(q, k, v, ctx);

    // 6) tgt1 = tgt + ctx @ wo + bo   -> d_out
    tf32_gemm<<<dim3(DIM / 128, MQ / 128), 256, GEMM_SMEM>>>(MQ, DIM, DIM, ctx, wo, bo, tgt, out, 2);

    // 7) h_in = LN(tgt1)
    ln_kernel<<<MQ, 256>>>(out, ln_g, ln_b, qn);

    // 8) h1 = gelu(h_in @ w1 + b1)
    tf32_gemm<<<dim3(HIDDEN / 128, MQ / 128), 256, GEMM_SMEM>>>(MQ, HIDDEN, DIM, qn, w1, b1, nullptr, h1, 1);

    // 9) out = tgt1 + h1 @ w2 + b2   (in-place residual on d_out)
    tf32_gemm<<<dim3(DIM / 128, MQ / 128), 256, GEMM_SMEM>>>(MQ, DIM, HIDDEN, h1, w2, b2, out, out, 2);
}

// round 3
// speedup vs baseline: 3.2828x; 1.7254x over previous
#include <cuda_runtime.h>
#include <math.h>
#include <stdint.h>

// ---------------- problem constants ----------------
#define BSZ     4
#define NQ      1024
#define NK      2048
#define DIM     1024
#define HEADS   16
#define HD      64
#define HIDDEN  4096
#define MQ      (BSZ*NQ)   // 4096
#define MK      (BSZ*NK)   // 8192

// ---------------- scratch ----------
__device__ float g_qn [(size_t)MQ * DIM];
__device__ float g_q  [(size_t)MQ * DIM];
__device__ float g_k  [(size_t)MK * DIM];
__device__ float g_v  [(size_t)MK * DIM];
__device__ float g_ctx[(size_t)MQ * DIM];
__device__ float g_h1 [(size_t)MQ * HIDDEN];

// ==================== LayerNorm ====================
__global__ __launch_bounds__(256)
void ln_kernel(const float* __restrict__ x, const float* __restrict__ g,
               const float* __restrict__ bt, float* __restrict__ out)
{
    int row = blockIdx.x;
    int t = threadIdx.x;
    const float4* xr = (const float4*)(x + (size_t)row * DIM);
    float4 v = xr[t];
    float s  = v.x + v.y + v.z + v.w;
    float sq = v.x*v.x + v.y*v.y + v.z*v.z + v.w*v.w;

    #pragma unroll
    for (int off = 16; off; off >>= 1) {
        s  += __shfl_xor_sync(0xffffffffu, s,  off);
        sq += __shfl_xor_sync(0xffffffffu, sq, off);
    }
    __shared__ float ss[8], sqs[8];
    int warp = t >> 5, lane = t & 31;
    if (lane == 0) { ss[warp] = s; sqs[warp] = sq; }
    __syncthreads();
    if (t < 32) {
        float a = (t < 8) ? ss[t]  : 0.f;
        float b = (t < 8) ? sqs[t] : 0.f;
        #pragma unroll
        for (int off = 4; off; off >>= 1) {
            a += __shfl_xor_sync(0xffffffffu, a, off);
            b += __shfl_xor_sync(0xffffffffu, b, off);
        }
        if (t == 0) { ss[0] = a; sqs[0] = b; }
    }
    __syncthreads();
    float mu  = ss[0]  * (1.0f / DIM);
    float var = sqs[0] * (1.0f / DIM) - mu * mu;
    float inv = rsqrtf(var + 1e-5f);

    float4 gv = ((const float4*)g)[t];
    float4 bv = ((const float4*)bt)[t];
    float4 o;
    o.x = (v.x - mu) * inv * gv.x + bv.x;
    o.y = (v.y - mu) * inv * gv.y + bv.y;
    o.z = (v.z - mu) * inv * gv.z + bv.z;
    o.w = (v.w - mu) * inv * gv.w + bv.w;
    ((float4*)(out + (size_t)row * DIM))[t] = o;
}

// ==================== helpers ====================
__device__ __forceinline__ float gelu_exact(float x) {
    return 0.5f * x * (1.0f + erff(x * 0.70710678118654752f));
}
__device__ __forceinline__ uint32_t f2tf32(float x) {
    uint32_t r;
    asm("cvt.rna.tf32.f32 %0, %1;" : "=r"(r) : "f"(x));
    return r;
}
__device__ __forceinline__ void mma_tf32(float d[4], const uint32_t a[4], const uint32_t b[2]) {
    asm volatile(
        "mma.sync.aligned.m16n8k8.row.col.f32.tf32.tf32.f32 "
        "{%0,%1,%2,%3}, {%4,%5,%6,%7}, {%8,%9}, {%0,%1,%2,%3};"
        : "+f"(d[0]), "+f"(d[1]), "+f"(d[2]), "+f"(d[3])
        : "r"(a[0]), "r"(a[1]), "r"(a[2]), "r"(a[3]), "r"(b[0]), "r"(b[1]));
}
__device__ __forceinline__ void cp16(void* s, const void* g) {
    uint32_t sa = (uint32_t)__cvta_generic_to_shared(s);
    asm volatile("cp.async.ca.shared.global [%0], [%1], 16;" :: "r"(sa), "l"(g));
}

// ==================== tf32 tensor-core GEMM (unchanged from R2) ====================
#define SKA 36
#define SKB 136
#define ASZ (128*SKA)
#define BSZ_SM (32*SKB)
#define GEMM_SMEM ((2*(ASZ+BSZ_SM))*4)

__global__ __launch_bounds__(256, 1)
void tf32_gemm(int M, int N, int K,
               const float* __restrict__ A,
               const float* __restrict__ B,
               const float* __restrict__ bias,
               const float* __restrict__ res,
               float* __restrict__ C, int mode)
{
    extern __shared__ uint32_t sm[];
    uint32_t* AsBase = sm;
    uint32_t* BsBase = sm + 2 * ASZ;

    int tid = threadIdx.x;
    int lane = tid & 31;
    int warp = tid >> 5;
    int wr = warp >> 1;
    int wc = warp & 1;
    int warp_m = wr * 32;
    int warp_n = wc * 64;
    int r = lane >> 2;
    int c = lane & 3;

    int ctaM = blockIdx.y * 128;
    int ctaN = blockIdx.x * 128;

    const float* Ab = A + (size_t)ctaM * K;
    const float* Bb = B + ctaN;

    int aRow = tid >> 3;
    int aK4  = (tid & 7) * 4;

    float4 Ar[4], Br[4];
    float acc[2][8][4] = {};

    #pragma unroll
    for (int i = 0; i < 4; i++)
        Ar[i] = *(const float4*)(Ab + (size_t)(aRow + i * 32) * K + aK4);
    #pragma unroll
    for (int i = 0; i < 4; i++) {
        int idx = tid + i * 256;
        int bk = idx >> 5, bn = (idx & 31) * 4;
        Br[i] = *(const float4*)(Bb + (size_t)bk * N + bn);
    }
    #pragma unroll
    for (int i = 0; i < 4; i++) {
        uint32_t* p = AsBase + (size_t)(aRow + i * 32) * SKA + aK4;
        p[0] = f2tf32(Ar[i].x); p[1] = f2tf32(Ar[i].y);
        p[2] = f2tf32(Ar[i].z); p[3] = f2tf32(Ar[i].w);
    }
    #pragma unroll
    for (int i = 0; i < 4; i++) {
        int idx = tid + i * 256;
        int bk = idx >> 5, bn = (idx & 31) * 4;
        uint32_t* p = BsBase + (size_t)bk * SKB + bn;
        p[0] = f2tf32(Br[i].x); p[1] = f2tf32(Br[i].y);
        p[2] = f2tf32(Br[i].z); p[3] = f2tf32(Br[i].w);
    }
    __syncthreads();

    int buf = 0;
    for (int k0 = 0; k0 < K; k0 += 32) {
        bool more = (k0 + 32) < K;
        if (more) {
            const float* An = Ab + (k0 + 32);
            const float* Bn = Bb + (size_t)(k0 + 32) * N;
            #pragma unroll
            for (int i = 0; i < 4; i++)
                Ar[i] = *(const float4*)(An + (size_t)(aRow + i * 32) * K + aK4);
            #pragma unroll
            for (int i = 0; i < 4; i++) {
                int idx = tid + i * 256;
                int bk = idx >> 5, bn = (idx & 31) * 4;
                Br[i] = *(const float4*)(Bn + (size_t)bk * N + bn);
            }
        }

        const uint32_t* Asb = AsBase + buf * ASZ;
        const uint32_t* Bsb = BsBase + buf * BSZ_SM;
        #pragma unroll
        for (int ks = 0; ks < 4; ks++) {
            uint32_t af[2][4], bf[8][2];
            #pragma unroll
            for (int mt = 0; mt < 2; mt++) {
                int m0 = warp_m + mt * 16;
                const uint32_t* pa = Asb + (size_t)(m0 + r) * SKA + ks * 8 + c;
                af[mt][0] = pa[0];
                af[mt][2] = pa[4];
                af[mt][1] = pa[8 * SKA];
                af[mt][3] = pa[8 * SKA + 4];
            }
            #pragma unroll
            for (int nt = 0; nt < 8; nt++) {
                int n0 = warp_n + nt * 8;
                const uint32_t* pb = Bsb + (size_t)(ks * 8 + c) * SKB + n0 + r;
                bf[nt][0] = pb[0];
                bf[nt][1] = pb[4 * SKB];
            }
            #pragma unroll
            for (int mt = 0; mt < 2; mt++)
                #pragma unroll
                for (int nt = 0; nt < 8; nt++)
                    mma_tf32(acc[mt][nt], af[mt], bf[nt]);
        }

        if (more) {
            uint32_t* Asw = AsBase + (buf ^ 1) * ASZ;
            uint32_t* Bsw = BsBase + (buf ^ 1) * BSZ_SM;
            #pragma unroll
            for (int i = 0; i < 4; i++) {
                uint32_t* p = Asw + (size_t)(aRow + i * 32) * SKA + aK4;
                p[0] = f2tf32(Ar[i].x); p[1] = f2tf32(Ar[i].y);
                p[2] = f2tf32(Ar[i].z); p[3] = f2tf32(Ar[i].w);
            }
            #pragma unroll
            for (int i = 0; i < 4; i++) {
                int idx = tid + i * 256;
                int bk = idx >> 5, bn = (idx & 31) * 4;
                uint32_t* p = Bsw + (size_t)bk * SKB + bn;
                p[0] = f2tf32(Br[i].x); p[1] = f2tf32(Br[i].y);
                p[2] = f2tf32(Br[i].z); p[3] = f2tf32(Br[i].w);
            }
            __syncthreads();
            buf ^= 1;
        }
    }

    #pragma unroll
    for (int mt = 0; mt < 2; mt++) {
        #pragma unroll
        for (int nt = 0; nt < 8; nt++) {
            int row = ctaM + warp_m + mt * 16 + r;
            int col = ctaN + warp_n + nt * 8 + 2 * c;
            float b0 = bias[col], b1 = bias[col + 1];
            float v0 = acc[mt][nt][0] + b0;
            float v1 = acc[mt][nt][1] + b1;
            float v2 = acc[mt][nt][2] + b0;
            float v3 = acc[mt][nt][3] + b1;
            if (mode == 1) {
                v0 = gelu_exact(v0); v1 = gelu_exact(v1);
                v2 = gelu_exact(v2); v3 = gelu_exact(v3);
            } else if (mode == 2) {
                const float* r0 = res + (size_t)row * N + col;
                const float* r1 = res + (size_t)(row + 8) * N + col;
                v0 += r0[0]; v1 += r0[1];
                v2 += r1[0]; v3 += r1[1];
            }
            *(float2*)(C + (size_t)row * N + col)       = make_float2(v0, v1);
            *(float2*)(C + (size_t)(row + 8) * N + col) = make_float2(v2, v3);
        }
    }
}

// ==================== tensor-core flash attention ====================
// CTA: 128 q-rows, 8 warps x (16q x 64k). K/V tiles of 64 keys, cp.async
// double-buffered. Q fragments resident in registers. P reshaped via
// warp-private smem. All values fed to mma as raw f32 bits (HW tf32 truncation).
#define BQ_T   128
#define TILE_K 64
#define SKK 68     // K smem stride: bank = 4r+c, conflict-free
#define SKV 72     // V smem stride: bank = 8c+r, conflict-free
#define SKP 72
#define NT_KV (NK / TILE_K)    // 32
#define ATT_SMEM ((2*TILE_K*SKK + 2*TILE_K*SKV + BQ_T*SKP) * 4)  // 108544 B

__global__ __launch_bounds__(256, 1)
void attn_mma(const float* __restrict__ Q, const float* __restrict__ Kg,
              const float* __restrict__ Vg, float* __restrict__ ctx)
{
    extern __shared__ float smf[];
    float* KsB = smf;                               // [2][TILE_K][SKK]
    float* VsB = smf + 2 * TILE_K * SKK;            // [2][TILE_K][SKV]
    float* Ps  = smf + 2 * TILE_K * (SKK + SKV);    // [128][SKP]

    int b = blockIdx.z, h = blockIdx.y, qt = blockIdx.x;
    int tid = threadIdx.x, lane = tid & 31, w = tid >> 5;
    int r = lane >> 2, c = lane & 3;

    const float* Qb = Q  + ((size_t)(b * NQ + qt * BQ_T)) * DIM + h * HD;
    const float* Kb = Kg + ((size_t)b * NK) * DIM + h * HD;
    const float* Vb = Vg + ((size_t)b * NK) * DIM + h * HD;

    // issue K/V tile 0
    #pragma unroll
    for (int i = 0; i < 4; i++) {
        int idx = tid + i * 256, row = idx >> 4, c4 = (idx & 15) * 4;
        cp16(&KsB[row * SKK + c4], Kb + (size_t)row * DIM + c4);
        cp16(&VsB[row * SKV + c4], Vb + (size_t)row * DIM + c4);
    }
    asm volatile("cp.async.commit_group;");

    // Q fragments (scaled by 1/sqrt(64))
    uint32_t qf[8][4];
    {
        const float* q0 = Qb + (size_t)(w * 16 + r) * DIM;
        const float* q1 = Qb + (size_t)(w * 16 + r + 8) * DIM;
        #pragma unroll
        for (int kg = 0; kg < 8; kg++) {
            qf[kg][0] = __float_as_uint(q0[kg * 8 + c]     * 0.125f);
            qf[kg][1] = __float_as_uint(q1[kg * 8 + c]     * 0.125f);
            qf[kg][2] = __float_as_uint(q0[kg * 8 + c + 4] * 0.125f);
            qf[kg][3] = __float_as_uint(q1[kg * 8 + c + 4] * 0.125f);
        }
    }

    float m0 = -1e30f, m1 = -1e30f, l0 = 0.f, l1 = 0.f;
    float accO[8][4] = {};
    float* Pw = Ps + (w * 16) * SKP;

    for (int kt = 0; kt < NT_KV; kt++) {
        int buf = kt & 1;
        asm volatile("cp.async.wait_group 0;");
        __syncthreads();

        if (kt + 1 < NT_KV) {
            const float* kp = Kb + (size_t)(kt + 1) * TILE_K * DIM;
            const float* vp = Vb + (size_t)(kt + 1) * TILE_K * DIM;
            float* Kd = KsB + (buf ^ 1) * TILE_K * SKK;
            float* Vd = VsB + (buf ^ 1) * TILE_K * SKV;
            #pragma unroll
            for (int i = 0; i < 4; i++) {
                int idx = tid + i * 256, row = idx >> 4, c4 = (idx & 15) * 4;
                cp16(&Kd[row * SKK + c4], kp + (size_t)row * DIM + c4);
                cp16(&Vd[row * SKV + c4], vp + (size_t)row * DIM + c4);
            }
            asm volatile("cp.async.commit_group;");
        }

        const float* Kt = KsB + buf * TILE_K * SKK;
        const float* Vt = VsB + buf * TILE_K * SKV;

        // S = Q @ K^T : warp computes 16x64
        float accS[8][4] = {};
        #pragma unroll
        for (int kg = 0; kg < 8; kg++) {
            uint32_t bf[8][2];
            #pragma unroll
            for (int nt = 0; nt < 8; nt++) {
                bf[nt][0] = __float_as_uint(Kt[(nt * 8 + r) * SKK + kg * 8 + c]);
                bf[nt][1] = __float_as_uint(Kt[(nt * 8 + r) * SKK + kg * 8 + c + 4]);
            }
            #pragma unroll
            for (int nt = 0; nt < 8; nt++)
                mma_tf32(accS[nt], qf[kg], bf[nt]);
        }

        // online softmax (rows r and r+8 of warp tile)
        float mx0 = -1e30f, mx1 = -1e30f;
        #pragma unroll
        for (int nt = 0; nt < 8; nt++) {
            mx0 = fmaxf(mx0, fmaxf(accS[nt][0], accS[nt][1]));
            mx1 = fmaxf(mx1, fmaxf(accS[nt][2], accS[nt][3]));
        }
        mx0 = fmaxf(mx0, __shfl_xor_sync(0xffffffffu, mx0, 1));
        mx0 = fmaxf(mx0, __shfl_xor_sync(0xffffffffu, mx0, 2));
        mx1 = fmaxf(mx1, __shfl_xor_sync(0xffffffffu, mx1, 1));
        mx1 = fmaxf(mx1, __shfl_xor_sync(0xffffffffu, mx1, 2));
        float mn0 = fmaxf(m0, mx0), mn1 = fmaxf(m1, mx1);
        float f0 = __expf(m0 - mn0), f1 = __expf(m1 - mn1);
        float s0 = 0.f, s1 = 0.f;
        #pragma unroll
        for (int nt = 0; nt < 8; nt++) {
            accS[nt][0] = __expf(accS[nt][0] - mn0);
            accS[nt][1] = __expf(accS[nt][1] - mn0);
            accS[nt][2] = __expf(accS[nt][2] - mn1);
            accS[nt][3] = __expf(accS[nt][3] - mn1);
            s0 += accS[nt][0] + accS[nt][1];
            s1 += accS[nt][2] + accS[nt][3];
        }
        s0 += __shfl_xor_sync(0xffffffffu, s0, 1);
        s0 += __shfl_xor_sync(0xffffffffu, s0, 2);
        s1 += __shfl_xor_sync(0xffffffffu, s1, 1);
        s1 += __shfl_xor_sync(0xffffffffu, s1, 2);
        l0 = l0 * f0 + s0; l1 = l1 * f1 + s1;
        m0 = mn0; m1 = mn1;
        #pragma unroll
        for (int nt = 0; nt < 8; nt++) {
            accO[nt][0] *= f0; accO[nt][1] *= f0;
            accO[nt][2] *= f1; accO[nt][3] *= f1;
        }

        // P -> warp-private smem (reshape C-frag to A-frag)
        #pragma unroll
        for (int nt = 0; nt < 8; nt++) {
            *(float2*)&Pw[r * SKP + nt * 8 + 2 * c]       = make_float2(accS[nt][0], accS[nt][1]);
            *(float2*)&Pw[(r + 8) * SKP + nt * 8 + 2 * c] = make_float2(accS[nt][2], accS[nt][3]);
        }
        __syncwarp();

        // O += P @ V
        #pragma unroll
        for (int kg = 0; kg < 8; kg++) {
            uint32_t af[4];
            af[0] = __float_as_uint(Pw[r * SKP + kg * 8 + c]);
            af[1] = __float_as_uint(Pw[(r + 8) * SKP + kg * 8 + c]);
            af[2] = __float_as_uint(Pw[r * SKP + kg * 8 + c + 4]);
            af[3] = __float_as_uint(Pw[(r + 8) * SKP + kg * 8 + c + 4]);
            #pragma unroll
            for (int nt = 0; nt < 8; nt++) {
                uint32_t bb[2];
                bb[0] = __float_as_uint(Vt[(kg * 8 + c) * SKV + nt * 8 + r]);
                bb[1] = __float_as_uint(Vt[(kg * 8 + c + 4) * SKV + nt * 8 + r]);
                mma_tf32(accO[nt], af, bb);
            }
        }
        __syncwarp();  // all lanes done reading Pw before next iter overwrites
    }

    // epilogue: divide by l, write ctx
    float inv0 = 1.f / l0, inv1 = 1.f / l1;
    float* Cb = ctx + ((size_t)(b * NQ + qt * BQ_T + w * 16)) * DIM + h * HD;
    #pragma unroll
    for (int nt = 0; nt < 8; nt++) {
        *(float2*)&Cb[(size_t)r * DIM + nt * 8 + 2 * c] =
            make_float2(accO[nt][0] * inv0, accO[nt][1] * inv0);
        *(float2*)&Cb[(size_t)(r + 8) * DIM + nt * 8 + 2 * c] =
            make_float2(accO[nt][2] * inv1, accO[nt][3] * inv1);
    }
}

// ==================== launch =================================================
extern "C" void kernel_launch(void* const* d_in, const int* in_sizes, int n_in,
                              void* d_out, int out_size)
{
    const float* tgt  = (const float*)d_in[0];
    const float* emb  = (const float*)d_in[1];
    const float* ln_g = (const float*)d_in[2];
    const float* ln_b = (const float*)d_in[3];
    const float* wq = (const float*)d_in[4];  const float* bq = (const float*)d_in[5];
    const float* wk = (const float*)d_in[6];  const float* bk = (const float*)d_in[7];
    const float* wv = (const float*)d_in[8];  const float* bv = (const float*)d_in[9];
    const float* wo = (const float*)d_in[10]; const float* bo = (const float*)d_in[11];
    const float* w1 = (const float*)d_in[12]; const float* b1 = (const float*)d_in[13];
    const float* w2 = (const float*)d_in[14]; const float* b2 = (const float*)d_in[15];
    float* out = (float*)d_out;

    float *qn, *q, *k, *v, *ctx, *h1;
    cudaGetSymbolAddress((void**)&qn,  g_qn);
    cudaGetSymbolAddress((void**)&q,   g_q);
    cudaGetSymbolAddress((void**)&k,   g_k);
    cudaGetSymbolAddress((void**)&v,   g_v);
    cudaGetSymbolAddress((void**)&ctx, g_ctx);
    cudaGetSymbolAddress((void**)&h1,  g_h1);

    cudaFuncSetAttribute(tf32_gemm, cudaFuncAttributeMaxDynamicSharedMemorySize,
                         GEMM_SMEM);
    cudaFuncSetAttribute(attn_mma, cudaFuncAttributeMaxDynamicSharedMemorySize,
                         ATT_SMEM);

    // 1) qn = LN(tgt)
    ln_kernel<<<MQ, 256>>>(tgt, ln_g, ln_b, qn);

    // 2-4) projections
    tf32_gemm<<<dim3(DIM / 128, MQ / 128), 256, GEMM_SMEM>>>(MQ, DIM, DIM, qn, wq, bq, nullptr, q, 0);
    tf32_gemm<<<dim3(DIM / 128, MK / 128), 256, GEMM_SMEM>>>(MK, DIM, DIM, emb, wk, bk, nullptr, k, 0);
    tf32_gemm<<<dim3(DIM / 128, MK / 128), 256, GEMM_SMEM>>>(MK, DIM, DIM, emb, wv, bv, nullptr, v, 0);

    // 5) ctx = softmax(Q K^T / sqrt(d)) V   (tensor-core flash)
    attn_mma<<<dim3(NQ / BQ_T, HEADS, BSZ), 256, ATT_SMEM>>>(q, k, v, ctx);

    // 6) tgt1 = tgt + ctx @ wo + bo -> d_out
    tf32_gemm<<<dim3(DIM / 128, MQ / 128), 256, GEMM_SMEM>>>(MQ, DIM, DIM, ctx, wo, bo, tgt, out, 2);

    // 7) h_in = LN(tgt1)
    ln_kernel<<<MQ, 256>>>(out, ln_g, ln_b, qn);

    // 8) h1 = gelu(h_in @ w1 + b1)
    tf32_gemm<<<dim3(HIDDEN / 128, MQ / 128), 256, GEMM_SMEM>>>(MQ, HIDDEN, DIM, qn, w1, b1, nullptr, h1, 1);

    // 9) out = tgt1 + h1 @ w2 + b2
    tf32_gemm<<<dim3(DIM / 128, MQ / 128), 256, GEMM_SMEM>>>(MQ, DIM, HIDDEN, h1, w2, b2, out, out, 2);
}

// round 4
// speedup vs baseline: 3.5854x; 1.0922x over previous
#include <cuda_runtime.h>
#include <math.h>
#include <stdint.h>

// ---------------- problem constants ----------------
#define BSZ     4
#define NQ      1024
#define NK      2048
#define DIM     1024
#define HEADS   16
#define HD      64
#define HIDDEN  4096
#define MQ      (BSZ*NQ)   // 4096
#define MK      (BSZ*NK)   // 8192

// ---------------- scratch ----------
__device__ float g_qn [(size_t)MQ * DIM];
__device__ float g_q  [(size_t)MQ * DIM];
__device__ float g_k  [(size_t)MK * DIM];
__device__ float g_v  [(size_t)MK * DIM];
__device__ float g_ctx[(size_t)MQ * DIM];
__device__ float g_h1 [(size_t)MQ * HIDDEN];

// ==================== LayerNorm ====================
__global__ __launch_bounds__(256)
void ln_kernel(const float* __restrict__ x, const float* __restrict__ g,
               const float* __restrict__ bt, float* __restrict__ out)
{
    int row = blockIdx.x;
    int t = threadIdx.x;
    const float4* xr = (const float4*)(x + (size_t)row * DIM);
    float4 v = xr[t];
    float s  = v.x + v.y + v.z + v.w;
    float sq = v.x*v.x + v.y*v.y + v.z*v.z + v.w*v.w;

    #pragma unroll
    for (int off = 16; off; off >>= 1) {
        s  += __shfl_xor_sync(0xffffffffu, s,  off);
        sq += __shfl_xor_sync(0xffffffffu, sq, off);
    }
    __shared__ float ss[8], sqs[8];
    int warp = t >> 5, lane = t & 31;
    if (lane == 0) { ss[warp] = s; sqs[warp] = sq; }
    __syncthreads();
    if (t < 32) {
        float a = (t < 8) ? ss[t]  : 0.f;
        float b = (t < 8) ? sqs[t] : 0.f;
        #pragma unroll
        for (int off = 4; off; off >>= 1) {
            a += __shfl_xor_sync(0xffffffffu, a, off);
            b += __shfl_xor_sync(0xffffffffu, b, off);
        }
        if (t == 0) { ss[0] = a; sqs[0] = b; }
    }
    __syncthreads();
    float mu  = ss[0]  * (1.0f / DIM);
    float var = sqs[0] * (1.0f / DIM) - mu * mu;
    float inv = rsqrtf(var + 1e-5f);

    float4 gv = ((const float4*)g)[t];
    float4 bv = ((const float4*)bt)[t];
    float4 o;
    o.x = (v.x - mu) * inv * gv.x + bv.x;
    o.y = (v.y - mu) * inv * gv.y + bv.y;
    o.z = (v.z - mu) * inv * gv.z + bv.z;
    o.w = (v.w - mu) * inv * gv.w + bv.w;
    ((float4*)(out + (size_t)row * DIM))[t] = o;
}

// ==================== helpers ====================
__device__ __forceinline__ float gelu_exact(float x) {
    return 0.5f * x * (1.0f + erff(x * 0.70710678118654752f));
}
__device__ __forceinline__ void mma_tf32(float d[4], const uint32_t a[4], const uint32_t b[2]) {
    asm volatile(
        "mma.sync.aligned.m16n8k8.row.col.f32.tf32.tf32.f32 "
        "{%0,%1,%2,%3}, {%4,%5,%6,%7}, {%8,%9}, {%0,%1,%2,%3};"
        : "+f"(d[0]), "+f"(d[1]), "+f"(d[2]), "+f"(d[3])
        : "r"(a[0]), "r"(a[1]), "r"(a[2]), "r"(a[3]), "r"(b[0]), "r"(b[1]));
}
__device__ __forceinline__ void cp16(void* s, const void* g) {
    uint32_t sa = (uint32_t)__cvta_generic_to_shared(s);
    asm volatile("cp.async.ca.shared.global [%0], [%1], 16;" :: "r"(sa), "l"(g));
}

// ==================== tf32 GEMM v3: cp.async 3-stage, 2 CTAs/SM ====================
// C[M,N] = A[M,K] @ B[K,N] + bias (+gelu | +residual)
// CTA 128x128, KC=32, 8 warps x (32m x 64n). Raw fp32 bits -> mma tf32.
#define KC   32
#define SKA  36                 // As [m][k], banks 4r+c distinct; 36*4 % 16 == 0
#define SKB  136                // Bs [k][n], banks 8c+r distinct; 136*4 % 16 == 0
#define A_ST (128*SKA)          // 4608 words
#define B_ST (KC*SKB)           // 4352 words
#define ST_W (A_ST + B_ST)      // 8960 words / stage
#define GEMM_SMEM (3*ST_W*4)    // 107520 bytes

__global__ __launch_bounds__(256, 2)
void tf32_gemm(int M, int N, int K,
               const float* __restrict__ A,
               const float* __restrict__ B,
               const float* __restrict__ bias,
               const float* __restrict__ res,
               float* __restrict__ C, int mode)
{
    extern __shared__ uint32_t sm[];

    int tid = threadIdx.x;
    int lane = tid & 31;
    int warp = tid >> 5;
    int warp_m = (warp >> 1) * 32;
    int warp_n = (warp & 1) * 64;
    int r = lane >> 2;
    int c = lane & 3;

    int ctaM = blockIdx.y * 128;
    int ctaN = blockIdx.x * 128;

    const float* Ab = A + (size_t)ctaM * K;
    const float* Bb = B + ctaN;

    int aRow = tid >> 3;              // 0..31 (+ i*32)
    int aK4  = (tid & 7) * 4;
    int bK   = tid >> 5;              // 0..7 (+ i*8)  [via idx = tid + i*256]
    int bN4  = (tid & 31) * 4;

    const int nk = K / KC;

    // issue a stage: copy A[128 x 32] and B[32 x 128] into stage s
    #define ISSUE_STAGE(s, k0)                                                   \
    do {                                                                         \
        uint32_t* As_ = sm + (s) * ST_W;                                         \
        uint32_t* Bs_ = As_ + A_ST;                                              \
        const float* An_ = Ab + (k0);                                            \
        const float* Bn_ = Bb + (size_t)(k0) * N;                                \
        _Pragma("unroll")                                                        \
        for (int i = 0; i < 4; i++) {                                            \
            int row = aRow + i * 32;                                             \
            cp16(As_ + (size_t)row * SKA + aK4, An_ + (size_t)row * K + aK4);    \
        }                                                                        \
        _Pragma("unroll")                                                        \
        for (int i = 0; i < 4; i++) {                                            \
            int kk = bK + i * 8;                                                 \
            cp16(Bs_ + (size_t)kk * SKB + bN4, Bn_ + (size_t)kk * N + bN4);      \
        }                                                                        \
        asm volatile("cp.async.commit_group;");                                  \
    } while (0)

    ISSUE_STAGE(0, 0);
    if (nk > 1) ISSUE_STAGE(1, KC);
    else        asm volatile("cp.async.commit_group;");   // keep group count sane

    float acc[2][8][4] = {};

    int buf = 0;
    for (int kt = 0; kt < nk; kt++) {
        if (kt + 2 < nk) {
            asm volatile("cp.async.wait_group 1;");
        } else {
            asm volatile("cp.async.wait_group 0;");
        }
        __syncthreads();

        const uint32_t* Asb = sm + buf * ST_W;
        const uint32_t* Bsb = Asb + A_ST;

        #pragma unroll
        for (int ks = 0; ks < 4; ks++) {
            uint32_t af[2][4], bf[8][2];
            #pragma unroll
            for (int mt = 0; mt < 2; mt++) {
                const uint32_t* pa = Asb + (size_t)(warp_m + mt * 16 + r) * SKA + ks * 8 + c;
                af[mt][0] = pa[0];
                af[mt][2] = pa[4];
                af[mt][1] = pa[8 * SKA];
                af[mt][3] = pa[8 * SKA + 4];
            }
            #pragma unroll
            for (int nt = 0; nt < 8; nt++) {
                const uint32_t* pb = Bsb + (size_t)(ks * 8 + c) * SKB + warp_n + nt * 8 + r;
                bf[nt][0] = pb[0];
                bf[nt][1] = pb[4 * SKB];
            }
            #pragma unroll
            for (int mt = 0; mt < 2; mt++)
                #pragma unroll
                for (int nt = 0; nt < 8; nt++)
                    mma_tf32(acc[mt][nt], af[mt], bf[nt]);
        }

        // prefetch stage kt+2 into the buffer we just finished
        if (kt + 2 < nk) {
            int s = (kt + 2) % 3;
            ISSUE_STAGE(s, (kt + 2) * KC);
        }
        buf = (buf + 1) % 3;
    }
    #undef ISSUE_STAGE

    // ---- epilogue ----
    #pragma unroll
    for (int mt = 0; mt < 2; mt++) {
        #pragma unroll
        for (int nt = 0; nt < 8; nt++) {
            int row = ctaM + warp_m + mt * 16 + r;
            int col = ctaN + warp_n + nt * 8 + 2 * c;
            float b0 = bias[col], b1 = bias[col + 1];
            float v0 = acc[mt][nt][0] + b0;
            float v1 = acc[mt][nt][1] + b1;
            float v2 = acc[mt][nt][2] + b0;
            float v3 = acc[mt][nt][3] + b1;
            if (mode == 1) {
                v0 = gelu_exact(v0); v1 = gelu_exact(v1);
                v2 = gelu_exact(v2); v3 = gelu_exact(v3);
            } else if (mode == 2) {
                const float* r0 = res + (size_t)row * N + col;
                const float* r1 = res + (size_t)(row + 8) * N + col;
                v0 += r0[0]; v1 += r0[1];
                v2 += r1[0]; v3 += r1[1];
            }
            *(float2*)(C + (size_t)row * N + col)       = make_float2(v0, v1);
            *(float2*)(C + (size_t)(row + 8) * N + col) = make_float2(v2, v3);
        }
    }
}

// ==================== tensor-core flash attention (unchanged, R3) ====================
#define BQ_T   128
#define TILE_K 64
#define SKK 68
#define SKV 72
#define SKP 72
#define NT_KV (NK / TILE_K)
#define ATT_SMEM ((2*TILE_K*SKK + 2*TILE_K*SKV + BQ_T*SKP) * 4)

__global__ __launch_bounds__(256, 1)
void attn_mma(const float* __restrict__ Q, const float* __restrict__ Kg,
              const float* __restrict__ Vg, float* __restrict__ ctx)
{
    extern __shared__ float smf[];
    float* KsB = smf;
    float* VsB = smf + 2 * TILE_K * SKK;
    float* Ps  = smf + 2 * TILE_K * (SKK + SKV);

    int b = blockIdx.z, h = blockIdx.y, qt = blockIdx.x;
    int tid = threadIdx.x, lane = tid & 31, w = tid >> 5;
    int r = lane >> 2, c = lane & 3;

    const float* Qb = Q  + ((size_t)(b * NQ + qt * BQ_T)) * DIM + h * HD;
    const float* Kb = Kg + ((size_t)b * NK) * DIM + h * HD;
    const float* Vb = Vg + ((size_t)b * NK) * DIM + h * HD;

    #pragma unroll
    for (int i = 0; i < 4; i++) {
        int idx = tid + i * 256, row = idx >> 4, c4 = (idx & 15) * 4;
        cp16(&KsB[row * SKK + c4], Kb + (size_t)row * DIM + c4);
        cp16(&VsB[row * SKV + c4], Vb + (size_t)row * DIM + c4);
    }
    asm volatile("cp.async.commit_group;");

    uint32_t qf[8][4];
    {
        const float* q0 = Qb + (size_t)(w * 16 + r) * DIM;
        const float* q1 = Qb + (size_t)(w * 16 + r + 8) * DIM;
        #pragma unroll
        for (int kg = 0; kg < 8; kg++) {
            qf[kg][0] = __float_as_uint(q0[kg * 8 + c]     * 0.125f);
            qf[kg][1] = __float_as_uint(q1[kg * 8 + c]     * 0.125f);
            qf[kg][2] = __float_as_uint(q0[kg * 8 + c + 4] * 0.125f);
            qf[kg][3] = __float_as_uint(q1[kg * 8 + c + 4] * 0.125f);
        }
    }

    float m0 = -1e30f, m1 = -1e30f, l0 = 0.f, l1 = 0.f;
    float accO[8][4] = {};
    float* Pw = Ps + (w * 16) * SKP;

    for (int kt = 0; kt < NT_KV; kt++) {
        int buf = kt & 1;
        asm volatile("cp.async.wait_group 0;");
        __syncthreads();

        if (kt + 1 < NT_KV) {
            const float* kp = Kb + (size_t)(kt + 1) * TILE_K * DIM;
            const float* vp = Vb + (size_t)(kt + 1) * TILE_K * DIM;
            float* Kd = KsB + (buf ^ 1) * TILE_K * SKK;
            float* Vd = VsB + (buf ^ 1) * TILE_K * SKV;
            #pragma unroll
            for (int i = 0; i < 4; i++) {
                int idx = tid + i * 256, row = idx >> 4, c4 = (idx & 15) * 4;
                cp16(&Kd[row * SKK + c4], kp + (size_t)row * DIM + c4);
                cp16(&Vd[row * SKV + c4], vp + (size_t)row * DIM + c4);
            }
            asm volatile("cp.async.commit_group;");
        }

        const float* Kt = KsB + buf * TILE_K * SKK;
        const float* Vt = VsB + buf * TILE_K * SKV;

        float accS[8][4] = {};
        #pragma unroll
        for (int kg = 0; kg < 8; kg++) {
            uint32_t bf[8][2];
            #pragma unroll
            for (int nt = 0; nt < 8; nt++) {
                bf[nt][0] = __float_as_uint(Kt[(nt * 8 + r) * SKK + kg * 8 + c]);
                bf[nt][1] = __float_as_uint(Kt[(nt * 8 + r) * SKK + kg * 8 + c + 4]);
            }
            #pragma unroll
            for (int nt = 0; nt < 8; nt++)
                mma_tf32(accS[nt], qf[kg], bf[nt]);
        }

        float mx0 = -1e30f, mx1 = -1e30f;
        #pragma unroll
        for (int nt = 0; nt < 8; nt++) {
            mx0 = fmaxf(mx0, fmaxf(accS[nt][0], accS[nt][1]));
            mx1 = fmaxf(mx1, fmaxf(accS[nt][2], accS[nt][3]));
        }
        mx0 = fmaxf(mx0, __shfl_xor_sync(0xffffffffu, mx0, 1));
        mx0 = fmaxf(mx0, __shfl_xor_sync(0xffffffffu, mx0, 2));
        mx1 = fmaxf(mx1, __shfl_xor_sync(0xffffffffu, mx1, 1));
        mx1 = fmaxf(mx1, __shfl_xor_sync(0xffffffffu, mx1, 2));
        float mn0 = fmaxf(m0, mx0), mn1 = fmaxf(m1, mx1);
        float f0 = __expf(m0 - mn0), f1 = __expf(m1 - mn1);
        float s0 = 0.f, s1 = 0.f;
        #pragma unroll
        for (int nt = 0; nt < 8; nt++) {
            accS[nt][0] = __expf(accS[nt][0] - mn0);
            accS[nt][1] = __expf(accS[nt][1] - mn0);
            accS[nt][2] = __expf(accS[nt][2] - mn1);
            accS[nt][3] = __expf(accS[nt][3] - mn1);
            s0 += accS[nt][0] + accS[nt][1];
            s1 += accS[nt][2] + accS[nt][3];
        }
        s0 += __shfl_xor_sync(0xffffffffu, s0, 1);
        s0 += __shfl_xor_sync(0xffffffffu, s0, 2);
        s1 += __shfl_xor_sync(0xffffffffu, s1, 1);
        s1 += __shfl_xor_sync(0xffffffffu, s1, 2);
        l0 = l0 * f0 + s0; l1 = l1 * f1 + s1;
        m0 = mn0; m1 = mn1;
        #pragma unroll
        for (int nt = 0; nt < 8; nt++) {
            accO[nt][0] *= f0; accO[nt][1] *= f0;
            accO[nt][2] *= f1; accO[nt][3] *= f1;
        }

        #pragma unroll
        for (int nt = 0; nt < 8; nt++) {
            *(float2*)&Pw[r * SKP + nt * 8 + 2 * c]       = make_float2(accS[nt][0], accS[nt][1]);
            *(float2*)&Pw[(r + 8) * SKP + nt * 8 + 2 * c] = make_float2(accS[nt][2], accS[nt][3]);
        }
        __syncwarp();

        #pragma unroll
        for (int kg = 0; kg < 8; kg++) {
            uint32_t af[4];
            af[0] = __float_as_uint(Pw[r * SKP + kg * 8 + c]);
            af[1] = __float_as_uint(Pw[(r + 8) * SKP + kg * 8 + c]);
            af[2] = __float_as_uint(Pw[r * SKP + kg * 8 + c + 4]);
            af[3] = __float_as_uint(Pw[(r + 8) * SKP + kg * 8 + c + 4]);
            #pragma unroll
            for (int nt = 0; nt < 8; nt++) {
                uint32_t bb[2];
                bb[0] = __float_as_uint(Vt[(kg * 8 + c) * SKV + nt * 8 + r]);
                bb[1] = __float_as_uint(Vt[(kg * 8 + c + 4) * SKV + nt * 8 + r]);
                mma_tf32(accO[nt], af, bb);
            }
        }
        __syncwarp();
    }

    float inv0 = 1.f / l0, inv1 = 1.f / l1;
    float* Cb = ctx + ((size_t)(b * NQ + qt * BQ_T + w * 16)) * DIM + h * HD;
    #pragma unroll
    for (int nt = 0; nt < 8; nt++) {
        *(float2*)&Cb[(size_t)r * DIM + nt * 8 + 2 * c] =
            make_float2(accO[nt][0] * inv0, accO[nt][1] * inv0);
        *(float2*)&Cb[(size_t)(r + 8) * DIM + nt * 8 + 2 * c] =
            make_float2(accO[nt][2] * inv1, accO[nt][3] * inv1);
    }
}

// ==================== launch =================================================
extern "C" void kernel_launch(void* const* d_in, const int* in_sizes, int n_in,
                              void* d_out, int out_size)
{
    const float* tgt  = (const float*)d_in[0];
    const float* emb  = (const float*)d_in[1];
    const float* ln_g = (const float*)d_in[2];
    const float* ln_b = (const float*)d_in[3];
    const float* wq = (const float*)d_in[4];  const float* bq = (const float*)d_in[5];
    const float* wk = (const float*)d_in[6];  const float* bk = (const float*)d_in[7];
    const float* wv = (const float*)d_in[8];  const float* bv = (const float*)d_in[9];
    const float* wo = (const float*)d_in[10]; const float* bo = (const float*)d_in[11];
    const float* w1 = (const float*)d_in[12]; const float* b1 = (const float*)d_in[13];
    const float* w2 = (const float*)d_in[14]; const float* b2 = (const float*)d_in[15];
    float* out = (float*)d_out;

    float *qn, *q, *k, *v, *ctx, *h1;
    cudaGetSymbolAddress((void**)&qn,  g_qn);
    cudaGetSymbolAddress((void**)&q,   g_q);
    cudaGetSymbolAddress((void**)&k,   g_k);
    cudaGetSymbolAddress((void**)&v,   g_v);
    cudaGetSymbolAddress((void**)&ctx, g_ctx);
    cudaGetSymbolAddress((void**)&h1,  g_h1);

    cudaFuncSetAttribute(tf32_gemm, cudaFuncAttributeMaxDynamicSharedMemorySize,
                         GEMM_SMEM);
    cudaFuncSetAttribute(attn_mma, cudaFuncAttributeMaxDynamicSharedMemorySize,
                         ATT_SMEM);

    // 1) qn = LN(tgt)
    ln_kernel<<<MQ, 256>>>(tgt, ln_g, ln_b, qn);

    // 2-4) projections
    tf32_gemm<<<dim3(DIM / 128, MQ / 128), 256, GEMM_SMEM>>>(MQ, DIM, DIM, qn, wq, bq, nullptr, q, 0);
    tf32_gemm<<<dim3(DIM / 128, MK / 128), 256, GEMM_SMEM>>>(MK, DIM, DIM, emb, wk, bk, nullptr, k, 0);
    tf32_gemm<<<dim3(DIM / 128, MK / 128), 256, GEMM_SMEM>>>(MK, DIM, DIM, emb, wv, bv, nullptr, v, 0);

    // 5) ctx = softmax(Q K^T / sqrt(d)) V
    attn_mma<<<dim3(NQ / BQ_T, HEADS, BSZ), 256, ATT_SMEM>>>(q, k, v, ctx);

    // 6) tgt1 = tgt + ctx @ wo + bo -> d_out
    tf32_gemm<<<dim3(DIM / 128, MQ / 128), 256, GEMM_SMEM>>>(MQ, DIM, DIM, ctx, wo, bo, tgt, out, 2);

    // 7) h_in = LN(tgt1)
    ln_kernel<<<MQ, 256>>>(out, ln_g, ln_b, qn);

    // 8) h1 = gelu(h_in @ w1 + b1)
    tf32_gemm<<<dim3(HIDDEN / 128, MQ / 128), 256, GEMM_SMEM>>>(MQ, HIDDEN, DIM, qn, w1, b1, nullptr, h1, 1);

    // 9) out = tgt1 + h1 @ w2 + b2
    tf32_gemm<<<dim3(DIM / 128, MQ / 128), 256, GEMM_SMEM>>>(MQ, DIM, HIDDEN, h1, w2, b2, out, out, 2);
}

// round 5
// speedup vs baseline: 3.5858x; 1.0001x over previous
#include <cuda_runtime.h>
#include <math.h>
#include <stdint.h>

// ---------------- problem constants ----------------
#define BSZ     4
#define NQ      1024
#define NK      2048
#define DIM     1024
#define HEADS   16
#define HD      64
#define HIDDEN  4096
#define MQ      (BSZ*NQ)   // 4096
#define MK      (BSZ*NK)   // 8192

// ---------------- scratch ----------
__device__ float g_qn  [(size_t)MQ * DIM];
__device__ float g_q   [(size_t)MQ * DIM];
__device__ float g_k   [(size_t)MK * DIM];
__device__ float g_v   [(size_t)MK * DIM];
__device__ float g_ctx [(size_t)MQ * DIM];
__device__ float g_h1  [(size_t)MQ * HIDDEN];
__device__ float g_embr[(size_t)MK * DIM];
__device__ float g_wqr [(size_t)DIM * DIM];
__device__ float g_wkr [(size_t)DIM * DIM];
__device__ float g_wvr [(size_t)DIM * DIM];
__device__ float g_wor [(size_t)DIM * DIM];
__device__ float g_w1r [(size_t)DIM * HIDDEN];
__device__ float g_w2r [(size_t)HIDDEN * DIM];

// ==================== helpers ====================
__device__ __forceinline__ uint32_t f2tf32(float x) {
    uint32_t r;
    asm("cvt.rna.tf32.f32 %0, %1;" : "=r"(r) : "f"(x));
    return r;
}
__device__ __forceinline__ float rnd(float x) { return __uint_as_float(f2tf32(x)); }
__device__ __forceinline__ float gelu_exact(float x) {
    return 0.5f * x * (1.0f + erff(x * 0.70710678118654752f));
}
__device__ __forceinline__ void mma_tf32(float d[4], const uint32_t a[4], const uint32_t b[2]) {
    asm volatile(
        "mma.sync.aligned.m16n8k8.row.col.f32.tf32.tf32.f32 "
        "{%0,%1,%2,%3}, {%4,%5,%6,%7}, {%8,%9}, {%0,%1,%2,%3};"
        : "+f"(d[0]), "+f"(d[1]), "+f"(d[2]), "+f"(d[3])
        : "r"(a[0]), "r"(a[1]), "r"(a[2]), "r"(a[3]), "r"(b[0]), "r"(b[1]));
}
__device__ __forceinline__ void cp16(void* s, const void* g) {
    uint32_t sa = (uint32_t)__cvta_generic_to_shared(s);
    asm volatile("cp.async.ca.shared.global [%0], [%1], 16;" :: "r"(sa), "l"(g));
}

// ==================== tf32 pre-rounding pass ====================
__global__ __launch_bounds__(256)
void round_tf32_kernel(const float4* __restrict__ in, float4* __restrict__ out, int n4)
{
    int i = blockIdx.x * blockDim.x + threadIdx.x;
    int stride = gridDim.x * blockDim.x;
    for (; i < n4; i += stride) {
        float4 v = in[i];
        v.x = rnd(v.x); v.y = rnd(v.y); v.z = rnd(v.z); v.w = rnd(v.w);
        out[i] = v;
    }
}

// ==================== LayerNorm (tf32-rounded output) ====================
__global__ __launch_bounds__(256)
void ln_kernel(const float* __restrict__ x, const float* __restrict__ g,
               const float* __restrict__ bt, float* __restrict__ out)
{
    int row = blockIdx.x;
    int t = threadIdx.x;
    const float4* xr = (const float4*)(x + (size_t)row * DIM);
    float4 v = xr[t];
    float s  = v.x + v.y + v.z + v.w;
    float sq = v.x*v.x + v.y*v.y + v.z*v.z + v.w*v.w;

    #pragma unroll
    for (int off = 16; off; off >>= 1) {
        s  += __shfl_xor_sync(0xffffffffu, s,  off);
        sq += __shfl_xor_sync(0xffffffffu, sq, off);
    }
    __shared__ float ss[8], sqs[8];
    int warp = t >> 5, lane = t & 31;
    if (lane == 0) { ss[warp] = s; sqs[warp] = sq; }
    __syncthreads();
    if (t < 32) {
        float a = (t < 8) ? ss[t]  : 0.f;
        float b = (t < 8) ? sqs[t] : 0.f;
        #pragma unroll
        for (int off = 4; off; off >>= 1) {
            a += __shfl_xor_sync(0xffffffffu, a, off);
            b += __shfl_xor_sync(0xffffffffu, b, off);
        }
        if (t == 0) { ss[0] = a; sqs[0] = b; }
    }
    __syncthreads();
    float mu  = ss[0]  * (1.0f / DIM);
    float var = sqs[0] * (1.0f / DIM) - mu * mu;
    float inv = rsqrtf(var + 1e-5f);

    float4 gv = ((const float4*)g)[t];
    float4 bv = ((const float4*)bt)[t];
    float4 o;
    o.x = rnd((v.x - mu) * inv * gv.x + bv.x);
    o.y = rnd((v.y - mu) * inv * gv.y + bv.y);
    o.z = rnd((v.z - mu) * inv * gv.z + bv.z);
    o.w = rnd((v.w - mu) * inv * gv.w + bv.w);
    ((float4*)(out + (size_t)row * DIM))[t] = o;
}

// ==================== tf32 GEMM v4: cp.async 3-stage + reg-buffered frags ===
// C[M,N] = A[M,K] @ B[K,N] + bias (+gelu | +residual). Inputs pre-rounded tf32.
// CTA 128x128, KC=32, 8 warps x (32m x 64n). gridDim.z==2 selects (B2,bias2,C2).
#define KC   32
#define SKA  36
#define SKB  136
#define A_ST (128*SKA)
#define B_ST (KC*SKB)
#define ST_W (A_ST + B_ST)
#define GEMM_SMEM (3*ST_W*4)    // 107520 bytes

__global__ __launch_bounds__(256, 2)
void tf32_gemm(int M, int N, int K,
               const float* __restrict__ A,
               const float* __restrict__ B,
               const float* __restrict__ bias,
               const float* __restrict__ res,
               float* __restrict__ C, int mode,
               const float* __restrict__ B2,
               const float* __restrict__ bias2,
               float* __restrict__ C2)
{
    extern __shared__ uint32_t sm[];

    if (blockIdx.z == 1) { B = B2; bias = bias2; C = C2; }

    int tid = threadIdx.x;
    int lane = tid & 31;
    int warp = tid >> 5;
    int warp_m = (warp >> 1) * 32;
    int warp_n = (warp & 1) * 64;
    int r = lane >> 2;
    int c = lane & 3;

    int ctaM = blockIdx.y * 128;
    int ctaN = blockIdx.x * 128;

    const float* Ab = A + (size_t)ctaM * K;
    const float* Bb = B + ctaN;

    int aRow = tid >> 3;
    int aK4  = (tid & 7) * 4;
    int bK   = tid >> 5;
    int bN4  = (tid & 31) * 4;

    const int nk = K / KC;

    #define ISSUE_STAGE(s, k0)                                                   \
    do {                                                                         \
        uint32_t* As_ = sm + (s) * ST_W;                                         \
        uint32_t* Bs_ = As_ + A_ST;                                              \
        const float* An_ = Ab + (k0);                                            \
        const float* Bn_ = Bb + (size_t)(k0) * N;                                \
        _Pragma("unroll")                                                        \
        for (int i = 0; i < 4; i++) {                                            \
            int row = aRow + i * 32;                                             \
            cp16(As_ + (size_t)row * SKA + aK4, An_ + (size_t)row * K + aK4);    \
        }                                                                        \
        _Pragma("unroll")                                                        \
        for (int i = 0; i < 4; i++) {                                            \
            int kk = bK + i * 8;                                                 \
            cp16(Bs_ + (size_t)kk * SKB + bN4, Bn_ + (size_t)kk * N + bN4);      \
        }                                                                        \
        asm volatile("cp.async.commit_group;");                                  \
    } while (0)

    ISSUE_STAGE(0, 0);
    if (nk > 1) ISSUE_STAGE(1, KC);
    else        asm volatile("cp.async.commit_group;");

    float acc[2][8][4] = {};
    uint32_t bfb[2][8][2];   // double-buffered B fragments

    #define LOAD_BF(bsel, ksv)                                                   \
    do {                                                                         \
        const uint32_t* pb_ = Bsb + (size_t)((ksv) * 8 + c) * SKB + warp_n + r;  \
        _Pragma("unroll")                                                        \
        for (int nt = 0; nt < 8; nt++) {                                         \
            bfb[bsel][nt][0] = pb_[nt * 8];                                      \
            bfb[bsel][nt][1] = pb_[nt * 8 + 4 * SKB];                            \
        }                                                                        \
    } while (0)

    int buf = 0;
    for (int kt = 0; kt < nk; kt++) {
        if (kt + 2 < nk) asm volatile("cp.async.wait_group 1;");
        else             asm volatile("cp.async.wait_group 0;");
        __syncthreads();

        const uint32_t* Asb = sm + buf * ST_W;
        const uint32_t* Bsb = Asb + A_ST;

        LOAD_BF(0, 0);
        #pragma unroll
        for (int ks = 0; ks < 4; ks++) {
            uint32_t af[2][4];
            #pragma unroll
            for (int mt = 0; mt < 2; mt++) {
                const uint32_t* pa = Asb + (size_t)(warp_m + mt * 16 + r) * SKA + ks * 8 + c;
                af[mt][0] = pa[0];
                af[mt][2] = pa[4];
                af[mt][1] = pa[8 * SKA];
                af[mt][3] = pa[8 * SKA + 4];
            }
            if (ks < 3) LOAD_BF((ks + 1) & 1, ks + 1);
            #pragma unroll
            for (int mt = 0; mt < 2; mt++)
                #pragma unroll
                for (int nt = 0; nt < 8; nt++)
                    mma_tf32(acc[mt][nt], af[mt], bfb[ks & 1][nt]);
        }

        if (kt + 2 < nk) {
            int s = (kt + 2) % 3;
            ISSUE_STAGE(s, (kt + 2) * KC);
        }
        buf = (buf + 1) % 3;
    }
    #undef ISSUE_STAGE
    #undef LOAD_BF

    // ---- epilogue ----
    #pragma unroll
    for (int mt = 0; mt < 2; mt++) {
        #pragma unroll
        for (int nt = 0; nt < 8; nt++) {
            int row = ctaM + warp_m + mt * 16 + r;
            int col = ctaN + warp_n + nt * 8 + 2 * c;
            float b0 = bias[col], b1 = bias[col + 1];
            float v0 = acc[mt][nt][0] + b0;
            float v1 = acc[mt][nt][1] + b1;
            float v2 = acc[mt][nt][2] + b0;
            float v3 = acc[mt][nt][3] + b1;
            if (mode == 1) {
                v0 = rnd(gelu_exact(v0)); v1 = rnd(gelu_exact(v1));
                v2 = rnd(gelu_exact(v2)); v3 = rnd(gelu_exact(v3));
            } else if (mode == 2) {
                const float* r0 = res + (size_t)row * N + col;
                const float* r1 = res + (size_t)(row + 8) * N + col;
                v0 += r0[0]; v1 += r0[1];
                v2 += r1[0]; v3 += r1[1];
            }
            *(float2*)(C + (size_t)row * N + col)       = make_float2(v0, v1);
            *(float2*)(C + (size_t)(row + 8) * N + col) = make_float2(v2, v3);
        }
    }
}

// ==================== tensor-core flash attention ====================
#define BQ_T   128
#define TILE_K 64
#define SKK 68
#define SKV 72
#define SKP 72
#define NT_KV (NK / TILE_K)
#define ATT_SMEM ((2*TILE_K*SKK + 2*TILE_K*SKV + BQ_T*SKP) * 4)

__global__ __launch_bounds__(256, 1)
void attn_mma(const float* __restrict__ Q, const float* __restrict__ Kg,
              const float* __restrict__ Vg, float* __restrict__ ctx)
{
    extern __shared__ float smf[];
    float* KsB = smf;
    float* VsB = smf + 2 * TILE_K * SKK;
    float* Ps  = smf + 2 * TILE_K * (SKK + SKV);

    int b = blockIdx.z, h = blockIdx.y, qt = blockIdx.x;
    int tid = threadIdx.x, lane = tid & 31, w = tid >> 5;
    int r = lane >> 2, c = lane & 3;

    const float* Qb = Q  + ((size_t)(b * NQ + qt * BQ_T)) * DIM + h * HD;
    const float* Kb = Kg + ((size_t)b * NK) * DIM + h * HD;
    const float* Vb = Vg + ((size_t)b * NK) * DIM + h * HD;

    #pragma unroll
    for (int i = 0; i < 4; i++) {
        int idx = tid + i * 256, row = idx >> 4, c4 = (idx & 15) * 4;
        cp16(&KsB[row * SKK + c4], Kb + (size_t)row * DIM + c4);
        cp16(&VsB[row * SKV + c4], Vb + (size_t)row * DIM + c4);
    }
    asm volatile("cp.async.commit_group;");

    uint32_t qf[8][4];
    {
        const float* q0 = Qb + (size_t)(w * 16 + r) * DIM;
        const float* q1 = Qb + (size_t)(w * 16 + r + 8) * DIM;
        #pragma unroll
        for (int kg = 0; kg < 8; kg++) {
            qf[kg][0] = __float_as_uint(q0[kg * 8 + c]     * 0.125f);
            qf[kg][1] = __float_as_uint(q1[kg * 8 + c]     * 0.125f);
            qf[kg][2] = __float_as_uint(q0[kg * 8 + c + 4] * 0.125f);
            qf[kg][3] = __float_as_uint(q1[kg * 8 + c + 4] * 0.125f);
        }
    }

    float m0 = -1e30f, m1 = -1e30f, l0 = 0.f, l1 = 0.f;
    float accO[8][4] = {};
    float* Pw = Ps + (w * 16) * SKP;

    for (int kt = 0; kt < NT_KV; kt++) {
        int buf = kt & 1;
        asm volatile("cp.async.wait_group 0;");
        __syncthreads();

        if (kt + 1 < NT_KV) {
            const float* kp = Kb + (size_t)(kt + 1) * TILE_K * DIM;
            const float* vp = Vb + (size_t)(kt + 1) * TILE_K * DIM;
            float* Kd = KsB + (buf ^ 1) * TILE_K * SKK;
            float* Vd = VsB + (buf ^ 1) * TILE_K * SKV;
            #pragma unroll
            for (int i = 0; i < 4; i++) {
                int idx = tid + i * 256, row = idx >> 4, c4 = (idx & 15) * 4;
                cp16(&Kd[row * SKK + c4], kp + (size_t)row * DIM + c4);
                cp16(&Vd[row * SKV + c4], vp + (size_t)row * DIM + c4);
            }
            asm volatile("cp.async.commit_group;");
        }

        const float* Kt = KsB + buf * TILE_K * SKK;
        const float* Vt = VsB + buf * TILE_K * SKV;

        float accS[8][4] = {};
        #pragma unroll
        for (int kg = 0; kg < 8; kg++) {
            uint32_t bf[8][2];
            #pragma unroll
            for (int nt = 0; nt < 8; nt++) {
                bf[nt][0] = __float_as_uint(Kt[(nt * 8 + r) * SKK + kg * 8 + c]);
                bf[nt][1] = __float_as_uint(Kt[(nt * 8 + r) * SKK + kg * 8 + c + 4]);
            }
            #pragma unroll
            for (int nt = 0; nt < 8; nt++)
                mma_tf32(accS[nt], qf[kg], bf[nt]);
        }

        float mx0 = -1e30f, mx1 = -1e30f;
        #pragma unroll
        for (int nt = 0; nt < 8; nt++) {
            mx0 = fmaxf(mx0, fmaxf(accS[nt][0], accS[nt][1]));
            mx1 = fmaxf(mx1, fmaxf(accS[nt][2], accS[nt][3]));
        }
        mx0 = fmaxf(mx0, __shfl_xor_sync(0xffffffffu, mx0, 1));
        mx0 = fmaxf(mx0, __shfl_xor_sync(0xffffffffu, mx0, 2));
        mx1 = fmaxf(mx1, __shfl_xor_sync(0xffffffffu, mx1, 1));
        mx1 = fmaxf(mx1, __shfl_xor_sync(0xffffffffu, mx1, 2));
        float mn0 = fmaxf(m0, mx0), mn1 = fmaxf(m1, mx1);
        float f0 = __expf(m0 - mn0), f1 = __expf(m1 - mn1);
        float s0 = 0.f, s1 = 0.f;
        #pragma unroll
        for (int nt = 0; nt < 8; nt++) {
            accS[nt][0] = __expf(accS[nt][0] - mn0);
            accS[nt][1] = __expf(accS[nt][1] - mn0);
            accS[nt][2] = __expf(accS[nt][2] - mn1);
            accS[nt][3] = __expf(accS[nt][3] - mn1);
            s0 += accS[nt][0] + accS[nt][1];
            s1 += accS[nt][2] + accS[nt][3];
        }
        s0 += __shfl_xor_sync(0xffffffffu, s0, 1);
        s0 += __shfl_xor_sync(0xffffffffu, s0, 2);
        s1 += __shfl_xor_sync(0xffffffffu, s1, 1);
        s1 += __shfl_xor_sync(0xffffffffu, s1, 2);
        l0 = l0 * f0 + s0; l1 = l1 * f1 + s1;
        m0 = mn0; m1 = mn1;
        #pragma unroll
        for (int nt = 0; nt < 8; nt++) {
            accO[nt][0] *= f0; accO[nt][1] *= f0;
            accO[nt][2] *= f1; accO[nt][3] *= f1;
        }

        #pragma unroll
        for (int nt = 0; nt < 8; nt++) {
            *(float2*)&Pw[r * SKP + nt * 8 + 2 * c]       = make_float2(accS[nt][0], accS[nt][1]);
            *(float2*)&Pw[(r + 8) * SKP + nt * 8 + 2 * c] = make_float2(accS[nt][2], accS[nt][3]);
        }
        __syncwarp();

        #pragma unroll
        for (int kg = 0; kg < 8; kg++) {
            uint32_t af[4];
            af[0] = __float_as_uint(Pw[r * SKP + kg * 8 + c]);
            af[1] = __float_as_uint(Pw[(r + 8) * SKP + kg * 8 + c]);
            af[2] = __float_as_uint(Pw[r * SKP + kg * 8 + c + 4]);
            af[3] = __float_as_uint(Pw[(r + 8) * SKP + kg * 8 + c + 4]);
            #pragma unroll
            for (int nt = 0; nt < 8; nt++) {
                uint32_t bb[2];
                bb[0] = __float_as_uint(Vt[(kg * 8 + c) * SKV + nt * 8 + r]);
                bb[1] = __float_as_uint(Vt[(kg * 8 + c + 4) * SKV + nt * 8 + r]);
                mma_tf32(accO[nt], af, bb);
            }
        }
        __syncwarp();
    }

    // epilogue: divide by l, round to tf32 (ctx feeds GEMM A), write
    float inv0 = 1.f / l0, inv1 = 1.f / l1;
    float* Cb = ctx + ((size_t)(b * NQ + qt * BQ_T + w * 16)) * DIM + h * HD;
    #pragma unroll
    for (int nt = 0; nt < 8; nt++) {
        *(float2*)&Cb[(size_t)r * DIM + nt * 8 + 2 * c] =
            make_float2(rnd(accO[nt][0] * inv0), rnd(accO[nt][1] * inv0));
        *(float2*)&Cb[(size_t)(r + 8) * DIM + nt * 8 + 2 * c] =
            make_float2(rnd(accO[nt][2] * inv1), rnd(accO[nt][3] * inv1));
    }
}

// ==================== launch =================================================
extern "C" void kernel_launch(void* const* d_in, const int* in_sizes, int n_in,
                              void* d_out, int out_size)
{
    const float* tgt  = (const float*)d_in[0];
    const float* emb  = (const float*)d_in[1];
    const float* ln_g = (const float*)d_in[2];
    const float* ln_b = (const float*)d_in[3];
    const float* wq = (const float*)d_in[4];  const float* bq = (const float*)d_in[5];
    const float* wk = (const float*)d_in[6];  const float* bk = (const float*)d_in[7];
    const float* wv = (const float*)d_in[8];  const float* bv = (const float*)d_in[9];
    const float* wo = (const float*)d_in[10]; const float* bo = (const float*)d_in[11];
    const float* w1 = (const float*)d_in[12]; const float* b1 = (const float*)d_in[13];
    const float* w2 = (const float*)d_in[14]; const float* b2 = (const float*)d_in[15];
    float* out = (float*)d_out;

    float *qn, *q, *k, *v, *ctx, *h1;
    float *embr, *wqr, *wkr, *wvr, *wor, *w1r, *w2r;
    cudaGetSymbolAddress((void**)&qn,   g_qn);
    cudaGetSymbolAddress((void**)&q,    g_q);
    cudaGetSymbolAddress((void**)&k,    g_k);
    cudaGetSymbolAddress((void**)&v,    g_v);
    cudaGetSymbolAddress((void**)&ctx,  g_ctx);
    cudaGetSymbolAddress((void**)&h1,   g_h1);
    cudaGetSymbolAddress((void**)&embr, g_embr);
    cudaGetSymbolAddress((void**)&wqr,  g_wqr);
    cudaGetSymbolAddress((void**)&wkr,  g_wkr);
    cudaGetSymbolAddress((void**)&wvr,  g_wvr);
    cudaGetSymbolAddress((void**)&wor,  g_wor);
    cudaGetSymbolAddress((void**)&w1r,  g_w1r);
    cudaGetSymbolAddress((void**)&w2r,  g_w2r);

    cudaFuncSetAttribute(tf32_gemm, cudaFuncAttributeMaxDynamicSharedMemorySize,
                         GEMM_SMEM);
    cudaFuncSetAttribute(attn_mma, cudaFuncAttributeMaxDynamicSharedMemorySize,
                         ATT_SMEM);

    // 0) pre-round GEMM operands to tf32 grid (rna)
    #define ROUND(src, dst, n) \
        round_tf32_kernel<<<((n)/4 + 255)/256, 256>>>((const float4*)(src), (float4*)(dst), (n)/4)
    ROUND(emb, embr, MK * DIM);
    ROUND(wq, wqr, DIM * DIM);
    ROUND(wk, wkr, DIM * DIM);
    ROUND(wv, wvr, DIM * DIM);
    ROUND(wo, wor, DIM * DIM);
    ROUND(w1, w1r, DIM * HIDDEN);
    ROUND(w2, w2r, HIDDEN * DIM);
    #undef ROUND

    // 1) qn = LN(tgt)  (rounded)
    ln_kernel<<<MQ, 256>>>(tgt, ln_g, ln_b, qn);

    // 2) Q = qn @ wq + bq
    tf32_gemm<<<dim3(DIM / 128, MQ / 128, 1), 256, GEMM_SMEM>>>(
        MQ, DIM, DIM, qn, wqr, bq, nullptr, q, 0, wqr, bq, q);
    // 3+4) K,V = emb @ {wk,wv} + {bk,bv}   (fused, z=2)
    tf32_gemm<<<dim3(DIM / 128, MK / 128, 2), 256, GEMM_SMEM>>>(
        MK, DIM, DIM, embr, wkr, bk, nullptr, k, 0, wvr, bv, v);

    // 5) ctx = softmax(Q K^T / sqrt(d)) V
    attn_mma<<<dim3(NQ / BQ_T, HEADS, BSZ), 256, ATT_SMEM>>>(q, k, v, ctx);

    // 6) tgt1 = tgt + ctx @ wo + bo -> d_out
    tf32_gemm<<<dim3(DIM / 128, MQ / 128, 1), 256, GEMM_SMEM>>>(
        MQ, DIM, DIM, ctx, wor, bo, tgt, out, 2, wor, bo, out);

    // 7) h_in = LN(tgt1)  (rounded)
    ln_kernel<<<MQ, 256>>>(out, ln_g, ln_b, qn);

    // 8) h1 = gelu(h_in @ w1 + b1)  (rounded in epilogue)
    tf32_gemm<<<dim3(HIDDEN / 128, MQ / 128, 1), 256, GEMM_SMEM>>>(
        MQ, HIDDEN, DIM, qn, w1r, b1, nullptr, h1, 1, w1r, b1, h1);

    // 9) out = tgt1 + h1 @ w2 + b2
    tf32_gemm<<<dim3(DIM / 128, MQ / 128, 1), 256, GEMM_SMEM>>>(
        MQ, DIM, HIDDEN, h1, w2r, b2, out, out, 2, w2r, b2, out);
}

// round 7
// speedup vs baseline: 5.4660x; 1.5243x over previous
#include <cuda_runtime.h>
#include <cuda_fp16.h>
#include <math.h>
#include <stdint.h>

// ---------------- problem constants ----------------
#define BSZ     4
#define NQ      1024
#define NK      2048
#define DIM     1024
#define HEADS   16
#define HD      64
#define HIDDEN  4096
#define MQ      (BSZ*NQ)   // 4096
#define MK      (BSZ*NK)   // 8192

// ---------------- scratch ----------
__device__ __align__(128) __half g_qn  [(size_t)MQ * DIM];
__device__ __align__(128) float  g_q   [(size_t)MQ * DIM];
__device__ __align__(128) float  g_k   [(size_t)MK * DIM];
__device__ __align__(128) float  g_v   [(size_t)MK * DIM];
__device__ __align__(128) __half g_ctx [(size_t)MQ * DIM];
__device__ __align__(128) __half g_h1  [(size_t)MQ * HIDDEN];
__device__ __align__(128) __half g_embh[(size_t)MK * DIM];
__device__ __align__(128) __half g_wqt [(size_t)DIM * DIM];
__device__ __align__(128) __half g_wkt [(size_t)DIM * DIM];
__device__ __align__(128) __half g_wvt [(size_t)DIM * DIM];
__device__ __align__(128) __half g_wot [(size_t)DIM * DIM];
__device__ __align__(128) __half g_w1t [(size_t)DIM * HIDDEN];
__device__ __align__(128) __half g_w2t [(size_t)HIDDEN * DIM];

// ==================== helpers ====================
__device__ __forceinline__ float gelu_exact(float x) {
    return 0.5f * x * (1.0f + erff(x * 0.70710678118654752f));
}
__device__ __forceinline__ void cp16(void* s, const void* g) {
    uint32_t sa = (uint32_t)__cvta_generic_to_shared(s);
    asm volatile("cp.async.ca.shared.global [%0], [%1], 16;" :: "r"(sa), "l"(g));
}
// fp16 mma m16n8k16, fp32 accumulate
__device__ __forceinline__ void mma_f16(float d[4], const uint32_t a[4], const uint32_t b[2]) {
    asm volatile(
        "mma.sync.aligned.m16n8k16.row.col.f32.f16.f16.f32 "
        "{%0,%1,%2,%3}, {%4,%5,%6,%7}, {%8,%9}, {%0,%1,%2,%3};"
        : "+f"(d[0]), "+f"(d[1]), "+f"(d[2]), "+f"(d[3])
        : "r"(a[0]), "r"(a[1]), "r"(a[2]), "r"(a[3]), "r"(b[0]), "r"(b[1]));
}
// tf32 mma (attention only)
__device__ __forceinline__ void mma_tf32(float d[4], const uint32_t a[4], const uint32_t b[2]) {
    asm volatile(
        "mma.sync.aligned.m16n8k8.row.col.f32.tf32.tf32.f32 "
        "{%0,%1,%2,%3}, {%4,%5,%6,%7}, {%8,%9}, {%0,%1,%2,%3};"
        : "+f"(d[0]), "+f"(d[1]), "+f"(d[2]), "+f"(d[3])
        : "r"(a[0]), "r"(a[1]), "r"(a[2]), "r"(a[3]), "r"(b[0]), "r"(b[1]));
}

// ==================== emb -> half ====================
__global__ __launch_bounds__(256)
void conv_half_kernel(const float4* __restrict__ in, __half2* __restrict__ out, int n4)
{
    int i = blockIdx.x * blockDim.x + threadIdx.x;
    int stride = gridDim.x * blockDim.x;
    for (; i < n4; i += stride) {
        float4 v = in[i];
        out[2 * i]     = __floats2half2_rn(v.x, v.y);
        out[2 * i + 1] = __floats2half2_rn(v.z, v.w);
    }
}

// ==================== transpose + convert: W[K][N] -> Wt[N][K] half ==========
__global__ __launch_bounds__(256)
void transpose_half_kernel(const float* __restrict__ in, __half* __restrict__ out,
                           int K, int N)
{
    __shared__ float tile[32][33];
    int bx = blockIdx.x * 32;   // N offset
    int by = blockIdx.y * 32;   // K offset
    int tx = threadIdx.x, ty = threadIdx.y;   // (32, 8)
    #pragma unroll
    for (int i = 0; i < 32; i += 8)
        tile[ty + i][tx] = in[(size_t)(by + ty + i) * N + bx + tx];
    __syncthreads();
    #pragma unroll
    for (int i = 0; i < 32; i += 8)
        out[(size_t)(bx + ty + i) * K + by + tx] = __float2half_rn(tile[tx][ty + i]);
}

// ==================== LayerNorm (half output) ====================
__global__ __launch_bounds__(256)
void ln_kernel(const float* __restrict__ x, const float* __restrict__ g,
               const float* __restrict__ bt, __half* __restrict__ out)
{
    int row = blockIdx.x;
    int t = threadIdx.x;
    const float4* xr = (const float4*)(x + (size_t)row * DIM);
    float4 v = xr[t];
    float s  = v.x + v.y + v.z + v.w;
    float sq = v.x*v.x + v.y*v.y + v.z*v.z + v.w*v.w;

    #pragma unroll
    for (int off = 16; off; off >>= 1) {
        s  += __shfl_xor_sync(0xffffffffu, s,  off);
        sq += __shfl_xor_sync(0xffffffffu, sq, off);
    }
    __shared__ float ss[8], sqs[8];
    int warp = t >> 5, lane = t & 31;
    if (lane == 0) { ss[warp] = s; sqs[warp] = sq; }
    __syncthreads();
    if (t < 32) {
        float a = (t < 8) ? ss[t]  : 0.f;
        float b = (t < 8) ? sqs[t] : 0.f;
        #pragma unroll
        for (int off = 4; off; off >>= 1) {
            a += __shfl_xor_sync(0xffffffffu, a, off);
            b += __shfl_xor_sync(0xffffffffu, b, off);
        }
        if (t == 0) { ss[0] = a; sqs[0] = b; }
    }
    __syncthreads();
    float mu  = ss[0]  * (1.0f / DIM);
    float var = sqs[0] * (1.0f / DIM) - mu * mu;
    float inv = rsqrtf(var + 1e-5f);

    float4 gv = ((const float4*)g)[t];
    float4 bv = ((const float4*)bt)[t];
    __half2* o2 = (__half2*)(out + (size_t)row * DIM);
    o2[2 * t]     = __floats2half2_rn((v.x - mu) * inv * gv.x + bv.x,
                                      (v.y - mu) * inv * gv.y + bv.y);
    o2[2 * t + 1] = __floats2half2_rn((v.z - mu) * inv * gv.z + bv.z,
                                      (v.w - mu) * inv * gv.w + bv.w);
}

// ==================== fp16 tensor-core GEMM =================================
// C[M,N] = A[M,K](half) @ Bt[N,K](half)^T + bias (+gelu->half | +residual)
// CTA 128x128, KC=32, 3-stage cp.async, 8 warps x (32m x 64n).
// mode: 0 = bias (fp32 out), 1 = bias+gelu (half out), 2 = bias+residual (fp32 out)
// gridDim.z==2 selects (Bt2, bias2, C2).
#define KCH   32                  // halves of K per stage
#define SKH   40                  // smem row stride in halves (80B; banks 20r+c distinct)
#define TILE_H (128 * SKH)        // halves per tile (A or B)
#define STAGE_H (2 * TILE_H)      // halves per stage
#define GEMM_SMEM (3 * STAGE_H * 2)   // 61440 bytes

__global__ __launch_bounds__(256, 2)
void h16_gemm(int M, int N, int K,
              const __half* __restrict__ A,
              const __half* __restrict__ Bt,
              const float* __restrict__ bias,
              const float* __restrict__ res,
              void* __restrict__ Cv, int mode,
              const __half* __restrict__ Bt2,
              const float* __restrict__ bias2,
              void* __restrict__ Cv2)
{
    extern __shared__ __half smh[];

    if (blockIdx.z == 1) { Bt = Bt2; bias = bias2; Cv = Cv2; }

    int tid = threadIdx.x;
    int lane = tid & 31;
    int warp = tid >> 5;
    int warp_m = (warp >> 1) * 32;
    int warp_n = (warp & 1) * 64;
    int r = lane >> 2;
    int c = lane & 3;

    int ctaM = blockIdx.y * 128;
    int ctaN = blockIdx.x * 128;

    const __half* gA = A  + (size_t)ctaM * K;
    const __half* gB = Bt + (size_t)ctaN * K;

    int ldRow = tid >> 2;        // 0..63 (+64 via j)
    int ldCh  = (tid & 3) * 8;   // half offset within 32

    const int nk = K / KCH;

    #define ISSUE_STAGE(s, k0)                                                     \
    do {                                                                           \
        __half* sA_ = smh + (s) * STAGE_H;                                         \
        __half* sB_ = sA_ + TILE_H;                                                \
        const __half* a_ = gA + (k0);                                              \
        const __half* b_ = gB + (k0);                                              \
        _Pragma("unroll")                                                          \
        for (int j = 0; j < 2; j++) {                                              \
            int row = ldRow + j * 64;                                              \
            cp16(sA_ + (size_t)row * SKH + ldCh, a_ + (size_t)row * K + ldCh);     \
            cp16(sB_ + (size_t)row * SKH + ldCh, b_ + (size_t)row * K + ldCh);     \
        }                                                                          \
        asm volatile("cp.async.commit_group;");                                    \
    } while (0)

    ISSUE_STAGE(0, 0);
    if (nk > 1) ISSUE_STAGE(1, KCH);
    else        asm volatile("cp.async.commit_group;");

    float acc[2][8][4] = {};

    int buf = 0;
    for (int kt = 0; kt < nk; kt++) {
        if (kt + 2 < nk) asm volatile("cp.async.wait_group 1;");
        else             asm volatile("cp.async.wait_group 0;");
        __syncthreads();

        const __half* Asb = smh + buf * STAGE_H;
        const __half* Bsb = Asb + TILE_H;

        #pragma unroll
        for (int ks = 0; ks < 2; ks++) {   // two k16 steps per KC=32
            uint32_t af[2][4], bf[8][2];
            #pragma unroll
            for (int mt = 0; mt < 2; mt++) {
                const __half* pa = Asb + (size_t)(warp_m + mt * 16 + r) * SKH + ks * 16 + 2 * c;
                af[mt][0] = *(const uint32_t*)(pa);
                af[mt][1] = *(const uint32_t*)(pa + 8 * SKH);
                af[mt][2] = *(const uint32_t*)(pa + 8);
                af[mt][3] = *(const uint32_t*)(pa + 8 * SKH + 8);
            }
            #pragma unroll
            for (int nt = 0; nt < 8; nt++) {
                const __half* pb = Bsb + (size_t)(warp_n + nt * 8 + r) * SKH + ks * 16 + 2 * c;
                bf[nt][0] = *(const uint32_t*)(pb);
                bf[nt][1] = *(const uint32_t*)(pb + 8);
            }
            #pragma unroll
            for (int mt = 0; mt < 2; mt++)
                #pragma unroll
                for (int nt = 0; nt < 8; nt++)
                    mma_f16(acc[mt][nt], af[mt], bf[nt]);
        }

        if (kt + 2 < nk) {
            int s = (kt + 2) % 3;
            ISSUE_STAGE(s, (kt + 2) * KCH);
        }
        buf = (buf + 1) % 3;
    }
    #undef ISSUE_STAGE

    // ---- epilogue ----
    float*  Cf = (float*)Cv;
    __half* Ch = (__half*)Cv;
    #pragma unroll
    for (int mt = 0; mt < 2; mt++) {
        #pragma unroll
        for (int nt = 0; nt < 8; nt++) {
            int row = ctaM + warp_m + mt * 16 + r;
            int col = ctaN + warp_n + nt * 8 + 2 * c;
            float b0 = bias[col], b1 = bias[col + 1];
            float v0 = acc[mt][nt][0] + b0;
            float v1 = acc[mt][nt][1] + b1;
            float v2 = acc[mt][nt][2] + b0;
            float v3 = acc[mt][nt][3] + b1;
            if (mode == 1) {
                __half2 h0 = __floats2half2_rn(gelu_exact(v0), gelu_exact(v1));
                __half2 h1 = __floats2half2_rn(gelu_exact(v2), gelu_exact(v3));
                *(__half2*)(Ch + (size_t)row * N + col)       = h0;
                *(__half2*)(Ch + (size_t)(row + 8) * N + col) = h1;
            } else {
                if (mode == 2) {
                    const float* r0 = res + (size_t)row * N + col;
                    const float* r1 = res + (size_t)(row + 8) * N + col;
                    v0 += r0[0]; v1 += r0[1];
                    v2 += r1[0]; v3 += r1[1];
                }
                *(float2*)(Cf + (size_t)row * N + col)       = make_float2(v0, v1);
                *(float2*)(Cf + (size_t)(row + 8) * N + col) = make_float2(v2, v3);
            }
        }
    }
}

// ==================== tensor-core flash attention (tf32, ctx -> half) ========
#define BQ_T   128
#define TILE_K 64
#define SKK 68
#define SKV 72
#define SKP 72
#define NT_KV (NK / TILE_K)
#define ATT_SMEM ((2*TILE_K*SKK + 2*TILE_K*SKV + BQ_T*SKP) * 4)

__global__ __launch_bounds__(256, 1)
void attn_mma(const float* __restrict__ Q, const float* __restrict__ Kg,
              const float* __restrict__ Vg, __half* __restrict__ ctx)
{
    extern __shared__ float smf[];
    float* KsB = smf;
    float* VsB = smf + 2 * TILE_K * SKK;
    float* Ps  = smf + 2 * TILE_K * (SKK + SKV);

    int b = blockIdx.z, h = blockIdx.y, qt = blockIdx.x;
    int tid = threadIdx.x, lane = tid & 31, w = tid >> 5;
    int r = lane >> 2, c = lane & 3;

    const float* Qb = Q  + ((size_t)(b * NQ + qt * BQ_T)) * DIM + h * HD;
    const float* Kb = Kg + ((size_t)b * NK) * DIM + h * HD;
    const float* Vb = Vg + ((size_t)b * NK) * DIM + h * HD;

    #pragma unroll
    for (int i = 0; i < 4; i++) {
        int idx = tid + i * 256, row = idx >> 4, c4 = (idx & 15) * 4;
        cp16(&KsB[row * SKK + c4], Kb + (size_t)row * DIM + c4);
        cp16(&VsB[row * SKV + c4], Vb + (size_t)row * DIM + c4);
    }
    asm volatile("cp.async.commit_group;");

    uint32_t qf[8][4];
    {
        const float* q0 = Qb + (size_t)(w * 16 + r) * DIM;
        const float* q1 = Qb + (size_t)(w * 16 + r + 8) * DIM;
        #pragma unroll
        for (int kg = 0; kg < 8; kg++) {
            qf[kg][0] = __float_as_uint(q0[kg * 8 + c]     * 0.125f);
            qf[kg][1] = __float_as_uint(q1[kg * 8 + c]     * 0.125f);
            qf[kg][2] = __float_as_uint(q0[kg * 8 + c + 4] * 0.125f);
            qf[kg][3] = __float_as_uint(q1[kg * 8 + c + 4] * 0.125f);
        }
    }

    float m0 = -1e30f, m1 = -1e30f, l0 = 0.f, l1 = 0.f;
    float accO[8][4] = {};
    float* Pw = Ps + (w * 16) * SKP;

    for (int kt = 0; kt < NT_KV; kt++) {
        int buf = kt & 1;
        asm volatile("cp.async.wait_group 0;");
        __syncthreads();

        if (kt + 1 < NT_KV) {
            const float* kp = Kb + (size_t)(kt + 1) * TILE_K * DIM;
            const float* vp = Vb + (size_t)(kt + 1) * TILE_K * DIM;
            float* Kd = KsB + (buf ^ 1) * TILE_K * SKK;
            float* Vd = VsB + (buf ^ 1) * TILE_K * SKV;
            #pragma unroll
            for (int i = 0; i < 4; i++) {
                int idx = tid + i * 256, row = idx >> 4, c4 = (idx & 15) * 4;
                cp16(&Kd[row * SKK + c4], kp + (size_t)row * DIM + c4);
                cp16(&Vd[row * SKV + c4], vp + (size_t)row * DIM + c4);
            }
            asm volatile("cp.async.commit_group;");
        }

        const float* Kt = KsB + buf * TILE_K * SKK;
        const float* Vt = VsB + buf * TILE_K * SKV;

        float accS[8][4] = {};
        #pragma unroll
        for (int kg = 0; kg < 8; kg++) {
            uint32_t bf[8][2];
            #pragma unroll
            for (int nt = 0; nt < 8; nt++) {
                bf[nt][0] = __float_as_uint(Kt[(nt * 8 + r) * SKK + kg * 8 + c]);
                bf[nt][1] = __float_as_uint(Kt[(nt * 8 + r) * SKK + kg * 8 + c + 4]);
            }
            #pragma unroll
            for (int nt = 0; nt < 8; nt++)
                mma_tf32(accS[nt], qf[kg], bf[nt]);
        }

        float mx0 = -1e30f, mx1 = -1e30f;
        #pragma unroll
        for (int nt = 0; nt < 8; nt++) {
            mx0 = fmaxf(mx0, fmaxf(accS[nt][0], accS[nt][1]));
            mx1 = fmaxf(mx1, fmaxf(accS[nt][2], accS[nt][3]));
        }
        mx0 = fmaxf(mx0, __shfl_xor_sync(0xffffffffu, mx0, 1));
        mx0 = fmaxf(mx0, __shfl_xor_sync(0xffffffffu, mx0, 2));
        mx1 = fmaxf(mx1, __shfl_xor_sync(0xffffffffu, mx1, 1));
        mx1 = fmaxf(mx1, __shfl_xor_sync(0xffffffffu, mx1, 2));
        float mn0 = fmaxf(m0, mx0), mn1 = fmaxf(m1, mx1);
        float f0 = __expf(m0 - mn0), f1 = __expf(m1 - mn1);
        float s0 = 0.f, s1 = 0.f;
        #pragma unroll
        for (int nt = 0; nt < 8; nt++) {
            accS[nt][0] = __expf(accS[nt][0] - mn0);
            accS[nt][1] = __expf(accS[nt][1] - mn0);
            accS[nt][2] = __expf(accS[nt][2] - mn1);
            accS[nt][3] = __expf(accS[nt][3] - mn1);
            s0 += accS[nt][0] + accS[nt][1];
            s1 += accS[nt][2] + accS[nt][3];
        }
        s0 += __shfl_xor_sync(0xffffffffu, s0, 1);
        s0 += __shfl_xor_sync(0xffffffffu, s0, 2);
        s1 += __shfl_xor_sync(0xffffffffu, s1, 1);
        s1 += __shfl_xor_sync(0xffffffffu, s1, 2);
        l0 = l0 * f0 + s0; l1 = l1 * f1 + s1;
        m0 = mn0; m1 = mn1;
        #pragma unroll
        for (int nt = 0; nt < 8; nt++) {
            accO[nt][0] *= f0; accO[nt][1] *= f0;
            accO[nt][2] *= f1; accO[nt][3] *= f1;
        }

        #pragma unroll
        for (int nt = 0; nt < 8; nt++) {
            *(float2*)&Pw[r * SKP + nt * 8 + 2 * c]       = make_float2(accS[nt][0], accS[nt][1]);
            *(float2*)&Pw[(r + 8) * SKP + nt * 8 + 2 * c] = make_float2(accS[nt][2], accS[nt][3]);
        }
        __syncwarp();

        #pragma unroll
        for (int kg = 0; kg < 8; kg++) {
            uint32_t af[4];
            af[0] = __float_as_uint(Pw[r * SKP + kg * 8 + c]);
            af[1] = __float_as_uint(Pw[(r + 8) * SKP + kg * 8 + c]);
            af[2] = __float_as_uint(Pw[r * SKP + kg * 8 + c + 4]);
            af[3] = __float_as_uint(Pw[(r + 8) * SKP + kg * 8 + c + 4]);
            #pragma unroll
            for (int nt = 0; nt < 8; nt++) {
                uint32_t bb[2];
                bb[0] = __float_as_uint(Vt[(kg * 8 + c) * SKV + nt * 8 + r]);
                bb[1] = __float_as_uint(Vt[(kg * 8 + c + 4) * SKV + nt * 8 + r]);
                mma_tf32(accO[nt], af, bb);
            }
        }
        __syncwarp();
    }

    // epilogue: divide by l, convert to half (ctx feeds fp16 GEMM)
    float inv0 = 1.f / l0, inv1 = 1.f / l1;
    __half* Cb = ctx + ((size_t)(b * NQ + qt * BQ_T + w * 16)) * DIM + h * HD;
    #pragma unroll
    for (int nt = 0; nt < 8; nt++) {
        *(__half2*)(Cb + (size_t)r * DIM + nt * 8 + 2 * c) =
            __floats2half2_rn(accO[nt][0] * inv0, accO[nt][1] * inv0);
        *(__half2*)(Cb + (size_t)(r + 8) * DIM + nt * 8 + 2 * c) =
            __floats2half2_rn(accO[nt][2] * inv1, accO[nt][3] * inv1);
    }
}

// ==================== launch =================================================
extern "C" void kernel_launch(void* const* d_in, const int* in_sizes, int n_in,
                              void* d_out, int out_size)
{
    const float* tgt  = (const float*)d_in[0];
    const float* emb  = (const float*)d_in[1];
    const float* ln_g = (const float*)d_in[2];
    const float* ln_b = (const float*)d_in[3];
    const float* wq = (const float*)d_in[4];  const float* bq = (const float*)d_in[5];
    const float* wk = (const float*)d_in[6];  const float* bk = (const float*)d_in[7];
    const float* wv = (const float*)d_in[8];  const float* bv = (const float*)d_in[9];
    const float* wo = (const float*)d_in[10]; const float* bo = (const float*)d_in[11];
    const float* w1 = (const float*)d_in[12]; const float* b1 = (const float*)d_in[13];
    const float* w2 = (const float*)d_in[14]; const float* b2 = (const float*)d_in[15];
    float* out = (float*)d_out;

    __half *qn, *ctx, *h1, *embh, *wqt, *wkt, *wvt, *wot, *w1t, *w2t;
    float *q, *k, *v;
    cudaGetSymbolAddress((void**)&qn,   g_qn);
    cudaGetSymbolAddress((void**)&q,    g_q);
    cudaGetSymbolAddress((void**)&k,    g_k);
    cudaGetSymbolAddress((void**)&v,    g_v);
    cudaGetSymbolAddress((void**)&ctx,  g_ctx);
    cudaGetSymbolAddress((void**)&h1,   g_h1);
    cudaGetSymbolAddress((void**)&embh, g_embh);
    cudaGetSymbolAddress((void**)&wqt,  g_wqt);
    cudaGetSymbolAddress((void**)&wkt,  g_wkt);
    cudaGetSymbolAddress((void**)&wvt,  g_wvt);
    cudaGetSymbolAddress((void**)&wot,  g_wot);
    cudaGetSymbolAddress((void**)&w1t,  g_w1t);
    cudaGetSymbolAddress((void**)&w2t,  g_w2t);

    cudaFuncSetAttribute(h16_gemm, cudaFuncAttributeMaxDynamicSharedMemorySize, GEMM_SMEM);
    cudaFuncSetAttribute(attn_mma, cudaFuncAttributeMaxDynamicSharedMemorySize, ATT_SMEM);

    // 0) transpose+convert weights into [N][K] half; convert emb to half
    dim3 tb(32, 8);
    transpose_half_kernel<<<dim3(DIM / 32, DIM / 32), tb>>>(wq, wqt, DIM, DIM);
    transpose_half_kernel<<<dim3(DIM / 32, DIM / 32), tb>>>(wk, wkt, DIM, DIM);
    transpose_half_kernel<<<dim3(DIM / 32, DIM / 32), tb>>>(wv, wvt, DIM, DIM);
    transpose_half_kernel<<<dim3(DIM / 32, DIM / 32), tb>>>(wo, wot, DIM, DIM);
    transpose_half_kernel<<<dim3(HIDDEN / 32, DIM / 32), tb>>>(w1, w1t, DIM, HIDDEN);
    transpose_half_kernel<<<dim3(DIM / 32, HIDDEN / 32), tb>>>(w2, w2t, HIDDEN, DIM);
    conv_half_kernel<<<1024, 256>>>((const float4*)emb, (__half2*)embh, MK * DIM / 4);

    // 1) qn = LN(tgt) (half)
    ln_kernel<<<MQ, 256>>>(tgt, ln_g, ln_b, qn);

    // 2) Q = qn @ wq + bq  (fp32 out)
    h16_gemm<<<dim3(DIM / 128, MQ / 128, 1), 256, GEMM_SMEM>>>(
        MQ, DIM, DIM, qn, wqt, bq, nullptr, q, 0, wqt, bq, q);
    // 3+4) K,V = emb @ {wk,wv} (fused z=2, fp32 out)
    h16_gemm<<<dim3(DIM / 128, MK / 128, 2), 256, GEMM_SMEM>>>(
        MK, DIM, DIM, embh, wkt, bk, nullptr, k, 0, wvt, bv, v);

    // 5) ctx = softmax(Q K^T / sqrt(d)) V  (half out)
    attn_mma<<<dim3(NQ / BQ_T, HEADS, BSZ), 256, ATT_SMEM>>>(q, k, v, ctx);

    // 6) tgt1 = tgt + ctx @ wo + bo -> d_out (fp32)
    h16_gemm<<<dim3(DIM / 128, MQ / 128, 1), 256, GEMM_SMEM>>>(
        MQ, DIM, DIM, ctx, wot, bo, tgt, out, 2, wot, bo, out);

    // 7) h_in = LN(tgt1) (half)
    ln_kernel<<<MQ, 256>>>(out, ln_g, ln_b, qn);

    // 8) h1 = gelu(h_in @ w1 + b1) (half out)
    h16_gemm<<<dim3(HIDDEN / 128, MQ / 128, 1), 256, GEMM_SMEM>>>(
        MQ, HIDDEN, DIM, qn, w1t, b1, nullptr, h1, 1, w1t, b1, h1);

    // 9) out = tgt1 + h1 @ w2 + b2 (fp32)
    h16_gemm<<<dim3(DIM / 128, MQ / 128, 1), 256, GEMM_SMEM>>>(
        MQ, DIM, HIDDEN, h1, w2t, b2, out, out, 2, w2t, b2, out);
}

// round 8
// speedup vs baseline: 6.5889x; 1.2054x over previous
#include <cuda_runtime.h>
#include <cuda_fp16.h>
#include <math.h>
#include <stdint.h>

// ---------------- problem constants ----------------
#define BSZ     4
#define NQ      1024
#define NK      2048
#define DIM     1024
#define HEADS   16
#define HD      64
#define HIDDEN  4096
#define MQ      (BSZ*NQ)   // 4096
#define MK      (BSZ*NK)   // 8192

// ---------------- scratch ----------
__device__ __align__(128) __half g_qn  [(size_t)MQ * DIM];
__device__ __align__(128) __half g_q   [(size_t)MQ * DIM];
__device__ __align__(128) __half g_k   [(size_t)MK * DIM];
__device__ __align__(128) __half g_v   [(size_t)MK * DIM];
__device__ __align__(128) __half g_ctx [(size_t)MQ * DIM];
__device__ __align__(128) __half g_h1  [(size_t)MQ * HIDDEN];
__device__ __align__(128) __half g_embh[(size_t)MK * DIM];
__device__ __align__(128) __half g_wqt [(size_t)DIM * DIM];
__device__ __align__(128) __half g_wkt [(size_t)DIM * DIM];
__device__ __align__(128) __half g_wvt [(size_t)DIM * DIM];
__device__ __align__(128) __half g_wot [(size_t)DIM * DIM];
__device__ __align__(128) __half g_w1t [(size_t)DIM * HIDDEN];
__device__ __align__(128) __half g_w2t [(size_t)HIDDEN * DIM];

// ==================== helpers ====================
__device__ __forceinline__ float gelu_exact(float x) {
    return 0.5f * x * (1.0f + erff(x * 0.70710678118654752f));
}
__device__ __forceinline__ void cp16(void* s, const void* g) {
    uint32_t sa = (uint32_t)__cvta_generic_to_shared(s);
    asm volatile("cp.async.ca.shared.global [%0], [%1], 16;" :: "r"(sa), "l"(g));
}
__device__ __forceinline__ void mma_f16(float d[4], const uint32_t a[4], const uint32_t b[2]) {
    asm volatile(
        "mma.sync.aligned.m16n8k16.row.col.f32.f16.f16.f32 "
        "{%0,%1,%2,%3}, {%4,%5,%6,%7}, {%8,%9}, {%0,%1,%2,%3};"
        : "+f"(d[0]), "+f"(d[1]), "+f"(d[2]), "+f"(d[3])
        : "r"(a[0]), "r"(a[1]), "r"(a[2]), "r"(a[3]), "r"(b[0]), "r"(b[1]));
}
__device__ __forceinline__ void ldsm_x4_trans(uint32_t& d0, uint32_t& d1,
                                              uint32_t& d2, uint32_t& d3, uint32_t addr) {
    asm volatile("ldmatrix.sync.aligned.m8n8.x4.trans.shared.b16 {%0,%1,%2,%3}, [%4];"
                 : "=r"(d0), "=r"(d1), "=r"(d2), "=r"(d3) : "r"(addr));
}

// ==================== emb -> half ====================
__global__ __launch_bounds__(256)
void conv_half_kernel(const float4* __restrict__ in, __half2* __restrict__ out, int n4)
{
    int i = blockIdx.x * blockDim.x + threadIdx.x;
    int stride = gridDim.x * blockDim.x;
    for (; i < n4; i += stride) {
        float4 v = in[i];
        out[2 * i]     = __floats2half2_rn(v.x, v.y);
        out[2 * i + 1] = __floats2half2_rn(v.z, v.w);
    }
}

// ==================== transpose + convert: W[K][N] -> Wt[N][K] half ==========
__global__ __launch_bounds__(256)
void transpose_half_kernel(const float* __restrict__ in, __half* __restrict__ out,
                           int K, int N)
{
    __shared__ float tile[32][33];
    int bx = blockIdx.x * 32;
    int by = blockIdx.y * 32;
    int tx = threadIdx.x, ty = threadIdx.y;
    #pragma unroll
    for (int i = 0; i < 32; i += 8)
        tile[ty + i][tx] = in[(size_t)(by + ty + i) * N + bx + tx];
    __syncthreads();
    #pragma unroll
    for (int i = 0; i < 32; i += 8)
        out[(size_t)(bx + ty + i) * K + by + tx] = __float2half_rn(tile[tx][ty + i]);
}

// ==================== LayerNorm (half output) ====================
__global__ __launch_bounds__(256)
void ln_kernel(const float* __restrict__ x, const float* __restrict__ g,
               const float* __restrict__ bt, __half* __restrict__ out)
{
    int row = blockIdx.x;
    int t = threadIdx.x;
    const float4* xr = (const float4*)(x + (size_t)row * DIM);
    float4 v = xr[t];
    float s  = v.x + v.y + v.z + v.w;
    float sq = v.x*v.x + v.y*v.y + v.z*v.z + v.w*v.w;

    #pragma unroll
    for (int off = 16; off; off >>= 1) {
        s  += __shfl_xor_sync(0xffffffffu, s,  off);
        sq += __shfl_xor_sync(0xffffffffu, sq, off);
    }
    __shared__ float ss[8], sqs[8];
    int warp = t >> 5, lane = t & 31;
    if (lane == 0) { ss[warp] = s; sqs[warp] = sq; }
    __syncthreads();
    if (t < 32) {
        float a = (t < 8) ? ss[t]  : 0.f;
        float b = (t < 8) ? sqs[t] : 0.f;
        #pragma unroll
        for (int off = 4; off; off >>= 1) {
            a += __shfl_xor_sync(0xffffffffu, a, off);
            b += __shfl_xor_sync(0xffffffffu, b, off);
        }
        if (t == 0) { ss[0] = a; sqs[0] = b; }
    }
    __syncthreads();
    float mu  = ss[0]  * (1.0f / DIM);
    float var = sqs[0] * (1.0f / DIM) - mu * mu;
    float inv = rsqrtf(var + 1e-5f);

    float4 gv = ((const float4*)g)[t];
    float4 bv = ((const float4*)bt)[t];
    __half2* o2 = (__half2*)(out + (size_t)row * DIM);
    o2[2 * t]     = __floats2half2_rn((v.x - mu) * inv * gv.x + bv.x,
                                      (v.y - mu) * inv * gv.y + bv.y);
    o2[2 * t + 1] = __floats2half2_rn((v.z - mu) * inv * gv.z + bv.z,
                                      (v.w - mu) * inv * gv.w + bv.w);
}

// ==================== fp16 tensor-core GEMM =================================
// mode: 0 = bias (half out), 1 = bias+gelu (half out), 2 = bias+residual (fp32 out)
#define KCH   32
#define SKH   40
#define TILE_H (128 * SKH)
#define STAGE_H (2 * TILE_H)
#define GEMM_SMEM (3 * STAGE_H * 2)   // 61440 bytes

__global__ __launch_bounds__(256, 2)
void h16_gemm(int M, int N, int K,
              const __half* __restrict__ A,
              const __half* __restrict__ Bt,
              const float* __restrict__ bias,
              const float* __restrict__ res,
              void* __restrict__ Cv, int mode,
              const __half* __restrict__ Bt2,
              const float* __restrict__ bias2,
              void* __restrict__ Cv2)
{
    extern __shared__ __half smh[];

    if (blockIdx.z == 1) { Bt = Bt2; bias = bias2; Cv = Cv2; }

    int tid = threadIdx.x;
    int lane = tid & 31;
    int warp = tid >> 5;
    int warp_m = (warp >> 1) * 32;
    int warp_n = (warp & 1) * 64;
    int r = lane >> 2;
    int c = lane & 3;

    int ctaM = blockIdx.y * 128;
    int ctaN = blockIdx.x * 128;

    const __half* gA = A  + (size_t)ctaM * K;
    const __half* gB = Bt + (size_t)ctaN * K;

    int ldRow = tid >> 2;
    int ldCh  = (tid & 3) * 8;

    const int nk = K / KCH;

    #define ISSUE_STAGE(s, k0)                                                     \
    do {                                                                           \
        __half* sA_ = smh + (s) * STAGE_H;                                         \
        __half* sB_ = sA_ + TILE_H;                                                \
        const __half* a_ = gA + (k0);                                              \
        const __half* b_ = gB + (k0);                                              \
        _Pragma("unroll")                                                          \
        for (int j = 0; j < 2; j++) {                                              \
            int row = ldRow + j * 64;                                              \
            cp16(sA_ + (size_t)row * SKH + ldCh, a_ + (size_t)row * K + ldCh);     \
            cp16(sB_ + (size_t)row * SKH + ldCh, b_ + (size_t)row * K + ldCh);     \
        }                                                                          \
        asm volatile("cp.async.commit_group;");                                    \
    } while (0)

    ISSUE_STAGE(0, 0);
    if (nk > 1) ISSUE_STAGE(1, KCH);
    else        asm volatile("cp.async.commit_group;");

    float acc[2][8][4] = {};

    int buf = 0;
    for (int kt = 0; kt < nk; kt++) {
        if (kt + 2 < nk) asm volatile("cp.async.wait_group 1;");
        else             asm volatile("cp.async.wait_group 0;");
        __syncthreads();

        const __half* Asb = smh + buf * STAGE_H;
        const __half* Bsb = Asb + TILE_H;

        #pragma unroll
        for (int ks = 0; ks < 2; ks++) {
            uint32_t af[2][4], bf[8][2];
            #pragma unroll
            for (int mt = 0; mt < 2; mt++) {
                const __half* pa = Asb + (size_t)(warp_m + mt * 16 + r) * SKH + ks * 16 + 2 * c;
                af[mt][0] = *(const uint32_t*)(pa);
                af[mt][1] = *(const uint32_t*)(pa + 8 * SKH);
                af[mt][2] = *(const uint32_t*)(pa + 8);
                af[mt][3] = *(const uint32_t*)(pa + 8 * SKH + 8);
            }
            #pragma unroll
            for (int nt = 0; nt < 8; nt++) {
                const __half* pb = Bsb + (size_t)(warp_n + nt * 8 + r) * SKH + ks * 16 + 2 * c;
                bf[nt][0] = *(const uint32_t*)(pb);
                bf[nt][1] = *(const uint32_t*)(pb + 8);
            }
            #pragma unroll
            for (int mt = 0; mt < 2; mt++)
                #pragma unroll
                for (int nt = 0; nt < 8; nt++)
                    mma_f16(acc[mt][nt], af[mt], bf[nt]);
        }

        if (kt + 2 < nk) {
            int s = (kt + 2) % 3;
            ISSUE_STAGE(s, (kt + 2) * KCH);
        }
        buf = (buf + 1) % 3;
    }
    #undef ISSUE_STAGE

    // ---- epilogue ----
    float*  Cf = (float*)Cv;
    __half* Ch = (__half*)Cv;
    #pragma unroll
    for (int mt = 0; mt < 2; mt++) {
        #pragma unroll
        for (int nt = 0; nt < 8; nt++) {
            int row = ctaM + warp_m + mt * 16 + r;
            int col = ctaN + warp_n + nt * 8 + 2 * c;
            float b0 = bias[col], b1 = bias[col + 1];
            float v0 = acc[mt][nt][0] + b0;
            float v1 = acc[mt][nt][1] + b1;
            float v2 = acc[mt][nt][2] + b0;
            float v3 = acc[mt][nt][3] + b1;
            if (mode == 2) {
                const float* r0 = res + (size_t)row * N + col;
                const float* r1 = res + (size_t)(row + 8) * N + col;
                v0 += r0[0]; v1 += r0[1];
                v2 += r1[0]; v3 += r1[1];
                *(float2*)(Cf + (size_t)row * N + col)       = make_float2(v0, v1);
                *(float2*)(Cf + (size_t)(row + 8) * N + col) = make_float2(v2, v3);
            } else {
                if (mode == 1) {
                    v0 = gelu_exact(v0); v1 = gelu_exact(v1);
                    v2 = gelu_exact(v2); v3 = gelu_exact(v3);
                }
                *(__half2*)(Ch + (size_t)row * N + col)       = __floats2half2_rn(v0, v1);
                *(__half2*)(Ch + (size_t)(row + 8) * N + col) = __floats2half2_rn(v2, v3);
            }
        }
    }
}

// ==================== fp16 tensor-core flash attention =======================
// CTA: 128 q-rows, 8 warps x 16q, K/V tiles of 64 keys (half), double-buffered.
// S = Q@K^T via m16n8k16 (K frags = direct u32), P@V via ldmatrix.x4.trans on V.
#define BQ_T   128
#define TILE_K 64
#define SKKH 72     // K smem stride (halves); 144B, 16B-aligned
#define SKVH 72     // V smem stride (halves)
#define SKPH 72     // P smem stride (halves)
#define NT_KV (NK / TILE_K)
// halves: K 2*64*72, V 2*64*72, P 128*72
#define ATT_SMEM ((2*TILE_K*SKKH + 2*TILE_K*SKVH + BQ_T*SKPH) * 2)   // 55296 B

__global__ __launch_bounds__(256, 2)
void attn_mma(const __half* __restrict__ Q, const __half* __restrict__ Kg,
              const __half* __restrict__ Vg, __half* __restrict__ ctx)
{
    extern __shared__ __half smA[];
    __half* KsB = smA;                                  // [2][64][SKKH]
    __half* VsB = smA + 2 * TILE_K * SKKH;              // [2][64][SKVH]
    __half* Ps  = smA + 2 * TILE_K * (SKKH + SKVH);     // [128][SKPH]

    int b = blockIdx.z, h = blockIdx.y, qt = blockIdx.x;
    int tid = threadIdx.x, lane = tid & 31, w = tid >> 5;
    int r = lane >> 2, c = lane & 3;

    const __half* Qb = Q  + ((size_t)(b * NQ + qt * BQ_T)) * DIM + h * HD;
    const __half* Kb = Kg + ((size_t)b * NK) * DIM + h * HD;
    const __half* Vb = Vg + ((size_t)b * NK) * DIM + h * HD;

    // issue K/V tile 0: 64 rows x 64 halves (8 x 16B chunks per row)
    #pragma unroll
    for (int i = 0; i < 2; i++) {
        int idx = tid + i * 256;              // 0..511
        int row = idx >> 3, ch = (idx & 7) * 8;
        cp16(&KsB[row * SKKH + ch], Kb + (size_t)row * DIM + ch);
        cp16(&VsB[row * SKVH + ch], Vb + (size_t)row * DIM + ch);
    }
    asm volatile("cp.async.commit_group;");

    // Q fragments (scaled by 1/8, exact in fp16), 4 k16-groups over HD=64
    uint32_t qf[4][4];
    {
        const __half2 sc = __floats2half2_rn(0.125f, 0.125f);
        const __half* q0 = Qb + (size_t)(w * 16 + r) * DIM;
        const __half* q1 = Qb + (size_t)(w * 16 + r + 8) * DIM;
        #pragma unroll
        for (int kg = 0; kg < 4; kg++) {
            __half2 a0 = __hmul2(*(const __half2*)(q0 + kg * 16 + 2 * c), sc);
            __half2 a1 = __hmul2(*(const __half2*)(q1 + kg * 16 + 2 * c), sc);
            __half2 a2 = __hmul2(*(const __half2*)(q0 + kg * 16 + 2 * c + 8), sc);
            __half2 a3 = __hmul2(*(const __half2*)(q1 + kg * 16 + 2 * c + 8), sc);
            qf[kg][0] = *(uint32_t*)&a0; qf[kg][1] = *(uint32_t*)&a1;
            qf[kg][2] = *(uint32_t*)&a2; qf[kg][3] = *(uint32_t*)&a3;
        }
    }

    float m0 = -1e30f, m1 = -1e30f, l0 = 0.f, l1 = 0.f;
    float accO[8][4] = {};
    __half* Pw = Ps + (w * 16) * SKPH;
    // ldmatrix source address (per-lane row), set per (buf, kg, nt) below
    int l16 = lane & 15, nsel = lane >> 4;

    for (int kt = 0; kt < NT_KV; kt++) {
        int buf = kt & 1;
        asm volatile("cp.async.wait_group 0;");
        __syncthreads();

        if (kt + 1 < NT_KV) {
            const __half* kp = Kb + (size_t)(kt + 1) * TILE_K * DIM;
            const __half* vp = Vb + (size_t)(kt + 1) * TILE_K * DIM;
            __half* Kd = KsB + (buf ^ 1) * TILE_K * SKKH;
            __half* Vd = VsB + (buf ^ 1) * TILE_K * SKVH;
            #pragma unroll
            for (int i = 0; i < 2; i++) {
                int idx = tid + i * 256;
                int row = idx >> 3, ch = (idx & 7) * 8;
                cp16(&Kd[row * SKKH + ch], kp + (size_t)row * DIM + ch);
                cp16(&Vd[row * SKVH + ch], vp + (size_t)row * DIM + ch);
            }
            asm volatile("cp.async.commit_group;");
        }

        const __half* Kt = KsB + buf * TILE_K * SKKH;
        const __half* Vt = VsB + buf * TILE_K * SKVH;

        // S = Q@K^T : 4 kg x 8 nt fp16 mma
        float accS[8][4] = {};
        #pragma unroll
        for (int kg = 0; kg < 4; kg++) {
            #pragma unroll
            for (int nt = 0; nt < 8; nt++) {
                const __half* pb = Kt + (size_t)(nt * 8 + r) * SKKH + kg * 16 + 2 * c;
                uint32_t bf[2];
                bf[0] = *(const uint32_t*)(pb);
                bf[1] = *(const uint32_t*)(pb + 8);
                mma_f16(accS[nt], qf[kg], bf);
            }
        }

        // online softmax
        float mx0 = -1e30f, mx1 = -1e30f;
        #pragma unroll
        for (int nt = 0; nt < 8; nt++) {
            mx0 = fmaxf(mx0, fmaxf(accS[nt][0], accS[nt][1]));
            mx1 = fmaxf(mx1, fmaxf(accS[nt][2], accS[nt][3]));
        }
        mx0 = fmaxf(mx0, __shfl_xor_sync(0xffffffffu, mx0, 1));
        mx0 = fmaxf(mx0, __shfl_xor_sync(0xffffffffu, mx0, 2));
        mx1 = fmaxf(mx1, __shfl_xor_sync(0xffffffffu, mx1, 1));
        mx1 = fmaxf(mx1, __shfl_xor_sync(0xffffffffu, mx1, 2));
        float mn0 = fmaxf(m0, mx0), mn1 = fmaxf(m1, mx1);
        float f0 = __expf(m0 - mn0), f1 = __expf(m1 - mn1);
        float s0 = 0.f, s1 = 0.f;
        #pragma unroll
        for (int nt = 0; nt < 8; nt++) {
            accS[nt][0] = __expf(accS[nt][0] - mn0);
            accS[nt][1] = __expf(accS[nt][1] - mn0);
            accS[nt][2] = __expf(accS[nt][2] - mn1);
            accS[nt][3] = __expf(accS[nt][3] - mn1);
            s0 += accS[nt][0] + accS[nt][1];
            s1 += accS[nt][2] + accS[nt][3];
        }
        s0 += __shfl_xor_sync(0xffffffffu, s0, 1);
        s0 += __shfl_xor_sync(0xffffffffu, s0, 2);
        s1 += __shfl_xor_sync(0xffffffffu, s1, 1);
        s1 += __shfl_xor_sync(0xffffffffu, s1, 2);
        l0 = l0 * f0 + s0; l1 = l1 * f1 + s1;
        m0 = mn0; m1 = mn1;
        #pragma unroll
        for (int nt = 0; nt < 8; nt++) {
            accO[nt][0] *= f0; accO[nt][1] *= f0;
            accO[nt][2] *= f1; accO[nt][3] *= f1;
        }

        // P -> warp-private smem (half2)
        #pragma unroll
        for (int nt = 0; nt < 8; nt++) {
            *(__half2*)&Pw[r * SKPH + nt * 8 + 2 * c] =
                __floats2half2_rn(accS[nt][0], accS[nt][1]);
            *(__half2*)&Pw[(r + 8) * SKPH + nt * 8 + 2 * c] =
                __floats2half2_rn(accS[nt][2], accS[nt][3]);
        }
        __syncwarp();

        // O += P @ V : 4 kg (16 keys each) x 8 nt (8 d each), V via ldmatrix.trans
        #pragma unroll
        for (int kg = 0; kg < 4; kg++) {
            uint32_t af[4];
            const __half* pp = Pw + kg * 16 + 2 * c;
            af[0] = *(const uint32_t*)(pp + r * SKPH);
            af[1] = *(const uint32_t*)(pp + (r + 8) * SKPH);
            af[2] = *(const uint32_t*)(pp + r * SKPH + 8);
            af[3] = *(const uint32_t*)(pp + (r + 8) * SKPH + 8);
            #pragma unroll
            for (int nt = 0; nt < 8; nt += 2) {
                uint32_t vaddr = (uint32_t)__cvta_generic_to_shared(
                    Vt + (size_t)(kg * 16 + l16) * SKVH + (nt + nsel) * 8);
                uint32_t b0, b1, b2, b3;
                ldsm_x4_trans(b0, b1, b2, b3, vaddr);
                uint32_t bfa[2] = { b0, b1 }, bfb[2] = { b2, b3 };
                mma_f16(accO[nt], af, bfa);
                mma_f16(accO[nt + 1], af, bfb);
            }
        }
        __syncwarp();
    }

    // epilogue: divide by l, write half ctx
    float inv0 = 1.f / l0, inv1 = 1.f / l1;
    __half* Cb = ctx + ((size_t)(b * NQ + qt * BQ_T + w * 16)) * DIM + h * HD;
    #pragma unroll
    for (int nt = 0; nt < 8; nt++) {
        *(__half2*)(Cb + (size_t)r * DIM + nt * 8 + 2 * c) =
            __floats2half2_rn(accO[nt][0] * inv0, accO[nt][1] * inv0);
        *(__half2*)(Cb + (size_t)(r + 8) * DIM + nt * 8 + 2 * c) =
            __floats2half2_rn(accO[nt][2] * inv1, accO[nt][3] * inv1);
    }
}

// ==================== launch =================================================
extern "C" void kernel_launch(void* const* d_in, const int* in_sizes, int n_in,
                              void* d_out, int out_size)
{
    const float* tgt  = (const float*)d_in[0];
    const float* emb  = (const float*)d_in[1];
    const float* ln_g = (const float*)d_in[2];
    const float* ln_b = (const float*)d_in[3];
    const float* wq = (const float*)d_in[4];  const float* bq = (const float*)d_in[5];
    const float* wk = (const float*)d_in[6];  const float* bk = (const float*)d_in[7];
    const float* wv = (const float*)d_in[8];  const float* bv = (const float*)d_in[9];
    const float* wo = (const float*)d_in[10]; const float* bo = (const float*)d_in[11];
    const float* w1 = (const float*)d_in[12]; const float* b1 = (const float*)d_in[13];
    const float* w2 = (const float*)d_in[14]; const float* b2 = (const float*)d_in[15];
    float* out = (float*)d_out;

    __half *qn, *q, *k, *v, *ctx, *h1, *embh, *wqt, *wkt, *wvt, *wot, *w1t, *w2t;
    cudaGetSymbolAddress((void**)&qn,   g_qn);
    cudaGetSymbolAddress((void**)&q,    g_q);
    cudaGetSymbolAddress((void**)&k,    g_k);
    cudaGetSymbolAddress((void**)&v,    g_v);
    cudaGetSymbolAddress((void**)&ctx,  g_ctx);
    cudaGetSymbolAddress((void**)&h1,   g_h1);
    cudaGetSymbolAddress((void**)&embh, g_embh);
    cudaGetSymbolAddress((void**)&wqt,  g_wqt);
    cudaGetSymbolAddress((void**)&wkt,  g_wkt);
    cudaGetSymbolAddress((void**)&wvt,  g_wvt);
    cudaGetSymbolAddress((void**)&wot,  g_wot);
    cudaGetSymbolAddress((void**)&w1t,  g_w1t);
    cudaGetSymbolAddress((void**)&w2t,  g_w2t);

    cudaFuncSetAttribute(h16_gemm, cudaFuncAttributeMaxDynamicSharedMemorySize, GEMM_SMEM);
    cudaFuncSetAttribute(attn_mma, cudaFuncAttributeMaxDynamicSharedMemorySize, ATT_SMEM);

    // 0) transpose+convert weights into [N][K] half; convert emb to half
    dim3 tb(32, 8);
    transpose_half_kernel<<<dim3(DIM / 32, DIM / 32), tb>>>(wq, wqt, DIM, DIM);
    transpose_half_kernel<<<dim3(DIM / 32, DIM / 32), tb>>>(wk, wkt, DIM, DIM);
    transpose_half_kernel<<<dim3(DIM / 32, DIM / 32), tb>>>(wv, wvt, DIM, DIM);
    transpose_half_kernel<<<dim3(DIM / 32, DIM / 32), tb>>>(wo, wot, DIM, DIM);
    transpose_half_kernel<<<dim3(HIDDEN / 32, DIM / 32), tb>>>(w1, w1t, DIM, HIDDEN);
    transpose_half_kernel<<<dim3(DIM / 32, HIDDEN / 32), tb>>>(w2, w2t, HIDDEN, DIM);
    conv_half_kernel<<<1024, 256>>>((const float4*)emb, (__half2*)embh, MK * DIM / 4);

    // 1) qn = LN(tgt) (half)
    ln_kernel<<<MQ, 256>>>(tgt, ln_g, ln_b, qn);

    // 2) Q = qn @ wq + bq (half out)
    h16_gemm<<<dim3(DIM / 128, MQ / 128, 1), 256, GEMM_SMEM>>>(
        MQ, DIM, DIM, qn, wqt, bq, nullptr, q, 0, wqt, bq, q);
    // 3+4) K,V = emb @ {wk,wv} (fused z=2, half out)
    h16_gemm<<<dim3(DIM / 128, MK / 128, 2), 256, GEMM_SMEM>>>(
        MK, DIM, DIM, embh, wkt, bk, nullptr, k, 0, wvt, bv, v);

    // 5) ctx = softmax(Q K^T / 8) V  (fp16 flash, half out)
    attn_mma<<<dim3(NQ / BQ_T, HEADS, BSZ), 256, ATT_SMEM>>>(q, k, v, ctx);

    // 6) tgt1 = tgt + ctx @ wo + bo -> d_out (fp32)
    h16_gemm<<<dim3(DIM / 128, MQ / 128, 1), 256, GEMM_SMEM>>>(
        MQ, DIM, DIM, ctx, wot, bo, tgt, out, 2, wot, bo, out);

    // 7) h_in = LN(tgt1) (half)
    ln_kernel<<<MQ, 256>>>(out, ln_g, ln_b, qn);

    // 8) h1 = gelu(h_in @ w1 + b1) (half out)
    h16_gemm<<<dim3(HIDDEN / 128, MQ / 128, 1), 256, GEMM_SMEM>>>(
        MQ, HIDDEN, DIM, qn, w1t, b1, nullptr, h1, 1, w1t, b1, h1);

    // 9) out = tgt1 + h1 @ w2 + b2 (fp32)
    h16_gemm<<<dim3(DIM / 128, MQ / 128, 1), 256, GEMM_SMEM>>>(
        MQ, DIM, HIDDEN, h1, w2t, b2, out, out, 2, w2t, b2, out);
}

// round 9
// speedup vs baseline: 7.1271x; 1.0817x over previous
#include <cuda_runtime.h>
#include <cuda_fp16.h>
#include <math.h>
#include <stdint.h>

// ---------------- problem constants ----------------
#define BSZ     4
#define NQ      1024
#define NK      2048
#define DIM     1024
#define HEADS   16
#define HD      64
#define HIDDEN  4096
#define MQ      (BSZ*NQ)   // 4096
#define MK      (BSZ*NK)   // 8192

// ---------------- scratch ----------
__device__ __align__(128) __half g_qn  [(size_t)MQ * DIM];
__device__ __align__(128) __half g_q   [(size_t)MQ * DIM];
__device__ __align__(128) __half g_k   [(size_t)MK * DIM];
__device__ __align__(128) __half g_v   [(size_t)MK * DIM];
__device__ __align__(128) __half g_ctx [(size_t)MQ * DIM];
__device__ __align__(128) __half g_h1  [(size_t)MQ * HIDDEN];
__device__ __align__(128) __half g_embh[(size_t)MK * DIM];
__device__ __align__(128) __half g_wqt [(size_t)DIM * DIM];
__device__ __align__(128) __half g_wkt [(size_t)DIM * DIM];
__device__ __align__(128) __half g_wvt [(size_t)DIM * DIM];
__device__ __align__(128) __half g_wot [(size_t)DIM * DIM];
__device__ __align__(128) __half g_w1t [(size_t)DIM * HIDDEN];
__device__ __align__(128) __half g_w2t [(size_t)HIDDEN * DIM];

// ==================== helpers ====================
__device__ __forceinline__ float gelu_exact(float x) {
    return 0.5f * x * (1.0f + erff(x * 0.70710678118654752f));
}
__device__ __forceinline__ void cp16(void* s, const void* g) {
    uint32_t sa = (uint32_t)__cvta_generic_to_shared(s);
    asm volatile("cp.async.ca.shared.global [%0], [%1], 16;" :: "r"(sa), "l"(g));
}
__device__ __forceinline__ void mma_f16(float d[4], const uint32_t a[4], const uint32_t b[2]) {
    asm volatile(
        "mma.sync.aligned.m16n8k16.row.col.f32.f16.f16.f32 "
        "{%0,%1,%2,%3}, {%4,%5,%6,%7}, {%8,%9}, {%0,%1,%2,%3};"
        : "+f"(d[0]), "+f"(d[1]), "+f"(d[2]), "+f"(d[3])
        : "r"(a[0]), "r"(a[1]), "r"(a[2]), "r"(a[3]), "r"(b[0]), "r"(b[1]));
}
__device__ __forceinline__ void ldsm_x4(uint32_t& d0, uint32_t& d1,
                                        uint32_t& d2, uint32_t& d3, uint32_t addr) {
    asm volatile("ldmatrix.sync.aligned.m8n8.x4.shared.b16 {%0,%1,%2,%3}, [%4];"
                 : "=r"(d0), "=r"(d1), "=r"(d2), "=r"(d3) : "r"(addr));
}
__device__ __forceinline__ void ldsm_x4_trans(uint32_t& d0, uint32_t& d1,
                                              uint32_t& d2, uint32_t& d3, uint32_t addr) {
    asm volatile("ldmatrix.sync.aligned.m8n8.x4.trans.shared.b16 {%0,%1,%2,%3}, [%4];"
                 : "=r"(d0), "=r"(d1), "=r"(d2), "=r"(d3) : "r"(addr));
}

// ==================== emb -> half ====================
__global__ __launch_bounds__(256)
void conv_half_kernel(const float4* __restrict__ in, __half2* __restrict__ out, int n4)
{
    int i = blockIdx.x * blockDim.x + threadIdx.x;
    int stride = gridDim.x * blockDim.x;
    for (; i < n4; i += stride) {
        float4 v = in[i];
        out[2 * i]     = __floats2half2_rn(v.x, v.y);
        out[2 * i + 1] = __floats2half2_rn(v.z, v.w);
    }
}

// ==================== transpose + convert: W[K][N] -> Wt[N][K] half ==========
__global__ __launch_bounds__(256)
void transpose_half_kernel(const float* __restrict__ in, __half* __restrict__ out,
                           int K, int N)
{
    __shared__ float tile[32][33];
    int bx = blockIdx.x * 32;
    int by = blockIdx.y * 32;
    int tx = threadIdx.x, ty = threadIdx.y;
    #pragma unroll
    for (int i = 0; i < 32; i += 8)
        tile[ty + i][tx] = in[(size_t)(by + ty + i) * N + bx + tx];
    __syncthreads();
    #pragma unroll
    for (int i = 0; i < 32; i += 8)
        out[(size_t)(bx + ty + i) * K + by + tx] = __float2half_rn(tile[tx][ty + i]);
}

// ==================== LayerNorm (half output) ====================
__global__ __launch_bounds__(256)
void ln_kernel(const float* __restrict__ x, const float* __restrict__ g,
               const float* __restrict__ bt, __half* __restrict__ out)
{
    int row = blockIdx.x;
    int t = threadIdx.x;
    const float4* xr = (const float4*)(x + (size_t)row * DIM);
    float4 v = xr[t];
    float s  = v.x + v.y + v.z + v.w;
    float sq = v.x*v.x + v.y*v.y + v.z*v.z + v.w*v.w;

    #pragma unroll
    for (int off = 16; off; off >>= 1) {
        s  += __shfl_xor_sync(0xffffffffu, s,  off);
        sq += __shfl_xor_sync(0xffffffffu, sq, off);
    }
    __shared__ float ss[8], sqs[8];
    int warp = t >> 5, lane = t & 31;
    if (lane == 0) { ss[warp] = s; sqs[warp] = sq; }
    __syncthreads();
    if (t < 32) {
        float a = (t < 8) ? ss[t]  : 0.f;
        float b = (t < 8) ? sqs[t] : 0.f;
        #pragma unroll
        for (int off = 4; off; off >>= 1) {
            a += __shfl_xor_sync(0xffffffffu, a, off);
            b += __shfl_xor_sync(0xffffffffu, b, off);
        }
        if (t == 0) { ss[0] = a; sqs[0] = b; }
    }
    __syncthreads();
    float mu  = ss[0]  * (1.0f / DIM);
    float var = sqs[0] * (1.0f / DIM) - mu * mu;
    float inv = rsqrtf(var + 1e-5f);

    float4 gv = ((const float4*)g)[t];
    float4 bv = ((const float4*)bt)[t];
    __half2* o2 = (__half2*)(out + (size_t)row * DIM);
    o2[2 * t]     = __floats2half2_rn((v.x - mu) * inv * gv.x + bv.x,
                                      (v.y - mu) * inv * gv.y + bv.y);
    o2[2 * t + 1] = __floats2half2_rn((v.z - mu) * inv * gv.z + bv.z,
                                      (v.w - mu) * inv * gv.w + bv.w);
}

// ==================== fp16 tensor-core GEMM (ldmatrix, 4-stage) ==============
// mode: 0 = bias (half out), 1 = bias+gelu (half out), 2 = bias+residual (fp32 out)
#define KCH   32
#define SKH   40
#define TILE_H (128 * SKH)
#define STAGE_H (2 * TILE_H)
#define N_STG 4
#define GEMM_SMEM (N_STG * STAGE_H * 2)   // 81920 bytes

__global__ __launch_bounds__(256, 2)
void h16_gemm(int M, int N, int K,
              const __half* __restrict__ A,
              const __half* __restrict__ Bt,
              const float* __restrict__ bias,
              const float* __restrict__ res,
              void* __restrict__ Cv, int mode,
              const __half* __restrict__ Bt2,
              const float* __restrict__ bias2,
              void* __restrict__ Cv2)
{
    extern __shared__ __half smh[];

    if (blockIdx.z == 1) { Bt = Bt2; bias = bias2; Cv = Cv2; }

    int tid = threadIdx.x;
    int lane = tid & 31;
    int warp = tid >> 5;
    int warp_m = (warp >> 1) * 32;
    int warp_n = (warp & 1) * 64;
    int r = lane >> 2;
    int c = lane & 3;

    int ctaM = blockIdx.y * 128;
    int ctaN = blockIdx.x * 128;

    const __half* gA = A  + (size_t)ctaM * K;
    const __half* gB = Bt + (size_t)ctaN * K;

    int ldRow = tid >> 2;
    int ldCh  = (tid & 3) * 8;

    const int nk = K / KCH;

    // ldmatrix per-lane selectors
    uint32_t smb = (uint32_t)__cvta_generic_to_shared(smh);
    int aRowSel = lane & 15;                 // A/M0..3 row within 16
    int aKSel   = (lane >> 4) * 8;           // k half
    int bNSel   = (lane & 7) + ((lane >> 4) << 3);   // n row within 16
    int bKSel   = ((lane >> 3) & 1) * 8;     // k half
    uint32_t aBase = smb + (uint32_t)(((warp_m + aRowSel) * SKH + aKSel) * 2);
    uint32_t bBase = smb + (uint32_t)((TILE_H + (warp_n + bNSel) * SKH + bKSel) * 2);

    #define ISSUE_STAGE(s, k0)                                                     \
    do {                                                                           \
        __half* sA_ = smh + (s) * STAGE_H;                                         \
        __half* sB_ = sA_ + TILE_H;                                                \
        const __half* a_ = gA + (k0);                                              \
        const __half* b_ = gB + (k0);                                              \
        _Pragma("unroll")                                                          \
        for (int j = 0; j < 2; j++) {                                              \
            int row = ldRow + j * 64;                                              \
            cp16(sA_ + (size_t)row * SKH + ldCh, a_ + (size_t)row * K + ldCh);     \
            cp16(sB_ + (size_t)row * SKH + ldCh, b_ + (size_t)row * K + ldCh);     \
        }                                                                          \
        asm volatile("cp.async.commit_group;");                                    \
    } while (0)

    ISSUE_STAGE(0, 0);
    if (nk > 1) ISSUE_STAGE(1, KCH);
    else        asm volatile("cp.async.commit_group;");
    if (nk > 2) ISSUE_STAGE(2, 2 * KCH);
    else        asm volatile("cp.async.commit_group;");

    float acc[2][8][4] = {};

    for (int kt = 0; kt < nk; kt++) {
        int buf = kt % N_STG;
        int rem = nk - 1 - kt;
        if (rem >= 2)      asm volatile("cp.async.wait_group 2;");
        else if (rem == 1) asm volatile("cp.async.wait_group 1;");
        else               asm volatile("cp.async.wait_group 0;");
        __syncthreads();

        uint32_t stOff = (uint32_t)(buf * STAGE_H * 2);

        #pragma unroll
        for (int ks = 0; ks < 2; ks++) {
            uint32_t af[2][4], bf[8][2];
            uint32_t kOff = (uint32_t)(ks * 16 * 2);
            #pragma unroll
            for (int mt = 0; mt < 2; mt++)
                ldsm_x4(af[mt][0], af[mt][1], af[mt][2], af[mt][3],
                        aBase + stOff + kOff + (uint32_t)(mt * 16 * SKH * 2));
            #pragma unroll
            for (int np = 0; np < 4; np++)
                ldsm_x4(bf[2 * np][0], bf[2 * np][1], bf[2 * np + 1][0], bf[2 * np + 1][1],
                        bBase + stOff + kOff + (uint32_t)(np * 16 * SKH * 2));
            #pragma unroll
            for (int mt = 0; mt < 2; mt++)
                #pragma unroll
                for (int nt = 0; nt < 8; nt++)
                    mma_f16(acc[mt][nt], af[mt], bf[nt]);
        }

        if (kt + 3 < nk) {
            int s = (kt + 3) % N_STG;
            ISSUE_STAGE(s, (kt + 3) * KCH);
        }
    }
    #undef ISSUE_STAGE

    // ---- epilogue ----
    float*  Cf = (float*)Cv;
    __half* Ch = (__half*)Cv;
    #pragma unroll
    for (int mt = 0; mt < 2; mt++) {
        #pragma unroll
        for (int nt = 0; nt < 8; nt++) {
            int row = ctaM + warp_m + mt * 16 + r;
            int col = ctaN + warp_n + nt * 8 + 2 * c;
            float b0 = bias[col], b1 = bias[col + 1];
            float v0 = acc[mt][nt][0] + b0;
            float v1 = acc[mt][nt][1] + b1;
            float v2 = acc[mt][nt][2] + b0;
            float v3 = acc[mt][nt][3] + b1;
            if (mode == 2) {
                const float* r0 = res + (size_t)row * N + col;
                const float* r1 = res + (size_t)(row + 8) * N + col;
                v0 += r0[0]; v1 += r0[1];
                v2 += r1[0]; v3 += r1[1];
                *(float2*)(Cf + (size_t)row * N + col)       = make_float2(v0, v1);
                *(float2*)(Cf + (size_t)(row + 8) * N + col) = make_float2(v2, v3);
            } else {
                if (mode == 1) {
                    v0 = gelu_exact(v0); v1 = gelu_exact(v1);
                    v2 = gelu_exact(v2); v3 = gelu_exact(v3);
                }
                *(__half2*)(Ch + (size_t)row * N + col)       = __floats2half2_rn(v0, v1);
                *(__half2*)(Ch + (size_t)(row + 8) * N + col) = __floats2half2_rn(v2, v3);
            }
        }
    }
}

// ==================== fp16 flash attention (ldmatrix everywhere) =============
#define BQ_T   128
#define TILE_K 64
#define SKKH 72
#define SKVH 72
#define SKPH 72
#define NT_KV (NK / TILE_K)
#define ATT_SMEM ((2*TILE_K*SKKH + 2*TILE_K*SKVH + BQ_T*SKPH) * 2)   // 55296 B

__global__ __launch_bounds__(256, 2)
void attn_mma(const __half* __restrict__ Q, const __half* __restrict__ Kg,
              const __half* __restrict__ Vg, __half* __restrict__ ctx)
{
    extern __shared__ __half smA[];
    __half* KsB = smA;
    __half* VsB = smA + 2 * TILE_K * SKKH;
    __half* Ps  = smA + 2 * TILE_K * (SKKH + SKVH);

    int b = blockIdx.z, h = blockIdx.y, qt = blockIdx.x;
    int tid = threadIdx.x, lane = tid & 31, w = tid >> 5;
    int r = lane >> 2, c = lane & 3;

    const __half* Qb = Q  + ((size_t)(b * NQ + qt * BQ_T)) * DIM + h * HD;
    const __half* Kb = Kg + ((size_t)b * NK) * DIM + h * HD;
    const __half* Vb = Vg + ((size_t)b * NK) * DIM + h * HD;

    #pragma unroll
    for (int i = 0; i < 2; i++) {
        int idx = tid + i * 256;
        int row = idx >> 3, ch = (idx & 7) * 8;
        cp16(&KsB[row * SKKH + ch], Kb + (size_t)row * DIM + ch);
        cp16(&VsB[row * SKVH + ch], Vb + (size_t)row * DIM + ch);
    }
    asm volatile("cp.async.commit_group;");

    uint32_t qf[4][4];
    {
        const __half2 sc = __floats2half2_rn(0.125f, 0.125f);
        const __half* q0 = Qb + (size_t)(w * 16 + r) * DIM;
        const __half* q1 = Qb + (size_t)(w * 16 + r + 8) * DIM;
        #pragma unroll
        for (int kg = 0; kg < 4; kg++) {
            __half2 a0 = __hmul2(*(const __half2*)(q0 + kg * 16 + 2 * c), sc);
            __half2 a1 = __hmul2(*(const __half2*)(q1 + kg * 16 + 2 * c), sc);
            __half2 a2 = __hmul2(*(const __half2*)(q0 + kg * 16 + 2 * c + 8), sc);
            __half2 a3 = __hmul2(*(const __half2*)(q1 + kg * 16 + 2 * c + 8), sc);
            qf[kg][0] = *(uint32_t*)&a0; qf[kg][1] = *(uint32_t*)&a1;
            qf[kg][2] = *(uint32_t*)&a2; qf[kg][3] = *(uint32_t*)&a3;
        }
    }

    float m0 = -1e30f, m1 = -1e30f, l0 = 0.f, l1 = 0.f;
    float accO[8][4] = {};
    __half* Pw = Ps + (w * 16) * SKPH;
    int l16 = lane & 15, nsel = lane >> 4;

    // ldmatrix selectors
    uint32_t smb = (uint32_t)__cvta_generic_to_shared(smA);
    int bNSel = (lane & 7) + ((lane >> 4) << 3);
    int bKSel = ((lane >> 3) & 1) * 8;
    int aRowSel = lane & 15;
    int aKSel   = (lane >> 4) * 8;
    uint32_t kFragBase = smb + (uint32_t)((bNSel * SKKH + bKSel) * 2);
    uint32_t pFragBase = smb + (uint32_t)((2 * TILE_K * (SKKH + SKVH)
                         + (w * 16 + aRowSel) * SKPH + aKSel) * 2);

    for (int kt = 0; kt < NT_KV; kt++) {
        int buf = kt & 1;
        asm volatile("cp.async.wait_group 0;");
        __syncthreads();

        if (kt + 1 < NT_KV) {
            const __half* kp = Kb + (size_t)(kt + 1) * TILE_K * DIM;
            const __half* vp = Vb + (size_t)(kt + 1) * TILE_K * DIM;
            __half* Kd = KsB + (buf ^ 1) * TILE_K * SKKH;
            __half* Vd = VsB + (buf ^ 1) * TILE_K * SKVH;
            #pragma unroll
            for (int i = 0; i < 2; i++) {
                int idx = tid + i * 256;
                int row = idx >> 3, ch = (idx & 7) * 8;
                cp16(&Kd[row * SKKH + ch], kp + (size_t)row * DIM + ch);
                cp16(&Vd[row * SKVH + ch], vp + (size_t)row * DIM + ch);
            }
            asm volatile("cp.async.commit_group;");
        }

        const __half* Vt = VsB + buf * TILE_K * SKVH;
        uint32_t kStage = (uint32_t)(buf * TILE_K * SKKH * 2);

        // S = Q@K^T : K frags via ldmatrix.x4 (2 n-tiles per load)
        float accS[8][4] = {};
        #pragma unroll
        for (int kg = 0; kg < 4; kg++) {
            uint32_t kOff = (uint32_t)(kg * 16 * 2);
            #pragma unroll
            for (int np = 0; np < 4; np++) {
                uint32_t bf0[2], bf1[2];
                ldsm_x4(bf0[0], bf0[1], bf1[0], bf1[1],
                        kFragBase + kStage + kOff + (uint32_t)(np * 16 * SKKH * 2));
                mma_f16(accS[2 * np],     qf[kg], bf0);
                mma_f16(accS[2 * np + 1], qf[kg], bf1);
            }
        }

        // online softmax
        float mx0 = -1e30f, mx1 = -1e30f;
        #pragma unroll
        for (int nt = 0; nt < 8; nt++) {
            mx0 = fmaxf(mx0, fmaxf(accS[nt][0], accS[nt][1]));
            mx1 = fmaxf(mx1, fmaxf(accS[nt][2], accS[nt][3]));
        }
        mx0 = fmaxf(mx0, __shfl_xor_sync(0xffffffffu, mx0, 1));
        mx0 = fmaxf(mx0, __shfl_xor_sync(0xffffffffu, mx0, 2));
        mx1 = fmaxf(mx1, __shfl_xor_sync(0xffffffffu, mx1, 1));
        mx1 = fmaxf(mx1, __shfl_xor_sync(0xffffffffu, mx1, 2));
        float mn0 = fmaxf(m0, mx0), mn1 = fmaxf(m1, mx1);
        float f0 = __expf(m0 - mn0), f1 = __expf(m1 - mn1);
        float s0 = 0.f, s1 = 0.f;
        #pragma unroll
        for (int nt = 0; nt < 8; nt++) {
            accS[nt][0] = __expf(accS[nt][0] - mn0);
            accS[nt][1] = __expf(accS[nt][1] - mn0);
            accS[nt][2] = __expf(accS[nt][2] - mn1);
            accS[nt][3] = __expf(accS[nt][3] - mn1);
            s0 += accS[nt][0] + accS[nt][1];
            s1 += accS[nt][2] + accS[nt][3];
        }
        s0 += __shfl_xor_sync(0xffffffffu, s0, 1);
        s0 += __shfl_xor_sync(0xffffffffu, s0, 2);
        s1 += __shfl_xor_sync(0xffffffffu, s1, 1);
        s1 += __shfl_xor_sync(0xffffffffu, s1, 2);
        l0 = l0 * f0 + s0; l1 = l1 * f1 + s1;
        m0 = mn0; m1 = mn1;
        #pragma unroll
        for (int nt = 0; nt < 8; nt++) {
            accO[nt][0] *= f0; accO[nt][1] *= f0;
            accO[nt][2] *= f1; accO[nt][3] *= f1;
        }

        // P -> warp-private smem (half2)
        #pragma unroll
        for (int nt = 0; nt < 8; nt++) {
            *(__half2*)&Pw[r * SKPH + nt * 8 + 2 * c] =
                __floats2half2_rn(accS[nt][0], accS[nt][1]);
            *(__half2*)&Pw[(r + 8) * SKPH + nt * 8 + 2 * c] =
                __floats2half2_rn(accS[nt][2], accS[nt][3]);
        }
        __syncwarp();

        // O += P @ V : P frags via ldmatrix.x4, V via ldmatrix.x4.trans
        #pragma unroll
        for (int kg = 0; kg < 4; kg++) {
            uint32_t af[4];
            ldsm_x4(af[0], af[1], af[2], af[3],
                    pFragBase + (uint32_t)(kg * 16 * 2));
            #pragma unroll
            for (int nt = 0; nt < 8; nt += 2) {
                uint32_t vaddr = (uint32_t)__cvta_generic_to_shared(
                    Vt + (size_t)(kg * 16 + l16) * SKVH + (nt + nsel) * 8);
                uint32_t b0, b1, b2, b3;
                ldsm_x4_trans(b0, b1, b2, b3, vaddr);
                uint32_t bfa[2] = { b0, b1 }, bfb[2] = { b2, b3 };
                mma_f16(accO[nt], af, bfa);
                mma_f16(accO[nt + 1], af, bfb);
            }
        }
        __syncwarp();
    }

    // epilogue
    float inv0 = 1.f / l0, inv1 = 1.f / l1;
    __half* Cb = ctx + ((size_t)(b * NQ + qt * BQ_T + w * 16)) * DIM + h * HD;
    #pragma unroll
    for (int nt = 0; nt < 8; nt++) {
        *(__half2*)(Cb + (size_t)r * DIM + nt * 8 + 2 * c) =
            __floats2half2_rn(accO[nt][0] * inv0, accO[nt][1] * inv0);
        *(__half2*)(Cb + (size_t)(r + 8) * DIM + nt * 8 + 2 * c) =
            __floats2half2_rn(accO[nt][2] * inv1, accO[nt][3] * inv1);
    }
}

// ==================== launch =================================================
extern "C" void kernel_launch(void* const* d_in, const int* in_sizes, int n_in,
                              void* d_out, int out_size)
{
    const float* tgt  = (const float*)d_in[0];
    const float* emb  = (const float*)d_in[1];
    const float* ln_g = (const float*)d_in[2];
    const float* ln_b = (const float*)d_in[3];
    const float* wq = (const float*)d_in[4];  const float* bq = (const float*)d_in[5];
    const float* wk = (const float*)d_in[6];  const float* bk = (const float*)d_in[7];
    const float* wv = (const float*)d_in[8];  const float* bv = (const float*)d_in[9];
    const float* wo = (const float*)d_in[10]; const float* bo = (const float*)d_in[11];
    const float* w1 = (const float*)d_in[12]; const float* b1 = (const float*)d_in[13];
    const float* w2 = (const float*)d_in[14]; const float* b2 = (const float*)d_in[15];
    float* out = (float*)d_out;

    __half *qn, *q, *k, *v, *ctx, *h1, *embh, *wqt, *wkt, *wvt, *wot, *w1t, *w2t;
    cudaGetSymbolAddress((void**)&qn,   g_qn);
    cudaGetSymbolAddress((void**)&q,    g_q);
    cudaGetSymbolAddress((void**)&k,    g_k);
    cudaGetSymbolAddress((void**)&v,    g_v);
    cudaGetSymbolAddress((void**)&ctx,  g_ctx);
    cudaGetSymbolAddress((void**)&h1,   g_h1);
    cudaGetSymbolAddress((void**)&embh, g_embh);
    cudaGetSymbolAddress((void**)&wqt,  g_wqt);
    cudaGetSymbolAddress((void**)&wkt,  g_wkt);
    cudaGetSymbolAddress((void**)&wvt,  g_wvt);
    cudaGetSymbolAddress((void**)&wot,  g_wot);
    cudaGetSymbolAddress((void**)&w1t,  g_w1t);
    cudaGetSymbolAddress((void**)&w2t,  g_w2t);

    cudaFuncSetAttribute(h16_gemm, cudaFuncAttributeMaxDynamicSharedMemorySize, GEMM_SMEM);
    cudaFuncSetAttribute(attn_mma, cudaFuncAttributeMaxDynamicSharedMemorySize, ATT_SMEM);

    // 0) transpose+convert weights into [N][K] half; convert emb to half
    dim3 tb(32, 8);
    transpose_half_kernel<<<dim3(DIM / 32, DIM / 32), tb>>>(wq, wqt, DIM, DIM);
    transpose_half_kernel<<<dim3(DIM / 32, DIM / 32), tb>>>(wk, wkt, DIM, DIM);
    transpose_half_kernel<<<dim3(DIM / 32, DIM / 32), tb>>>(wv, wvt, DIM, DIM);
    transpose_half_kernel<<<dim3(DIM / 32, DIM / 32), tb>>>(wo, wot, DIM, DIM);
    transpose_half_kernel<<<dim3(HIDDEN / 32, DIM / 32), tb>>>(w1, w1t, DIM, HIDDEN);
    transpose_half_kernel<<<dim3(DIM / 32, HIDDEN / 32), tb>>>(w2, w2t, HIDDEN, DIM);
    conv_half_kernel<<<1024, 256>>>((const float4*)emb, (__half2*)embh, MK * DIM / 4);

    // 1) qn = LN(tgt) (half)
    ln_kernel<<<MQ, 256>>>(tgt, ln_g, ln_b, qn);

    // 2) Q = qn @ wq + bq (half out)
    h16_gemm<<<dim3(DIM / 128, MQ / 128, 1), 256, GEMM_SMEM>>>(
        MQ, DIM, DIM, qn, wqt, bq, nullptr, q, 0, wqt, bq, q);
    // 3+4) K,V = emb @ {wk,wv} (fused z=2, half out)
    h16_gemm<<<dim3(DIM / 128, MK / 128, 2), 256, GEMM_SMEM>>>(
        MK, DIM, DIM, embh, wkt, bk, nullptr, k, 0, wvt, bv, v);

    // 5) ctx = softmax(Q K^T / 8) V  (fp16 flash, half out)
    attn_mma<<<dim3(NQ / BQ_T, HEADS, BSZ), 256, ATT_SMEM>>>(q, k, v, ctx);

    // 6) tgt1 = tgt + ctx @ wo + bo -> d_out (fp32)
    h16_gemm<<<dim3(DIM / 128, MQ / 128, 1), 256, GEMM_SMEM>>>(
        MQ, DIM, DIM, ctx, wot, bo, tgt, out, 2, wot, bo, out);

    // 7) h_in = LN(tgt1) (half)
    ln_kernel<<<MQ, 256>>>(out, ln_g, ln_b, qn);

    // 8) h1 = gelu(h_in @ w1 + b1) (half out)
    h16_gemm<<<dim3(HIDDEN / 128, MQ / 128, 1), 256, GEMM_SMEM>>>(
        MQ, HIDDEN, DIM, qn, w1t, b1, nullptr, h1, 1, w1t, b1, h1);

    // 9) out = tgt1 + h1 @ w2 + b2 (fp32)
    h16_gemm<<<dim3(DIM / 128, MQ / 128, 1), 256, GEMM_SMEM>>>(
        MQ, DIM, HIDDEN, h1, w2t, b2, out, out, 2, w2t, b2, out);
}

// round 10
// speedup vs baseline: 7.5195x; 1.0551x over previous
#include <cuda_runtime.h>
#include <cuda_fp16.h>
#include <math.h>
#include <stdint.h>

// ---------------- problem constants ----------------
#define BSZ     4
#define NQ      1024
#define NK      2048
#define DIM     1024
#define HEADS   16
#define HD      64
#define HIDDEN  4096
#define MQ      (BSZ*NQ)   // 4096
#define MK      (BSZ*NK)   // 8192

// ---------------- scratch ----------
__device__ __align__(128) __half g_qn  [(size_t)MQ * DIM];
__device__ __align__(128) __half g_q   [(size_t)MQ * DIM];
__device__ __align__(128) __half g_k   [(size_t)MK * DIM];
__device__ __align__(128) __half g_v   [(size_t)MK * DIM];
__device__ __align__(128) __half g_ctx [(size_t)MQ * DIM];
__device__ __align__(128) __half g_h1  [(size_t)MQ * HIDDEN];
__device__ __align__(128) __half g_embh[(size_t)MK * DIM];
__device__ __align__(128) __half g_wqt [(size_t)DIM * DIM];
__device__ __align__(128) __half g_wkt [(size_t)DIM * DIM];
__device__ __align__(128) __half g_wvt [(size_t)DIM * DIM];
__device__ __align__(128) __half g_wot [(size_t)DIM * DIM];
__device__ __align__(128) __half g_w1t [(size_t)DIM * HIDDEN];
__device__ __align__(128) __half g_w2t [(size_t)HIDDEN * DIM];

// ==================== helpers ====================
__device__ __forceinline__ float gelu_exact(float x) {
    return 0.5f * x * (1.0f + erff(x * 0.70710678118654752f));
}
__device__ __forceinline__ void cp16(void* s, const void* g) {
    uint32_t sa = (uint32_t)__cvta_generic_to_shared(s);
    asm volatile("cp.async.ca.shared.global [%0], [%1], 16;" :: "r"(sa), "l"(g));
}
__device__ __forceinline__ void mma_f16(float d[4], const uint32_t a[4], const uint32_t b[2]) {
    asm volatile(
        "mma.sync.aligned.m16n8k16.row.col.f32.f16.f16.f32 "
        "{%0,%1,%2,%3}, {%4,%5,%6,%7}, {%8,%9}, {%0,%1,%2,%3};"
        : "+f"(d[0]), "+f"(d[1]), "+f"(d[2]), "+f"(d[3])
        : "r"(a[0]), "r"(a[1]), "r"(a[2]), "r"(a[3]), "r"(b[0]), "r"(b[1]));
}
__device__ __forceinline__ void ldsm_x4(uint32_t& d0, uint32_t& d1,
                                        uint32_t& d2, uint32_t& d3, uint32_t addr) {
    asm volatile("ldmatrix.sync.aligned.m8n8.x4.shared.b16 {%0,%1,%2,%3}, [%4];"
                 : "=r"(d0), "=r"(d1), "=r"(d2), "=r"(d3) : "r"(addr));
}
__device__ __forceinline__ void ldsm_x4_trans(uint32_t& d0, uint32_t& d1,
                                              uint32_t& d2, uint32_t& d3, uint32_t addr) {
    asm volatile("ldmatrix.sync.aligned.m8n8.x4.trans.shared.b16 {%0,%1,%2,%3}, [%4];"
                 : "=r"(d0), "=r"(d1), "=r"(d2), "=r"(d3) : "r"(addr));
}

// ==================== emb -> half ====================
__global__ __launch_bounds__(256)
void conv_half_kernel(const float4* __restrict__ in, __half2* __restrict__ out, int n4)
{
    int i = blockIdx.x * blockDim.x + threadIdx.x;
    int stride = gridDim.x * blockDim.x;
    for (; i < n4; i += stride) {
        float4 v = in[i];
        out[2 * i]     = __floats2half2_rn(v.x, v.y);
        out[2 * i + 1] = __floats2half2_rn(v.z, v.w);
    }
}

// ==================== fused transpose of all 6 weights ========================
// tile ranges: [0,1024) wq, [1024,2048) wk, [2048,3072) wv, [3072,4096) wo,
// [4096,8192) w1 (K=1024,N=4096 -> 32x128 tilesYxX), [8192,12288) w2 (K=4096,N=1024)
struct TMat { const float* in; __half* out; int K, N, tilesX; };

__global__ __launch_bounds__(256)
void transpose_all_kernel(const float* wq, const float* wk, const float* wv,
                          const float* wo, const float* w1, const float* w2,
                          __half* wqt, __half* wkt, __half* wvt,
                          __half* wot, __half* w1t, __half* w2t)
{
    __shared__ float tile[32][33];
    int t = blockIdx.x;
    const float* in; __half* out; int K, N, lt;
    if (t < 4096) {
        K = DIM; N = DIM; lt = t & 1023;
        int sel = t >> 10;
        in  = sel == 0 ? wq  : sel == 1 ? wk  : sel == 2 ? wv  : wo;
        out = sel == 0 ? wqt : sel == 1 ? wkt : sel == 2 ? wvt : wot;
    } else if (t < 8192) {
        K = DIM; N = HIDDEN; lt = t - 4096; in = w1; out = w1t;
    } else {
        K = HIDDEN; N = DIM; lt = t - 8192; in = w2; out = w2t;
    }
    int tilesX = N >> 5;
    int bx = (lt % tilesX) * 32;
    int by = (lt / tilesX) * 32;
    int tx = threadIdx.x & 31, ty = threadIdx.x >> 5;   // (32, 8)
    #pragma unroll
    for (int i = 0; i < 32; i += 8)
        tile[ty + i][tx] = in[(size_t)(by + ty + i) * N + bx + tx];
    __syncthreads();
    #pragma unroll
    for (int i = 0; i < 32; i += 8)
        out[(size_t)(bx + ty + i) * K + by + tx] = __float2half_rn(tile[tx][ty + i]);
}

// ==================== LayerNorm (half output) ====================
__global__ __launch_bounds__(256)
void ln_kernel(const float* __restrict__ x, const float* __restrict__ g,
               const float* __restrict__ bt, __half* __restrict__ out)
{
    int row = blockIdx.x;
    int t = threadIdx.x;
    const float4* xr = (const float4*)(x + (size_t)row * DIM);
    float4 v = xr[t];
    float s  = v.x + v.y + v.z + v.w;
    float sq = v.x*v.x + v.y*v.y + v.z*v.z + v.w*v.w;

    #pragma unroll
    for (int off = 16; off; off >>= 1) {
        s  += __shfl_xor_sync(0xffffffffu, s,  off);
        sq += __shfl_xor_sync(0xffffffffu, sq, off);
    }
    __shared__ float ss[8], sqs[8];
    int warp = t >> 5, lane = t & 31;
    if (lane == 0) { ss[warp] = s; sqs[warp] = sq; }
    __syncthreads();
    if (t < 32) {
        float a = (t < 8) ? ss[t]  : 0.f;
        float b = (t < 8) ? sqs[t] : 0.f;
        #pragma unroll
        for (int off = 4; off; off >>= 1) {
            a += __shfl_xor_sync(0xffffffffu, a, off);
            b += __shfl_xor_sync(0xffffffffu, b, off);
        }
        if (t == 0) { ss[0] = a; sqs[0] = b; }
    }
    __syncthreads();
    float mu  = ss[0]  * (1.0f / DIM);
    float var = sqs[0] * (1.0f / DIM) - mu * mu;
    float inv = rsqrtf(var + 1e-5f);

    float4 gv = ((const float4*)g)[t];
    float4 bv = ((const float4*)bt)[t];
    __half2* o2 = (__half2*)(out + (size_t)row * DIM);
    o2[2 * t]     = __floats2half2_rn((v.x - mu) * inv * gv.x + bv.x,
                                      (v.y - mu) * inv * gv.y + bv.y);
    o2[2 * t + 1] = __floats2half2_rn((v.z - mu) * inv * gv.z + bv.z,
                                      (v.w - mu) * inv * gv.w + bv.w);
}

// ==================== fp16 tensor-core GEMM (ldmatrix, KC=64, 3-stage) =======
// mode: 0 = bias (half out), 1 = bias+gelu (half out), 2 = bias+residual (fp32 out)
#define KCH   64
#define SKH   72
#define TILE_H (128 * SKH)
#define STAGE_H (2 * TILE_H)
#define N_STG 3
#define GEMM_SMEM (N_STG * STAGE_H * 2)   // 110592 bytes

__global__ __launch_bounds__(256, 2)
void h16_gemm(int M, int N, int K,
              const __half* __restrict__ A,
              const __half* __restrict__ Bt,
              const float* __restrict__ bias,
              const float* __restrict__ res,
              void* __restrict__ Cv, int mode,
              const __half* __restrict__ Bt2,
              const float* __restrict__ bias2,
              void* __restrict__ Cv2)
{
    extern __shared__ __half smh[];

    if (blockIdx.z == 1) { Bt = Bt2; bias = bias2; Cv = Cv2; }

    int tid = threadIdx.x;
    int lane = tid & 31;
    int warp = tid >> 5;
    int warp_m = (warp >> 1) * 32;
    int warp_n = (warp & 1) * 64;
    int r = lane >> 2;
    int c = lane & 3;

    int ctaM = blockIdx.y * 128;
    int ctaN = blockIdx.x * 128;

    const __half* gA = A  + (size_t)ctaM * K;
    const __half* gB = Bt + (size_t)ctaN * K;

    int ldRow = tid >> 3;          // 0..31 (+32 per j)
    int ldCh  = (tid & 7) * 8;     // 8 chunks of 8 halves = 64 halves

    const int nk = K / KCH;

    // ldmatrix per-lane selectors
    uint32_t smb = (uint32_t)__cvta_generic_to_shared(smh);
    int aRowSel = lane & 15;
    int aKSel   = (lane >> 4) * 8;
    int bNSel   = (lane & 7) + ((lane >> 4) << 3);
    int bKSel   = ((lane >> 3) & 1) * 8;
    uint32_t aBase = smb + (uint32_t)(((warp_m + aRowSel) * SKH + aKSel) * 2);
    uint32_t bBase = smb + (uint32_t)((TILE_H + (warp_n + bNSel) * SKH + bKSel) * 2);

    #define ISSUE_STAGE(s, k0)                                                     \
    do {                                                                           \
        __half* sA_ = smh + (s) * STAGE_H;                                         \
        __half* sB_ = sA_ + TILE_H;                                                \
        const __half* a_ = gA + (k0);                                              \
        const __half* b_ = gB + (k0);                                              \
        _Pragma("unroll")                                                          \
        for (int j = 0; j < 4; j++) {                                              \
            int row = ldRow + j * 32;                                              \
            cp16(sA_ + (size_t)row * SKH + ldCh, a_ + (size_t)row * K + ldCh);     \
            cp16(sB_ + (size_t)row * SKH + ldCh, b_ + (size_t)row * K + ldCh);     \
        }                                                                          \
        asm volatile("cp.async.commit_group;");                                    \
    } while (0)

    ISSUE_STAGE(0, 0);
    if (nk > 1) ISSUE_STAGE(1, KCH);
    else        asm volatile("cp.async.commit_group;");

    float acc[2][8][4] = {};

    for (int kt = 0; kt < nk; kt++) {
        int buf = kt % N_STG;
        if (kt + 1 < nk) asm volatile("cp.async.wait_group 1;");
        else             asm volatile("cp.async.wait_group 0;");
        __syncthreads();

        uint32_t stOff = (uint32_t)(buf * STAGE_H * 2);

        #pragma unroll
        for (int ks = 0; ks < 4; ks++) {
            uint32_t af[2][4], bf[8][2];
            uint32_t kOff = (uint32_t)(ks * 16 * 2);
            #pragma unroll
            for (int mt = 0; mt < 2; mt++)
                ldsm_x4(af[mt][0], af[mt][1], af[mt][2], af[mt][3],
                        aBase + stOff + kOff + (uint32_t)(mt * 16 * SKH * 2));
            #pragma unroll
            for (int np = 0; np < 4; np++)
                ldsm_x4(bf[2 * np][0], bf[2 * np][1], bf[2 * np + 1][0], bf[2 * np + 1][1],
                        bBase + stOff + kOff + (uint32_t)(np * 16 * SKH * 2));
            #pragma unroll
            for (int mt = 0; mt < 2; mt++)
                #pragma unroll
                for (int nt = 0; nt < 8; nt++)
                    mma_f16(acc[mt][nt], af[mt], bf[nt]);
        }

        if (kt + 2 < nk) {
            int s = (kt + 2) % N_STG;
            ISSUE_STAGE(s, (kt + 2) * KCH);
        }
    }
    #undef ISSUE_STAGE

    // ---- epilogue ----
    float*  Cf = (float*)Cv;
    __half* Ch = (__half*)Cv;
    #pragma unroll
    for (int mt = 0; mt < 2; mt++) {
        #pragma unroll
        for (int nt = 0; nt < 8; nt++) {
            int row = ctaM + warp_m + mt * 16 + r;
            int col = ctaN + warp_n + nt * 8 + 2 * c;
            float b0 = bias[col], b1 = bias[col + 1];
            float v0 = acc[mt][nt][0] + b0;
            float v1 = acc[mt][nt][1] + b1;
            float v2 = acc[mt][nt][2] + b0;
            float v3 = acc[mt][nt][3] + b1;
            if (mode == 2) {
                const float* r0 = res + (size_t)row * N + col;
                const float* r1 = res + (size_t)(row + 8) * N + col;
                v0 += r0[0]; v1 += r0[1];
                v2 += r1[0]; v3 += r1[1];
                *(float2*)(Cf + (size_t)row * N + col)       = make_float2(v0, v1);
                *(float2*)(Cf + (size_t)(row + 8) * N + col) = make_float2(v2, v3);
            } else {
                if (mode == 1) {
                    v0 = gelu_exact(v0); v1 = gelu_exact(v1);
                    v2 = gelu_exact(v2); v3 = gelu_exact(v3);
                }
                *(__half2*)(Ch + (size_t)row * N + col)       = __floats2half2_rn(v0, v1);
                *(__half2*)(Ch + (size_t)(row + 8) * N + col) = __floats2half2_rn(v2, v3);
            }
        }
    }
}

// ==================== fp16 flash attention (ldmatrix everywhere) =============
#define BQ_T   128
#define TILE_K 64
#define SKKH 72
#define SKVH 72
#define SKPH 72
#define NT_KV (NK / TILE_K)
#define ATT_SMEM ((2*TILE_K*SKKH + 2*TILE_K*SKVH + BQ_T*SKPH) * 2)   // 55296 B

__global__ __launch_bounds__(256, 2)
void attn_mma(const __half* __restrict__ Q, const __half* __restrict__ Kg,
              const __half* __restrict__ Vg, __half* __restrict__ ctx)
{
    extern __shared__ __half smA[];
    __half* KsB = smA;
    __half* VsB = smA + 2 * TILE_K * SKKH;
    __half* Ps  = smA + 2 * TILE_K * (SKKH + SKVH);

    int b = blockIdx.z, h = blockIdx.y, qt = blockIdx.x;
    int tid = threadIdx.x, lane = tid & 31, w = tid >> 5;
    int r = lane >> 2, c = lane & 3;

    const __half* Qb = Q  + ((size_t)(b * NQ + qt * BQ_T)) * DIM + h * HD;
    const __half* Kb = Kg + ((size_t)b * NK) * DIM + h * HD;
    const __half* Vb = Vg + ((size_t)b * NK) * DIM + h * HD;

    #pragma unroll
    for (int i = 0; i < 2; i++) {
        int idx = tid + i * 256;
        int row = idx >> 3, ch = (idx & 7) * 8;
        cp16(&KsB[row * SKKH + ch], Kb + (size_t)row * DIM + ch);
        cp16(&VsB[row * SKVH + ch], Vb + (size_t)row * DIM + ch);
    }
    asm volatile("cp.async.commit_group;");

    uint32_t qf[4][4];
    {
        const __half2 sc = __floats2half2_rn(0.125f, 0.125f);
        const __half* q0 = Qb + (size_t)(w * 16 + r) * DIM;
        const __half* q1 = Qb + (size_t)(w * 16 + r + 8) * DIM;
        #pragma unroll
        for (int kg = 0; kg < 4; kg++) {
            __half2 a0 = __hmul2(*(const __half2*)(q0 + kg * 16 + 2 * c), sc);
            __half2 a1 = __hmul2(*(const __half2*)(q1 + kg * 16 + 2 * c), sc);
            __half2 a2 = __hmul2(*(const __half2*)(q0 + kg * 16 + 2 * c + 8), sc);
            __half2 a3 = __hmul2(*(const __half2*)(q1 + kg * 16 + 2 * c + 8), sc);
            qf[kg][0] = *(uint32_t*)&a0; qf[kg][1] = *(uint32_t*)&a1;
            qf[kg][2] = *(uint32_t*)&a2; qf[kg][3] = *(uint32_t*)&a3;
        }
    }

    float m0 = -1e30f, m1 = -1e30f, l0 = 0.f, l1 = 0.f;
    float accO[8][4] = {};
    __half* Pw = Ps + (w * 16) * SKPH;
    int l16 = lane & 15, nsel = lane >> 4;

    uint32_t smb = (uint32_t)__cvta_generic_to_shared(smA);
    int bNSel = (lane & 7) + ((lane >> 4) << 3);
    int bKSel = ((lane >> 3) & 1) * 8;
    int aRowSel = lane & 15;
    int aKSel   = (lane >> 4) * 8;
    uint32_t kFragBase = smb + (uint32_t)((bNSel * SKKH + bKSel) * 2);
    uint32_t pFragBase = smb + (uint32_t)((2 * TILE_K * (SKKH + SKVH)
                         + (w * 16 + aRowSel) * SKPH + aKSel) * 2);

    for (int kt = 0; kt < NT_KV; kt++) {
        int buf = kt & 1;
        asm volatile("cp.async.wait_group 0;");
        __syncthreads();

        if (kt + 1 < NT_KV) {
            const __half* kp = Kb + (size_t)(kt + 1) * TILE_K * DIM;
            const __half* vp = Vb + (size_t)(kt + 1) * TILE_K * DIM;
            __half* Kd = KsB + (buf ^ 1) * TILE_K * SKKH;
            __half* Vd = VsB + (buf ^ 1) * TILE_K * SKVH;
            #pragma unroll
            for (int i = 0; i < 2; i++) {
                int idx = tid + i * 256;
                int row = idx >> 3, ch = (idx & 7) * 8;
                cp16(&Kd[row * SKKH + ch], kp + (size_t)row * DIM + ch);
                cp16(&Vd[row * SKVH + ch], vp + (size_t)row * DIM + ch);
            }
            asm volatile("cp.async.commit_group;");
        }

        const __half* Vt = VsB + buf * TILE_K * SKVH;
        uint32_t kStage = (uint32_t)(buf * TILE_K * SKKH * 2);

        float accS[8][4] = {};
        #pragma unroll
        for (int kg = 0; kg < 4; kg++) {
            uint32_t kOff = (uint32_t)(kg * 16 * 2);
            #pragma unroll
            for (int np = 0; np < 4; np++) {
                uint32_t bf0[2], bf1[2];
                ldsm_x4(bf0[0], bf0[1], bf1[0], bf1[1],
                        kFragBase + kStage + kOff + (uint32_t)(np * 16 * SKKH * 2));
                mma_f16(accS[2 * np],     qf[kg], bf0);
                mma_f16(accS[2 * np + 1], qf[kg], bf1);
            }
        }

        float mx0 = -1e30f, mx1 = -1e30f;
        #pragma unroll
        for (int nt = 0; nt < 8; nt++) {
            mx0 = fmaxf(mx0, fmaxf(accS[nt][0], accS[nt][1]));
            mx1 = fmaxf(mx1, fmaxf(accS[nt][2], accS[nt][3]));
        }
        mx0 = fmaxf(mx0, __shfl_xor_sync(0xffffffffu, mx0, 1));
        mx0 = fmaxf(mx0, __shfl_xor_sync(0xffffffffu, mx0, 2));
        mx1 = fmaxf(mx1, __shfl_xor_sync(0xffffffffu, mx1, 1));
        mx1 = fmaxf(mx1, __shfl_xor_sync(0xffffffffu, mx1, 2));
        float mn0 = fmaxf(m0, mx0), mn1 = fmaxf(m1, mx1);
        float f0 = __expf(m0 - mn0), f1 = __expf(m1 - mn1);
        float s0 = 0.f, s1 = 0.f;
        #pragma unroll
        for (int nt = 0; nt < 8; nt++) {
            accS[nt][0] = __expf(accS[nt][0] - mn0);
            accS[nt][1] = __expf(accS[nt][1] - mn0);
            accS[nt][2] = __expf(accS[nt][2] - mn1);
            accS[nt][3] = __expf(accS[nt][3] - mn1);
            s0 += accS[nt][0] + accS[nt][1];
            s1 += accS[nt][2] + accS[nt][3];
        }
        s0 += __shfl_xor_sync(0xffffffffu, s0, 1);
        s0 += __shfl_xor_sync(0xffffffffu, s0, 2);
        s1 += __shfl_xor_sync(0xffffffffu, s1, 1);
        s1 += __shfl_xor_sync(0xffffffffu, s1, 2);
        l0 = l0 * f0 + s0; l1 = l1 * f1 + s1;
        m0 = mn0; m1 = mn1;
        #pragma unroll
        for (int nt = 0; nt < 8; nt++) {
            accO[nt][0] *= f0; accO[nt][1] *= f0;
            accO[nt][2] *= f1; accO[nt][3] *= f1;
        }

        #pragma unroll
        for (int nt = 0; nt < 8; nt++) {
            *(__half2*)&Pw[r * SKPH + nt * 8 + 2 * c] =
                __floats2half2_rn(accS[nt][0], accS[nt][1]);
            *(__half2*)&Pw[(r + 8) * SKPH + nt * 8 + 2 * c] =
                __floats2half2_rn(accS[nt][2], accS[nt][3]);
        }
        __syncwarp();

        #pragma unroll
        for (int kg = 0; kg < 4; kg++) {
            uint32_t af[4];
            ldsm_x4(af[0], af[1], af[2], af[3],
                    pFragBase + (uint32_t)(kg * 16 * 2));
            #pragma unroll
            for (int nt = 0; nt < 8; nt += 2) {
                uint32_t vaddr = (uint32_t)__cvta_generic_to_shared(
                    Vt + (size_t)(kg * 16 + l16) * SKVH + (nt + nsel) * 8);
                uint32_t b0, b1, b2, b3;
                ldsm_x4_trans(b0, b1, b2, b3, vaddr);
                uint32_t bfa[2] = { b0, b1 }, bfb[2] = { b2, b3 };
                mma_f16(accO[nt], af, bfa);
                mma_f16(accO[nt + 1], af, bfb);
            }
        }
        __syncwarp();
    }

    float inv0 = 1.f / l0, inv1 = 1.f / l1;
    __half* Cb = ctx + ((size_t)(b * NQ + qt * BQ_T + w * 16)) * DIM + h * HD;
    #pragma unroll
    for (int nt = 0; nt < 8; nt++) {
        *(__half2*)(Cb + (size_t)r * DIM + nt * 8 + 2 * c) =
            __floats2half2_rn(accO[nt][0] * inv0, accO[nt][1] * inv0);
        *(__half2*)(Cb + (size_t)(r + 8) * DIM + nt * 8 + 2 * c) =
            __floats2half2_rn(accO[nt][2] * inv1, accO[nt][3] * inv1);
    }
}

// ==================== launch =================================================
extern "C" void kernel_launch(void* const* d_in, const int* in_sizes, int n_in,
                              void* d_out, int out_size)
{
    const float* tgt  = (const float*)d_in[0];
    const float* emb  = (const float*)d_in[1];
    const float* ln_g = (const float*)d_in[2];
    const float* ln_b = (const float*)d_in[3];
    const float* wq = (const float*)d_in[4];  const float* bq = (const float*)d_in[5];
    const float* wk = (const float*)d_in[6];  const float* bk = (const float*)d_in[7];
    const float* wv = (const float*)d_in[8];  const float* bv = (const float*)d_in[9];
    const float* wo = (const float*)d_in[10]; const float* bo = (const float*)d_in[11];
    const float* w1 = (const float*)d_in[12]; const float* b1 = (const float*)d_in[13];
    const float* w2 = (const float*)d_in[14]; const float* b2 = (const float*)d_in[15];
    float* out = (float*)d_out;

    __half *qn, *q, *k, *v, *ctx, *h1, *embh, *wqt, *wkt, *wvt, *wot, *w1t, *w2t;
    cudaGetSymbolAddress((void**)&qn,   g_qn);
    cudaGetSymbolAddress((void**)&q,    g_q);
    cudaGetSymbolAddress((void**)&k,    g_k);
    cudaGetSymbolAddress((void**)&v,    g_v);
    cudaGetSymbolAddress((void**)&ctx,  g_ctx);
    cudaGetSymbolAddress((void**)&h1,   g_h1);
    cudaGetSymbolAddress((void**)&embh, g_embh);
    cudaGetSymbolAddress((void**)&wqt,  g_wqt);
    cudaGetSymbolAddress((void**)&wkt,  g_wkt);
    cudaGetSymbolAddress((void**)&wvt,  g_wvt);
    cudaGetSymbolAddress((void**)&wot,  g_wot);
    cudaGetSymbolAddress((void**)&w1t,  g_w1t);
    cudaGetSymbolAddress((void**)&w2t,  g_w2t);

    cudaFuncSetAttribute(h16_gemm, cudaFuncAttributeMaxDynamicSharedMemorySize, GEMM_SMEM);
    cudaFuncSetAttribute(attn_mma, cudaFuncAttributeMaxDynamicSharedMemorySize, ATT_SMEM);

    // 0) one fused transpose for all 6 weights; convert emb to half
    transpose_all_kernel<<<12288, 256>>>(wq, wk, wv, wo, w1, w2,
                                         wqt, wkt, wvt, wot, w1t, w2t);
    conv_half_kernel<<<1024, 256>>>((const float4*)emb, (__half2*)embh, MK * DIM / 4);

    // 1) qn = LN(tgt) (half)
    ln_kernel<<<MQ, 256>>>(tgt, ln_g, ln_b, qn);

    // 2) Q = qn @ wq + bq (half out)
    h16_gemm<<<dim3(DIM / 128, MQ / 128, 1), 256, GEMM_SMEM>>>(
        MQ, DIM, DIM, qn, wqt, bq, nullptr, q, 0, wqt, bq, q);
    // 3+4) K,V = emb @ {wk,wv} (fused z=2, half out)
    h16_gemm<<<dim3(DIM / 128, MK / 128, 2), 256, GEMM_SMEM>>>(
        MK, DIM, DIM, embh, wkt, bk, nullptr, k, 0, wvt, bv, v);

    // 5) ctx = softmax(Q K^T / 8) V  (fp16 flash, half out)
    attn_mma<<<dim3(NQ / BQ_T, HEADS, BSZ), 256, ATT_SMEM>>>(q, k, v, ctx);

    // 6) tgt1 = tgt + ctx @ wo + bo -> d_out (fp32)
    h16_gemm<<<dim3(DIM / 128, MQ / 128, 1), 256, GEMM_SMEM>>>(
        MQ, DIM, DIM, ctx, wot, bo, tgt, out, 2, wot, bo, out);

    // 7) h_in = LN(tgt1) (half)
    ln_kernel<<<MQ, 256>>>(out, ln_g, ln_b, qn);

    // 8) h1 = gelu(h_in @ w1 + b1) (half out)
    h16_gemm<<<dim3(HIDDEN / 128, MQ / 128, 1), 256, GEMM_SMEM>>>(
        MQ, HIDDEN, DIM, qn, w1t, b1, nullptr, h1, 1, w1t, b1, h1);

    // 9) out = tgt1 + h1 @ w2 + b2 (fp32)
    h16_gemm<<<dim3(DIM / 128, MQ / 128, 1), 256, GEMM_SMEM>>>(
        MQ, DIM, HIDDEN, h1, w2t, b2, out, out, 2, w2t, b2, out);
}

// round 11
// speedup vs baseline: 7.5464x; 1.0036x over previous
#include <cuda_runtime.h>
#include <cuda_fp16.h>
#include <math.h>
#include <stdint.h>

// ---------------- problem constants ----------------
#define BSZ     4
#define NQ      1024
#define NK      2048
#define DIM     1024
#define HEADS   16
#define HD      64
#define HIDDEN  4096
#define MQ      (BSZ*NQ)   // 4096
#define MK      (BSZ*NK)   // 8192

// ---------------- scratch ----------
__device__ __align__(128) __half g_qn  [(size_t)MQ * DIM];
__device__ __align__(128) __half g_q   [(size_t)MQ * DIM];
__device__ __align__(128) __half g_k   [(size_t)MK * DIM];
__device__ __align__(128) __half g_v   [(size_t)MK * DIM];
__device__ __align__(128) __half g_ctx [(size_t)MQ * DIM];
__device__ __align__(128) __half g_h1  [(size_t)MQ * HIDDEN];
__device__ __align__(128) __half g_embh[(size_t)MK * DIM];
__device__ __align__(128) __half g_wqt [(size_t)DIM * DIM];
__device__ __align__(128) __half g_wkt [(size_t)DIM * DIM];
__device__ __align__(128) __half g_wvt [(size_t)DIM * DIM];
__device__ __align__(128) __half g_wot [(size_t)DIM * DIM];
__device__ __align__(128) __half g_w1t [(size_t)DIM * HIDDEN];
__device__ __align__(128) __half g_w2t [(size_t)HIDDEN * DIM];

// ==================== helpers ====================
__device__ __forceinline__ float gelu_exact(float x) {
    return 0.5f * x * (1.0f + erff(x * 0.70710678118654752f));
}
__device__ __forceinline__ void cp16(void* s, const void* g) {
    uint32_t sa = (uint32_t)__cvta_generic_to_shared(s);
    asm volatile("cp.async.ca.shared.global [%0], [%1], 16;" :: "r"(sa), "l"(g));
}
__device__ __forceinline__ void mma_f16(float d[4], const uint32_t a[4], const uint32_t b[2]) {
    asm volatile(
        "mma.sync.aligned.m16n8k16.row.col.f32.f16.f16.f32 "
        "{%0,%1,%2,%3}, {%4,%5,%6,%7}, {%8,%9}, {%0,%1,%2,%3};"
        : "+f"(d[0]), "+f"(d[1]), "+f"(d[2]), "+f"(d[3])
        : "r"(a[0]), "r"(a[1]), "r"(a[2]), "r"(a[3]), "r"(b[0]), "r"(b[1]));
}
__device__ __forceinline__ void ldsm_x4(uint32_t& d0, uint32_t& d1,
                                        uint32_t& d2, uint32_t& d3, uint32_t addr) {
    asm volatile("ldmatrix.sync.aligned.m8n8.x4.shared.b16 {%0,%1,%2,%3}, [%4];"
                 : "=r"(d0), "=r"(d1), "=r"(d2), "=r"(d3) : "r"(addr));
}
__device__ __forceinline__ void ldsm_x4_trans(uint32_t& d0, uint32_t& d1,
                                              uint32_t& d2, uint32_t& d3, uint32_t addr) {
    asm volatile("ldmatrix.sync.aligned.m8n8.x4.trans.shared.b16 {%0,%1,%2,%3}, [%4];"
                 : "=r"(d0), "=r"(d1), "=r"(d2), "=r"(d3) : "r"(addr));
}

// ==================== emb -> half ====================
__global__ __launch_bounds__(256)
void conv_half_kernel(const float4* __restrict__ in, __half2* __restrict__ out, int n4)
{
    int i = blockIdx.x * blockDim.x + threadIdx.x;
    int stride = gridDim.x * blockDim.x;
    for (; i < n4; i += stride) {
        float4 v = in[i];
        out[2 * i]     = __floats2half2_rn(v.x, v.y);
        out[2 * i + 1] = __floats2half2_rn(v.z, v.w);
    }
}

// ==================== fused transpose of all 6 weights ========================
__global__ __launch_bounds__(256)
void transpose_all_kernel(const float* wq, const float* wk, const float* wv,
                          const float* wo, const float* w1, const float* w2,
                          __half* wqt, __half* wkt, __half* wvt,
                          __half* wot, __half* w1t, __half* w2t)
{
    __shared__ float tile[32][33];
    int t = blockIdx.x;
    const float* in; __half* out; int K, N, lt;
    if (t < 4096) {
        K = DIM; N = DIM; lt = t & 1023;
        int sel = t >> 10;
        in  = sel == 0 ? wq  : sel == 1 ? wk  : sel == 2 ? wv  : wo;
        out = sel == 0 ? wqt : sel == 1 ? wkt : sel == 2 ? wvt : wot;
    } else if (t < 8192) {
        K = DIM; N = HIDDEN; lt = t - 4096; in = w1; out = w1t;
    } else {
        K = HIDDEN; N = DIM; lt = t - 8192; in = w2; out = w2t;
    }
    int tilesX = N >> 5;
    int bx = (lt % tilesX) * 32;
    int by = (lt / tilesX) * 32;
    int tx = threadIdx.x & 31, ty = threadIdx.x >> 5;
    #pragma unroll
    for (int i = 0; i < 32; i += 8)
        tile[ty + i][tx] = in[(size_t)(by + ty + i) * N + bx + tx];
    __syncthreads();
    #pragma unroll
    for (int i = 0; i < 32; i += 8)
        out[(size_t)(bx + ty + i) * K + by + tx] = __float2half_rn(tile[tx][ty + i]);
}

// ==================== LayerNorm (half output) ====================
__global__ __launch_bounds__(256)
void ln_kernel(const float* __restrict__ x, const float* __restrict__ g,
               const float* __restrict__ bt, __half* __restrict__ out)
{
    int row = blockIdx.x;
    int t = threadIdx.x;
    const float4* xr = (const float4*)(x + (size_t)row * DIM);
    float4 v = xr[t];
    float s  = v.x + v.y + v.z + v.w;
    float sq = v.x*v.x + v.y*v.y + v.z*v.z + v.w*v.w;

    #pragma unroll
    for (int off = 16; off; off >>= 1) {
        s  += __shfl_xor_sync(0xffffffffu, s,  off);
        sq += __shfl_xor_sync(0xffffffffu, sq, off);
    }
    __shared__ float ss[8], sqs[8];
    int warp = t >> 5, lane = t & 31;
    if (lane == 0) { ss[warp] = s; sqs[warp] = sq; }
    __syncthreads();
    if (t < 32) {
        float a = (t < 8) ? ss[t]  : 0.f;
        float b = (t < 8) ? sqs[t] : 0.f;
        #pragma unroll
        for (int off = 4; off; off >>= 1) {
            a += __shfl_xor_sync(0xffffffffu, a, off);
            b += __shfl_xor_sync(0xffffffffu, b, off);
        }
        if (t == 0) { ss[0] = a; sqs[0] = b; }
    }
    __syncthreads();
    float mu  = ss[0]  * (1.0f / DIM);
    float var = sqs[0] * (1.0f / DIM) - mu * mu;
    float inv = rsqrtf(var + 1e-5f);

    float4 gv = ((const float4*)g)[t];
    float4 bv = ((const float4*)bt)[t];
    __half2* o2 = (__half2*)(out + (size_t)row * DIM);
    o2[2 * t]     = __floats2half2_rn((v.x - mu) * inv * gv.x + bv.x,
                                      (v.y - mu) * inv * gv.y + bv.y);
    o2[2 * t + 1] = __floats2half2_rn((v.z - mu) * inv * gv.z + bv.z,
                                      (v.w - mu) * inv * gv.w + bv.w);
}

// ==================== fp16 GEMM: CTA 128x256, warp 64x64, 1 CTA/SM ===========
// mode: 0 = bias (half out), 1 = bias+gelu (half out), 2 = bias+residual (fp32 out)
#define BM    128
#define BN    256
#define KCH   64
#define SKH   72
#define A_TILE_H (BM * SKH)            // 9216 halves
#define B_TILE_H (BN * SKH)            // 18432 halves
#define STAGE_H (A_TILE_H + B_TILE_H)  // 27648 halves = 55296 B
#define N_STG 3
#define GEMM_SMEM (N_STG * STAGE_H * 2)   // 165888 bytes

__global__ __launch_bounds__(256, 1)
void h16_gemm(int M, int N, int K,
              const __half* __restrict__ A,
              const __half* __restrict__ Bt,
              const float* __restrict__ bias,
              const float* __restrict__ res,
              void* __restrict__ Cv, int mode,
              const __half* __restrict__ Bt2,
              const float* __restrict__ bias2,
              void* __restrict__ Cv2)
{
    extern __shared__ __half smh[];

    if (blockIdx.z == 1) { Bt = Bt2; bias = bias2; Cv = Cv2; }

    int tid = threadIdx.x;
    int lane = tid & 31;
    int warp = tid >> 5;
    int warp_m = (warp & 1) * 64;        // 0 / 64
    int warp_n = (warp >> 1) * 64;       // 0 / 64 / 128 / 192
    int r = lane >> 2;
    int c = lane & 3;

    int ctaM = blockIdx.y * BM;
    int ctaN = blockIdx.x * BN;

    const __half* gA = A  + (size_t)ctaM * K;
    const __half* gB = Bt + (size_t)ctaN * K;

    int ldRow = tid >> 3;          // 0..31 (+32 per j)
    int ldCh  = (tid & 7) * 8;     // 8 chunks of 8 halves = 64 halves

    const int nk = K / KCH;

    // ldmatrix per-lane selectors
    uint32_t smb = (uint32_t)__cvta_generic_to_shared(smh);
    int aRowSel = lane & 15;
    int aKSel   = (lane >> 4) * 8;
    int bNSel   = (lane & 7) + ((lane >> 4) << 3);
    int bKSel   = ((lane >> 3) & 1) * 8;
    uint32_t aBase = smb + (uint32_t)(((warp_m + aRowSel) * SKH + aKSel) * 2);
    uint32_t bBase = smb + (uint32_t)((A_TILE_H + (warp_n + bNSel) * SKH + bKSel) * 2);

    #define ISSUE_STAGE(s, k0)                                                     \
    do {                                                                           \
        __half* sA_ = smh + (s) * STAGE_H;                                         \
        __half* sB_ = sA_ + A_TILE_H;                                              \
        const __half* a_ = gA + (k0);                                              \
        const __half* b_ = gB + (k0);                                              \
        _Pragma("unroll")                                                          \
        for (int j = 0; j < 4; j++) {                                              \
            int row = ldRow + j * 32;                                              \
            cp16(sA_ + (size_t)row * SKH + ldCh, a_ + (size_t)row * K + ldCh);     \
        }                                                                          \
        _Pragma("unroll")                                                          \
        for (int j = 0; j < 8; j++) {                                              \
            int row = ldRow + j * 32;                                              \
            cp16(sB_ + (size_t)row * SKH + ldCh, b_ + (size_t)row * K + ldCh);     \
        }                                                                          \
        asm volatile("cp.async.commit_group;");                                    \
    } while (0)

    ISSUE_STAGE(0, 0);
    if (nk > 1) ISSUE_STAGE(1, KCH);
    else        asm volatile("cp.async.commit_group;");

    float acc[4][8][4] = {};

    for (int kt = 0; kt < nk; kt++) {
        int buf = kt % N_STG;
        if (kt + 1 < nk) asm volatile("cp.async.wait_group 1;");
        else             asm volatile("cp.async.wait_group 0;");
        __syncthreads();

        // prefetch next stage BEFORE compute (buffer (kt+2)%3 was freed at kt-1)
        if (kt + 2 < nk) {
            int s = (kt + 2) % N_STG;
            ISSUE_STAGE(s, (kt + 2) * KCH);
        }

        uint32_t stOff = (uint32_t)(buf * STAGE_H * 2);

        #pragma unroll
        for (int ks = 0; ks < 4; ks++) {
            uint32_t af[4][4], bf[8][2];
            uint32_t kOff = (uint32_t)(ks * 16 * 2);
            #pragma unroll
            for (int mt = 0; mt < 4; mt++)
                ldsm_x4(af[mt][0], af[mt][1], af[mt][2], af[mt][3],
                        aBase + stOff + kOff + (uint32_t)(mt * 16 * SKH * 2));
            #pragma unroll
            for (int np = 0; np < 4; np++)
                ldsm_x4(bf[2 * np][0], bf[2 * np][1], bf[2 * np + 1][0], bf[2 * np + 1][1],
                        bBase + stOff + kOff + (uint32_t)(np * 16 * SKH * 2));
            #pragma unroll
            for (int mt = 0; mt < 4; mt++)
                #pragma unroll
                for (int nt = 0; nt < 8; nt++)
                    mma_f16(acc[mt][nt], af[mt], bf[nt]);
        }
    }
    #undef ISSUE_STAGE

    // ---- epilogue ----
    float*  Cf = (float*)Cv;
    __half* Ch = (__half*)Cv;
    #pragma unroll
    for (int mt = 0; mt < 4; mt++) {
        #pragma unroll
        for (int nt = 0; nt < 8; nt++) {
            int row = ctaM + warp_m + mt * 16 + r;
            int col = ctaN + warp_n + nt * 8 + 2 * c;
            float b0 = bias[col], b1 = bias[col + 1];
            float v0 = acc[mt][nt][0] + b0;
            float v1 = acc[mt][nt][1] + b1;
            float v2 = acc[mt][nt][2] + b0;
            float v3 = acc[mt][nt][3] + b1;
            if (mode == 2) {
                const float* r0 = res + (size_t)row * N + col;
                const float* r1 = res + (size_t)(row + 8) * N + col;
                v0 += r0[0]; v1 += r0[1];
                v2 += r1[0]; v3 += r1[1];
                *(float2*)(Cf + (size_t)row * N + col)       = make_float2(v0, v1);
                *(float2*)(Cf + (size_t)(row + 8) * N + col) = make_float2(v2, v3);
            } else {
                if (mode == 1) {
                    v0 = gelu_exact(v0); v1 = gelu_exact(v1);
                    v2 = gelu_exact(v2); v3 = gelu_exact(v3);
                }
                *(__half2*)(Ch + (size_t)row * N + col)       = __floats2half2_rn(v0, v1);
                *(__half2*)(Ch + (size_t)(row + 8) * N + col) = __floats2half2_rn(v2, v3);
            }
        }
    }
}

// ==================== fp16 flash attention (3-stage K/V) ======================
#define BQ_T   128
#define TILE_K 64
#define SKKH 72
#define SKVH 72
#define SKPH 72
#define NT_KV (NK / TILE_K)
#define ATT_SMEM ((3*TILE_K*SKKH + 3*TILE_K*SKVH + BQ_T*SKPH) * 2)   // 73728 B

__global__ __launch_bounds__(256, 2)
void attn_mma(const __half* __restrict__ Q, const __half* __restrict__ Kg,
              const __half* __restrict__ Vg, __half* __restrict__ ctx)
{
    extern __shared__ __half smA[];
    __half* KsB = smA;                                  // [3][64][SKKH]
    __half* VsB = smA + 3 * TILE_K * SKKH;              // [3][64][SKVH]
    __half* Ps  = smA + 3 * TILE_K * (SKKH + SKVH);     // [128][SKPH]

    int b = blockIdx.z, h = blockIdx.y, qt = blockIdx.x;
    int tid = threadIdx.x, lane = tid & 31, w = tid >> 5;
    int r = lane >> 2, c = lane & 3;

    const __half* Qb = Q  + ((size_t)(b * NQ + qt * BQ_T)) * DIM + h * HD;
    const __half* Kb = Kg + ((size_t)b * NK) * DIM + h * HD;
    const __half* Vb = Vg + ((size_t)b * NK) * DIM + h * HD;

    #define ATT_ISSUE(s, kt_)                                                      \
    do {                                                                           \
        const __half* kp_ = Kb + (size_t)(kt_) * TILE_K * DIM;                     \
        const __half* vp_ = Vb + (size_t)(kt_) * TILE_K * DIM;                     \
        __half* Kd_ = KsB + (s) * TILE_K * SKKH;                                   \
        __half* Vd_ = VsB + (s) * TILE_K * SKVH;                                   \
        _Pragma("unroll")                                                          \
        for (int i = 0; i < 2; i++) {                                              \
            int idx = tid + i * 256;                                               \
            int row = idx >> 3, ch = (idx & 7) * 8;                                \
            cp16(&Kd_[row * SKKH + ch], kp_ + (size_t)row * DIM + ch);             \
            cp16(&Vd_[row * SKVH + ch], vp_ + (size_t)row * DIM + ch);             \
        }                                                                          \
        asm volatile("cp.async.commit_group;");                                    \
    } while (0)

    ATT_ISSUE(0, 0);
    ATT_ISSUE(1, 1);

    uint32_t qf[4][4];
    {
        const __half2 sc = __floats2half2_rn(0.125f, 0.125f);
        const __half* q0 = Qb + (size_t)(w * 16 + r) * DIM;
        const __half* q1 = Qb + (size_t)(w * 16 + r + 8) * DIM;
        #pragma unroll
        for (int kg = 0; kg < 4; kg++) {
            __half2 a0 = __hmul2(*(const __half2*)(q0 + kg * 16 + 2 * c), sc);
            __half2 a1 = __hmul2(*(const __half2*)(q1 + kg * 16 + 2 * c), sc);
            __half2 a2 = __hmul2(*(const __half2*)(q0 + kg * 16 + 2 * c + 8), sc);
            __half2 a3 = __hmul2(*(const __half2*)(q1 + kg * 16 + 2 * c + 8), sc);
            qf[kg][0] = *(uint32_t*)&a0; qf[kg][1] = *(uint32_t*)&a1;
            qf[kg][2] = *(uint32_t*)&a2; qf[kg][3] = *(uint32_t*)&a3;
        }
    }

    float m0 = -1e30f, m1 = -1e30f, l0 = 0.f, l1 = 0.f;
    float accO[8][4] = {};
    __half* Pw = Ps + (w * 16) * SKPH;
    int l16 = lane & 15, nsel = lane >> 4;

    uint32_t smb = (uint32_t)__cvta_generic_to_shared(smA);
    int bNSel = (lane & 7) + ((lane >> 4) << 3);
    int bKSel = ((lane >> 3) & 1) * 8;
    int aRowSel = lane & 15;
    int aKSel   = (lane >> 4) * 8;
    uint32_t kFragBase = smb + (uint32_t)((bNSel * SKKH + bKSel) * 2);
    uint32_t pFragBase = smb + (uint32_t)((3 * TILE_K * (SKKH + SKVH)
                         + (w * 16 + aRowSel) * SKPH + aKSel) * 2);

    for (int kt = 0; kt < NT_KV; kt++) {
        int buf = kt % 3;
        if (kt + 1 < NT_KV) asm volatile("cp.async.wait_group 1;");
        else                asm volatile("cp.async.wait_group 0;");
        __syncthreads();

        if (kt + 2 < NT_KV) ATT_ISSUE((kt + 2) % 3, kt + 2);

        const __half* Vt = VsB + buf * TILE_K * SKVH;
        uint32_t kStage = (uint32_t)(buf * TILE_K * SKKH * 2);

        float accS[8][4] = {};
        #pragma unroll
        for (int kg = 0; kg < 4; kg++) {
            uint32_t kOff = (uint32_t)(kg * 16 * 2);
            #pragma unroll
            for (int np = 0; np < 4; np++) {
                uint32_t bf0[2], bf1[2];
                ldsm_x4(bf0[0], bf0[1], bf1[0], bf1[1],
                        kFragBase + kStage + kOff + (uint32_t)(np * 16 * SKKH * 2));
                mma_f16(accS[2 * np],     qf[kg], bf0);
                mma_f16(accS[2 * np + 1], qf[kg], bf1);
            }
        }

        float mx0 = -1e30f, mx1 = -1e30f;
        #pragma unroll
        for (int nt = 0; nt < 8; nt++) {
            mx0 = fmaxf(mx0, fmaxf(accS[nt][0], accS[nt][1]));
            mx1 = fmaxf(mx1, fmaxf(accS[nt][2], accS[nt][3]));
        }
        mx0 = fmaxf(mx0, __shfl_xor_sync(0xffffffffu, mx0, 1));
        mx0 = fmaxf(mx0, __shfl_xor_sync(0xffffffffu, mx0, 2));
        mx1 = fmaxf(mx1, __shfl_xor_sync(0xffffffffu, mx1, 1));
        mx1 = fmaxf(mx1, __shfl_xor_sync(0xffffffffu, mx1, 2));
        float mn0 = fmaxf(m0, mx0), mn1 = fmaxf(m1, mx1);
        float f0 = __expf(m0 - mn0), f1 = __expf(m1 - mn1);
        float s0 = 0.f, s1 = 0.f;
        #pragma unroll
        for (int nt = 0; nt < 8; nt++) {
            accS[nt][0] = __expf(accS[nt][0] - mn0);
            accS[nt][1] = __expf(accS[nt][1] - mn0);
            accS[nt][2] = __expf(accS[nt][2] - mn1);
            accS[nt][3] = __expf(accS[nt][3] - mn1);
            s0 += accS[nt][0] + accS[nt][1];
            s1 += accS[nt][2] + accS[nt][3];
        }
        s0 += __shfl_xor_sync(0xffffffffu, s0, 1);
        s0 += __shfl_xor_sync(0xffffffffu, s0, 2);
        s1 += __shfl_xor_sync(0xffffffffu, s1, 1);
        s1 += __shfl_xor_sync(0xffffffffu, s1, 2);
        l0 = l0 * f0 + s0; l1 = l1 * f1 + s1;
        m0 = mn0; m1 = mn1;
        #pragma unroll
        for (int nt = 0; nt < 8; nt++) {
            accO[nt][0] *= f0; accO[nt][1] *= f0;
            accO[nt][2] *= f1; accO[nt][3] *= f1;
        }

        #pragma unroll
        for (int nt = 0; nt < 8; nt++) {
            *(__half2*)&Pw[r * SKPH + nt * 8 + 2 * c] =
                __floats2half2_rn(accS[nt][0], accS[nt][1]);
            *(__half2*)&Pw[(r + 8) * SKPH + nt * 8 + 2 * c] =
                __floats2half2_rn(accS[nt][2], accS[nt][3]);
        }
        __syncwarp();

        #pragma unroll
        for (int kg = 0; kg < 4; kg++) {
            uint32_t af[4];
            ldsm_x4(af[0], af[1], af[2], af[3],
                    pFragBase + (uint32_t)(kg * 16 * 2));
            #pragma unroll
            for (int nt = 0; nt < 8; nt += 2) {
                uint32_t vaddr = (uint32_t)__cvta_generic_to_shared(
                    Vt + (size_t)(kg * 16 + l16) * SKVH + (nt + nsel) * 8);
                uint32_t b0, b1, b2, b3;
                ldsm_x4_trans(b0, b1, b2, b3, vaddr);
                uint32_t bfa[2] = { b0, b1 }, bfb[2] = { b2, b3 };
                mma_f16(accO[nt], af, bfa);
                mma_f16(accO[nt + 1], af, bfb);
            }
        }
        __syncwarp();
    }
    #undef ATT_ISSUE

    float inv0 = 1.f / l0, inv1 = 1.f / l1;
    __half* Cb = ctx + ((size_t)(b * NQ + qt * BQ_T + w * 16)) * DIM + h * HD;
    #pragma unroll
    for (int nt = 0; nt < 8; nt++) {
        *(__half2*)(Cb + (size_t)r * DIM + nt * 8 + 2 * c) =
            __floats2half2_rn(accO[nt][0] * inv0, accO[nt][1] * inv0);
        *(__half2*)(Cb + (size_t)(r + 8) * DIM + nt * 8 + 2 * c) =
            __floats2half2_rn(accO[nt][2] * inv1, accO[nt][3] * inv1);
    }
}

// ==================== launch =================================================
extern "C" void kernel_launch(void* const* d_in, const int* in_sizes, int n_in,
                              void* d_out, int out_size)
{
    const float* tgt  = (const float*)d_in[0];
    const float* emb  = (const float*)d_in[1];
    const float* ln_g = (const float*)d_in[2];
    const float* ln_b = (const float*)d_in[3];
    const float* wq = (const float*)d_in[4];  const float* bq = (const float*)d_in[5];
    const float* wk = (const float*)d_in[6];  const float* bk = (const float*)d_in[7];
    const float* wv = (const float*)d_in[8];  const float* bv = (const float*)d_in[9];
    const float* wo = (const float*)d_in[10]; const float* bo = (const float*)d_in[11];
    const float* w1 = (const float*)d_in[12]; const float* b1 = (const float*)d_in[13];
    const float* w2 = (const float*)d_in[14]; const float* b2 = (const float*)d_in[15];
    float* out = (float*)d_out;

    __half *qn, *q, *k, *v, *ctx, *h1, *embh, *wqt, *wkt, *wvt, *wot, *w1t, *w2t;
    cudaGetSymbolAddress((void**)&qn,   g_qn);
    cudaGetSymbolAddress((void**)&q,    g_q);
    cudaGetSymbolAddress((void**)&k,    g_k);
    cudaGetSymbolAddress((void**)&v,    g_v);
    cudaGetSymbolAddress((void**)&ctx,  g_ctx);
    cudaGetSymbolAddress((void**)&h1,   g_h1);
    cudaGetSymbolAddress((void**)&embh, g_embh);
    cudaGetSymbolAddress((void**)&wqt,  g_wqt);
    cudaGetSymbolAddress((void**)&wkt,  g_wkt);
    cudaGetSymbolAddress((void**)&wvt,  g_wvt);
    cudaGetSymbolAddress((void**)&wot,  g_wot);
    cudaGetSymbolAddress((void**)&w1t,  g_w1t);
    cudaGetSymbolAddress((void**)&w2t,  g_w2t);

    cudaFuncSetAttribute(h16_gemm, cudaFuncAttributeMaxDynamicSharedMemorySize, GEMM_SMEM);
    cudaFuncSetAttribute(attn_mma, cudaFuncAttributeMaxDynamicSharedMemorySize, ATT_SMEM);

    // 0) one fused transpose for all 6 weights; convert emb to half
    transpose_all_kernel<<<12288, 256>>>(wq, wk, wv, wo, w1, w2,
                                         wqt, wkt, wvt, wot, w1t, w2t);
    conv_half_kernel<<<1024, 256>>>((const float4*)emb, (__half2*)embh, MK * DIM / 4);

    // 1) qn = LN(tgt) (half)
    ln_kernel<<<MQ, 256>>>(tgt, ln_g, ln_b, qn);

    // 2) Q = qn @ wq + bq (half out)
    h16_gemm<<<dim3(DIM / BN, MQ / BM, 1), 256, GEMM_SMEM>>>(
        MQ, DIM, DIM, qn, wqt, bq, nullptr, q, 0, wqt, bq, q);
    // 3+4) K,V = emb @ {wk,wv} (fused z=2, half out)
    h16_gemm<<<dim3(DIM / BN, MK / BM, 2), 256, GEMM_SMEM>>>(
        MK, DIM, DIM, embh, wkt, bk, nullptr, k, 0, wvt, bv, v);

    // 5) ctx = softmax(Q K^T / 8) V  (fp16 flash, half out)
    attn_mma<<<dim3(NQ / BQ_T, HEADS, BSZ), 256, ATT_SMEM>>>(q, k, v, ctx);

    // 6) tgt1 = tgt + ctx @ wo + bo -> d_out (fp32)
    h16_gemm<<<dim3(DIM / BN, MQ / BM, 1), 256, GEMM_SMEM>>>(
        MQ, DIM, DIM, ctx, wot, bo, tgt, out, 2, wot, bo, out);

    // 7) h_in = LN(tgt1) (half)
    ln_kernel<<<MQ, 256>>>(out, ln_g, ln_b, qn);

    // 8) h1 = gelu(h_in @ w1 + b1) (half out)
    h16_gemm<<<dim3(HIDDEN / BN, MQ / BM, 1), 256, GEMM_SMEM>>>(
        MQ, HIDDEN, DIM, qn, w1t, b1, nullptr, h1, 1, w1t, b1, h1);

    // 9) out = tgt1 + h1 @ w2 + b2 (fp32)
    h16_gemm<<<dim3(DIM / BN, MQ / BM, 1), 256, GEMM_SMEM>>>(
        MQ, DIM, HIDDEN, h1, w2t, b2, out, out, 2, w2t, b2, out);
}